// round 7
// baseline (speedup 1.0000x reference)
#include <cuda_runtime.h>
#include <math.h>
#include <stdint.h>

#define BB 256
#define SS 512
#define II 256
#define HH 256
#define OO 256
#define LL 64
#define NT 512

__device__ float g_xproj[(size_t)SS * BB * HH];

__device__ __forceinline__ float sigf(float x) {
    return __fdividef(1.f, 1.f + __expf(-x));
}
__device__ __forceinline__ float tanhfast(float x) {
    float e = __expf(2.f * x);
    return 1.f - __fdividef(2.f, e + 1.f);
}

// ---------------------------------------------------------------------------
// PTX helpers
// ---------------------------------------------------------------------------
__device__ __forceinline__ uint32_t smem_u32(const void* p) {
    uint32_t r;
    asm("{ .reg .u64 t; cvta.to.shared.u64 t, %1; cvt.u32.u64 %0, t; }" : "=r"(r) : "l"(p));
    return r;
}
__device__ __forceinline__ uint32_t mapa_peer(uint32_t a, uint32_t peer) {
    uint32_t r;
    asm("mapa.shared::cluster.u32 %0, %1, %2;" : "=r"(r) : "r"(a), "r"(peer));
    return r;
}
__device__ __forceinline__ void mbar_init(uint32_t a, uint32_t c) {
    asm volatile("mbarrier.init.shared.b64 [%0], %1;" :: "r"(a), "r"(c) : "memory");
}
__device__ __forceinline__ void mbar_arrive_local(uint32_t a) {
    asm volatile("mbarrier.arrive.release.cta.shared::cta.b64 _, [%0];"
                 :: "r"(a) : "memory");
}
__device__ __forceinline__ void mbar_arrive_cluster(uint32_t a) {
    asm volatile("mbarrier.arrive.release.cluster.shared::cluster.b64 _, [%0];"
                 :: "r"(a) : "memory");
}
__device__ __forceinline__ void mbar_wait_par(uint32_t a, uint32_t par) {
    asm volatile(
        "{\n\t.reg .pred P;\n\t"
        "WL%=:\n\t"
        "mbarrier.try_wait.parity.acquire.cluster.shared::cta.b64 P, [%0], %1, 0x989680;\n\t"
        "@P bra WD%=;\n\t"
        "bra WL%=;\n\t"
        "WD%=:\n\t}"
        :: "r"(a), "r"(par) : "memory");
}
__device__ __forceinline__ void st_cluster_f32(uint32_t a, float v) {
    asm volatile("st.shared::cluster.b32 [%0], %1;"
                 :: "r"(a), "r"(__float_as_uint(v)) : "memory");
}
__device__ __forceinline__ void cluster_sync_all() {
    asm volatile("barrier.cluster.arrive.aligned;" ::: "memory");
    asm volatile("barrier.cluster.wait.aligned;" ::: "memory");
}

// ---------------------------------------------------------------------------
// Kernel 1: xproj = x @ W1x + (b1x+b1a)  (tiled SGEMM, ~fp32 FMA roofline)
// ---------------------------------------------------------------------------
__global__ __launch_bounds__(256) void xproj_kernel(
    const float* __restrict__ x, const float* __restrict__ W1x,
    const float* __restrict__ b1x, const float* __restrict__ b1a)
{
    __shared__ float As[2][16][64];
    __shared__ float Bs[2][16][64];

    const int t  = threadIdx.x;
    const int tx = t & 15;
    const int ty = t >> 4;
    const int m0 = blockIdx.x * 64;
    const int n0 = blockIdx.y * 64;
    const int s  = m0 >> 8;
    const int b0 = m0 & 255;

    const int ar = t >> 2;
    const int ak = t & 3;
    const int bk = t >> 4;
    const int bn = t & 15;

    const float* aptr = x + ((size_t)(b0 + ar) * SS + s) * II + ak * 4;
    const float* bptr = W1x + (size_t)bk * HH + n0 + bn * 4;

    float4 areg = *(const float4*)aptr;
    float4 breg = *(const float4*)bptr;
    As[0][ak * 4 + 0][ar] = areg.x;
    As[0][ak * 4 + 1][ar] = areg.y;
    As[0][ak * 4 + 2][ar] = areg.z;
    As[0][ak * 4 + 3][ar] = areg.w;
    *(float4*)&Bs[0][bk][bn * 4] = breg;
    __syncthreads();

    float4 acc[4];
    #pragma unroll
    for (int r = 0; r < 4; r++) acc[r] = make_float4(0.f, 0.f, 0.f, 0.f);

    #pragma unroll 1
    for (int step = 0; step < 16; step++) {
        const int p = step & 1;
        if (step < 15) {
            areg = *(const float4*)(aptr + (step + 1) * 16);
            breg = *(const float4*)(bptr + (size_t)(step + 1) * 16 * HH);
        }
        #pragma unroll
        for (int k = 0; k < 16; k++) {
            float4 av = *(const float4*)&As[p][k][ty * 4];
            float4 bv = *(const float4*)&Bs[p][k][tx * 4];
            acc[0].x = fmaf(av.x, bv.x, acc[0].x); acc[0].y = fmaf(av.x, bv.y, acc[0].y);
            acc[0].z = fmaf(av.x, bv.z, acc[0].z); acc[0].w = fmaf(av.x, bv.w, acc[0].w);
            acc[1].x = fmaf(av.y, bv.x, acc[1].x); acc[1].y = fmaf(av.y, bv.y, acc[1].y);
            acc[1].z = fmaf(av.y, bv.z, acc[1].z); acc[1].w = fmaf(av.y, bv.w, acc[1].w);
            acc[2].x = fmaf(av.z, bv.x, acc[2].x); acc[2].y = fmaf(av.z, bv.y, acc[2].y);
            acc[2].z = fmaf(av.z, bv.z, acc[2].z); acc[2].w = fmaf(av.z, bv.w, acc[2].w);
            acc[3].x = fmaf(av.w, bv.x, acc[3].x); acc[3].y = fmaf(av.w, bv.y, acc[3].y);
            acc[3].z = fmaf(av.w, bv.z, acc[3].z); acc[3].w = fmaf(av.w, bv.w, acc[3].w);
        }
        if (step < 15) {
            const int q2 = 1 - p;
            As[q2][ak * 4 + 0][ar] = areg.x;
            As[q2][ak * 4 + 1][ar] = areg.y;
            As[q2][ak * 4 + 2][ar] = areg.z;
            As[q2][ak * 4 + 3][ar] = areg.w;
            *(float4*)&Bs[q2][bk][bn * 4] = breg;
            __syncthreads();
        }
    }

    float4 bx = *(const float4*)&b1x[n0 + tx * 4];
    float4 ba = *(const float4*)&b1a[n0 + tx * 4];
    float4 bias = make_float4(bx.x + ba.x, bx.y + ba.y, bx.z + ba.z, bx.w + ba.w);
    #pragma unroll
    for (int r = 0; r < 4; r++) {
        float4 v = make_float4(acc[r].x + bias.x, acc[r].y + bias.y,
                               acc[r].z + bias.z, acc[r].w + bias.w);
        *(float4*)&g_xproj[(size_t)(m0 + ty * 4 + r) * HH + n0 + tx * 4] = v;
    }
}

// ---------------------------------------------------------------------------
// GEMV partials. Warp w: kq = w>>1, half = w&1; thread: 2 cols x 4 rows.
// ---------------------------------------------------------------------------
__device__ __forceinline__ void gemv8_s(const float* __restrict__ Wp,   // smem, stride 128
                                        const float4* __restrict__ a, float acc[8])
{
    #pragma unroll
    for (int j = 0; j < 8; j++) acc[j] = 0.f;
    #pragma unroll 8
    for (int k = 0; k < 32; k++) {
        float2 w  = *(const float2*)(Wp + k * 128);
        float4 av = a[k];
        acc[0] = fmaf(av.x, w.x, acc[0]); acc[4] = fmaf(av.x, w.y, acc[4]);
        acc[1] = fmaf(av.y, w.x, acc[1]); acc[5] = fmaf(av.y, w.y, acc[5]);
        acc[2] = fmaf(av.z, w.x, acc[2]); acc[6] = fmaf(av.z, w.y, acc[6]);
        acc[3] = fmaf(av.w, w.x, acc[3]); acc[7] = fmaf(av.w, w.y, acc[7]);
    }
}
__device__ __forceinline__ void gemv8_g(const float* __restrict__ Wp,   // global, stride 256
                                        const float4* __restrict__ a, float acc[8])
{
    #pragma unroll
    for (int j = 0; j < 8; j++) acc[j] = 0.f;
    #pragma unroll 16
    for (int k = 0; k < 32; k++) {
        float2 w  = *(const float2*)(Wp + (size_t)k * 256);
        float4 av = a[k];
        acc[0] = fmaf(av.x, w.x, acc[0]); acc[4] = fmaf(av.x, w.y, acc[4]);
        acc[1] = fmaf(av.y, w.x, acc[1]); acc[5] = fmaf(av.y, w.y, acc[5]);
        acc[2] = fmaf(av.z, w.x, acc[2]); acc[6] = fmaf(av.z, w.y, acc[6]);
        acc[3] = fmaf(av.w, w.x, acc[3]); acc[7] = fmaf(av.w, w.y, acc[7]);
    }
}

#define RSTRIDE 1032

// SMEM: ws 131072 + wy_lo 65536 + a4s 8192 + y4s 4096 + red 16512 + mbars 16
#define SMEM_BYTES (131072 + 65536 + 8192 + 4096 + 16512 + 16)

__device__ __forceinline__ void fill_w(float* dst, const float* __restrict__ W,
                                       int c0, int t, int nk)
{
    const int lane = t & 31, w = t >> 5;          // 16 warps
    #pragma unroll 4
    for (int i = 0; i < nk / 16; i++) {
        int k = i * 16 + w;
        float4 v = *(const float4*)(W + (size_t)k * 256 + c0 + lane * 4);
        *(float4*)(dst + k * 128 + lane * 4) = v;
    }
}

// ---------------------------------------------------------------------------
// Kernel 2: cluster-2 N-split persistent RNN, SMEM weights, fused exchange,
// SPLIT WAIT: only warps whose k-range maps to peer-produced columns wait.
// ---------------------------------------------------------------------------
__global__ __launch_bounds__(NT, 1) __cluster_dims__(2, 1, 1)
void rnn_kernel(const float* __restrict__ W1a,
                const float* __restrict__ W2x, const float* __restrict__ b2x,
                const float* __restrict__ W2a, const float* __restrict__ b2a,
                const float* __restrict__ Wy,  const float* __restrict__ by,
                float* __restrict__ out)
{
    extern __shared__ __align__(16) unsigned char dsm[];
    float*  ws    = (float*)dsm;                 // [256 k][128 cols]
    float*  wy_lo = ws + 32768;                  // [128 k][128 cols]
    float4* a4s   = (float4*)(wy_lo + 16384);    // [2][256] state
    float4* y4s   = a4s + 512;                   // [256]
    float*  red   = (float*)(y4s + 256);
    unsigned long long* mbars = (unsigned long long*)(red + 4 * RSTRIDE);

    const int t    = threadIdx.x;
    const int lane = t & 31;
    const int w    = t >> 5;                     // 0..15
    const int kq   = w >> 1;                     // 0..7
    const int half = w & 1;
    const int cl2  = half * 64 + lane * 2;

    uint32_t rank;
    asm("mov.u32 %0, %%cluster_ctarank;" : "=r"(rank));
    const uint32_t peer = rank ^ 1;
    const int b0 = (blockIdx.x >> 1) * 4;
    const int c0 = (int)rank * 128;
    const bool is_peer = ((uint32_t)(kq >> 2) != rank);  // k-range is peer's cols

    const int row_o = t >> 7;
    const int coll  = t & 127;
    const int col   = c0 + coll;
    const int brow  = b0 + row_o;

    uint32_t mF[2], pF[2];
    mF[0] = smem_u32(&mbars[0]); mF[1] = smem_u32(&mbars[1]);
    pF[0] = mapa_peer(mF[0], peer); pF[1] = mapa_peer(mF[1], peer);
    uint32_t pa4[2];
    pa4[0] = mapa_peer(smem_u32(&a4s[0]), peer);
    pa4[1] = mapa_peer(smem_u32(&a4s[256]), peer);
    uint32_t py4 = mapa_peer(smem_u32(&y4s[0]), peer);
    const uint32_t stoff = (uint32_t)(col * 16 + row_o * 4);

    if (t == 0) { mbar_init(mF[0], 16); mbar_init(mF[1], 16); }  // peer arrives only
    a4s[t] = make_float4(0.f, 0.f, 0.f, 0.f);
    fill_w(ws, W1a, c0, t, 256);
    __syncthreads();
    cluster_sync_all();
    if (lane == 0) mbar_arrive_local(mF[0]);     // prime: 16 local arrives

    int fpar[2] = {0, 0};

    const float* wsp   = ws + kq * 32 * 128 + cl2;
    const float* wylop = wy_lo + kq * 32 * 128 + cl2;
    const float* wyg   = Wy  + (size_t)(kq * 32) * 256 + c0 + cl2;
    const float* w2xg  = W2x + (size_t)(kq * 32) * 256 + c0 + cl2;

    // ======================= encoder =======================
    for (int s = 0; s < SS; s++) {
        const int p = s & 1, q = p ^ 1;
        float xpv = __ldcs(&g_xproj[((size_t)s * BB + brow) * HH + col]);

        if (is_peer) mbar_wait_par(mF[p], fpar[p]);   // local warps: sync2 covers
        fpar[p] ^= 1;

        float acc[8];
        gemv8_s(wsp, &a4s[p * 256 + kq * 32], acc);
        #pragma unroll
        for (int r = 0; r < 4; r++)
            *(float2*)&red[r * RSTRIDE + kq * 128 + cl2] = make_float2(acc[r], acc[4 + r]);
        __syncthreads();                              // sync1

        float v = 0.f;
        #pragma unroll
        for (int g = 0; g < 8; g++) v += red[row_o * RSTRIDE + g * 128 + coll];
        v = tanhfast(v + xpv);
        st_cluster_f32(pa4[q] + stoff, v);            // push first (start DSMEM early)
        ((float*)&a4s[q * 256 + col])[row_o] = v;
        __syncwarp();
        if (lane == 0) mbar_arrive_cluster(pF[q]);    // 16 arrives at peer
        __syncthreads();                              // sync2: local q half visible
    }

    // a_last in buf 0
    if (is_peer) mbar_wait_par(mF[0], fpar[0]);
    fpar[0] ^= 1;

    // ======================= glue =======================
    const float byv = by[col];
    const float bbv = b2x[col] + b2a[col];
    float base0;
    {
        float acc[8];
        gemv8_g(wyg, &a4s[kq * 32], acc);             // buf 0
        #pragma unroll
        for (int r = 0; r < 4; r++)
            *(float2*)&red[r * RSTRIDE + kq * 128 + cl2] = make_float2(acc[r], acc[4 + r]);
        __syncthreads();
        float v = 0.f;
        #pragma unroll
        for (int g = 0; g < 8; g++) v += red[row_o * RSTRIDE + g * 128 + coll];
        float y0v = sigf(v + byv);
        ((float*)&y4s[col])[row_o] = y0v;
        st_cluster_f32(py4 + stoff, y0v);
        cluster_sync_all();                           // y4s complete everywhere

        gemv8_g(w2xg, &y4s[kq * 32], acc);
        #pragma unroll
        for (int r = 0; r < 4; r++)
            *(float2*)&red[r * RSTRIDE + kq * 128 + cl2] = make_float2(acc[r], acc[4 + r]);
        __syncthreads();
        v = 0.f;
        #pragma unroll
        for (int g = 0; g < 8; g++) v += red[row_o * RSTRIDE + g * 128 + coll];
        base0 = v + bbv;
        __syncthreads();
    }

    // restage: ws <- W2a slice, wy_lo <- Wy low-k slice
    fill_w(ws, W2a, c0, t, 256);
    fill_w(wy_lo, Wy, c0, t, 128);
    __syncthreads();

    // ======================= decoder =======================
    for (int i = 0; i < LL; i++) {
        const int p = i & 1, q = p ^ 1;
        float acc[8];

        // a = tanh(base + a @ W2a)  (buf p full: peer half waited in prev y-phase)
        gemv8_s(wsp, &a4s[p * 256 + kq * 32], acc);
        #pragma unroll
        for (int r = 0; r < 4; r++)
            *(float2*)&red[r * RSTRIDE + kq * 128 + cl2] = make_float2(acc[r], acc[4 + r]);
        __syncthreads();
        float v = 0.f;
        #pragma unroll
        for (int g = 0; g < 8; g++) v += red[row_o * RSTRIDE + g * 128 + coll];
        v = tanhfast(v + ((i == 0) ? base0 : bbv));
        st_cluster_f32(pa4[q] + stoff, v);
        ((float*)&a4s[q * 256 + col])[row_o] = v;
        __syncwarp();
        if (lane == 0) mbar_arrive_cluster(pF[q]);
        __syncthreads();                              // local q half visible

        // y = sigmoid(a_new @ Wy + by)
        if (is_peer) mbar_wait_par(mF[q], fpar[q]);
        fpar[q] ^= 1;
        if (kq < 4) gemv8_s(wylop, &a4s[q * 256 + kq * 32], acc);
        else        gemv8_g(wyg,   &a4s[q * 256 + kq * 32], acc);
        #pragma unroll
        for (int r = 0; r < 4; r++)
            *(float2*)&red[r * RSTRIDE + kq * 128 + cl2] = make_float2(acc[r], acc[4 + r]);
        __syncthreads();
        v = 0.f;
        #pragma unroll
        for (int g = 0; g < 8; g++) v += red[row_o * RSTRIDE + g * 128 + coll];
        out[((size_t)brow * LL + i) * OO + col] = sigf(v + byv);
        __syncthreads();                              // red reuse guard
    }

    cluster_sync_all();   // no CTA exits while peer DSMEM ops may be in flight
}

// ---------------------------------------------------------------------------
extern "C" void kernel_launch(void* const* d_in, const int* in_sizes, int n_in,
                              void* d_out, int out_size)
{
    const float* x   = (const float*)d_in[0];
    const float* W1x = (const float*)d_in[1];
    const float* b1x = (const float*)d_in[2];
    const float* W1a = (const float*)d_in[3];
    const float* b1a = (const float*)d_in[4];
    const float* W2x = (const float*)d_in[5];
    const float* b2x = (const float*)d_in[6];
    const float* W2a = (const float*)d_in[7];
    const float* b2a = (const float*)d_in[8];
    const float* Wy  = (const float*)d_in[9];
    const float* by  = (const float*)d_in[10];
    float* out = (float*)d_out;

    (void)in_sizes; (void)n_in; (void)out_size;

    cudaFuncSetAttribute(rnn_kernel, cudaFuncAttributeMaxDynamicSharedMemorySize,
                         SMEM_BYTES);

    dim3 xgrid((BB * SS) / 64, HH / 64);
    xproj_kernel<<<xgrid, 256>>>(x, W1x, b1x, b1a);
    rnn_kernel<<<BB / 2, NT, SMEM_BYTES>>>(W1a, W2x, b2x, W2a, b2a, Wy, by, out);
}

// round 9
// speedup vs baseline: 1.3053x; 1.3053x over previous
#include <cuda_runtime.h>
#include <cuda_bf16.h>
#include <math.h>
#include <stdint.h>

#define BB 256
#define SS 512
#define II 256
#define HH 256
#define OO 256
#define LL 64

__device__ float g_xproj[(size_t)SS * BB * HH];
__device__ __nv_bfloat16 g_wh[256 * 256];   // W1x^T hi: [n][k]
__device__ __nv_bfloat16 g_wl[256 * 256];   // W1x^T lo: [n][k]

__device__ __forceinline__ float sigf(float x) {
    return __fdividef(1.f, 1.f + __expf(-x));
}
__device__ __forceinline__ float tanhfast(float x) {
    float e = __expf(2.f * x);
    return 1.f - __fdividef(2.f, e + 1.f);
}

// ---------------------------------------------------------------------------
// PTX helpers
// ---------------------------------------------------------------------------
__device__ __forceinline__ uint32_t smem_u32(const void* p) {
    uint32_t r;
    asm("{ .reg .u64 t; cvta.to.shared.u64 t, %1; cvt.u32.u64 %0, t; }" : "=r"(r) : "l"(p));
    return r;
}
__device__ __forceinline__ uint32_t mapa_peer(uint32_t a, uint32_t peer) {
    uint32_t r;
    asm("mapa.shared::cluster.u32 %0, %1, %2;" : "=r"(r) : "r"(a), "r"(peer));
    return r;
}
__device__ __forceinline__ void mbar_init(uint32_t a, uint32_t c) {
    asm volatile("mbarrier.init.shared.b64 [%0], %1;" :: "r"(a), "r"(c) : "memory");
}
__device__ __forceinline__ void mbar_arrive_cluster(uint32_t a) {
    asm volatile("mbarrier.arrive.release.cluster.shared::cluster.b64 _, [%0];"
                 :: "r"(a) : "memory");
}
__device__ __forceinline__ void mbar_wait_par(uint32_t a, uint32_t par) {
    asm volatile(
        "{\n\t.reg .pred P;\n\t"
        "WL%=:\n\t"
        "mbarrier.try_wait.parity.acquire.cluster.shared::cta.b64 P, [%0], %1, 0x989680;\n\t"
        "@P bra WD%=;\n\t"
        "bra WL%=;\n\t"
        "WD%=:\n\t}"
        :: "r"(a), "r"(par) : "memory");
}
__device__ __forceinline__ void st_cluster_f4(uint32_t a, float4 v) {
    asm volatile("st.shared::cluster.v4.b32 [%0], {%1,%2,%3,%4};" :: "r"(a),
                 "r"(__float_as_uint(v.x)), "r"(__float_as_uint(v.y)),
                 "r"(__float_as_uint(v.z)), "r"(__float_as_uint(v.w)) : "memory");
}
__device__ __forceinline__ void cluster_sync_all() {
    asm volatile("barrier.cluster.arrive.aligned;" ::: "memory");
    asm volatile("barrier.cluster.wait.aligned;" ::: "memory");
}

// ===========================================================================
// Kernel 0: W1x -> bf16 hi/lo, transposed to [n][k]
// ===========================================================================
__global__ void wconv_kernel(const float* __restrict__ W1x)
{
    int k = blockIdx.x, n = threadIdx.x;
    float v = W1x[k * 256 + n];
    __nv_bfloat16 h = __float2bfloat16(v);
    __nv_bfloat16 l = __float2bfloat16(v - __bfloat162float(h));
    g_wh[n * 256 + k] = h;
    g_wl[n * 256 + k] = l;
}

// ===========================================================================
// Kernel 1: xproj = x @ W1x + (b1x+b1a) via mma.sync bf16 hi/lo (3-term).
// CTA tile 128m x 128n, 8 warps (2m x 4n), warp tile 64x32, K=256 (4x64).
// B resident in SMEM (hi+lo 128KB), A double-buffered (2x32KB).
// ===========================================================================
#define SB_BH    0
#define SB_BL    65536
#define SB_A     131072     // buf p at SB_A + p*32768 : hi 16384, lo 16384
#define SB_BIAS  196608
#define XP_SMEM  197120

__device__ __forceinline__ uint32_t packbf2(float a, float b) {
    __nv_bfloat16 ha = __float2bfloat16(a), hb = __float2bfloat16(b);
    return ((uint32_t)__bfloat16_as_ushort(hb) << 16) | __bfloat16_as_ushort(ha);
}

__device__ __forceinline__ void ldsm_x4(uint32_t addr, uint32_t r[4]) {
    asm volatile("ldmatrix.sync.aligned.m8n8.x4.shared.b16 {%0,%1,%2,%3}, [%4];"
                 : "=r"(r[0]), "=r"(r[1]), "=r"(r[2]), "=r"(r[3]) : "r"(addr));
}
__device__ __forceinline__ void mma_bf16(float c[4], const uint32_t a[4],
                                         uint32_t b0, uint32_t b1) {
    asm volatile(
        "mma.sync.aligned.m16n8k16.row.col.f32.bf16.bf16.f32 "
        "{%0,%1,%2,%3}, {%4,%5,%6,%7}, {%8,%9}, {%0,%1,%2,%3};"
        : "+f"(c[0]), "+f"(c[1]), "+f"(c[2]), "+f"(c[3])
        : "r"(a[0]), "r"(a[1]), "r"(a[2]), "r"(a[3]), "r"(b0), "r"(b1));
}

// A fragment (m16 x k16): rows of 128B (8 chunks), XOR-swizzled chunk = q^(row&7)
__device__ __forceinline__ void afrag(uint32_t Ab, int mbase, int j, int lane,
                                      uint32_t r[4]) {
    int row = mbase + (lane & 15);
    int q   = j * 2 + (lane >> 4);
    uint32_t addr = Ab + (uint32_t)(row * 128 + ((q ^ row) & 7) * 16);
    ldsm_x4(addr, r);
}
// B fragment x4 (n16 x k16): rows of 512B (32 chunks), swizzle within 128B blk
__device__ __forceinline__ void bfrag(uint32_t Bb, int nbase, int ks, int lane,
                                      uint32_t r[4]) {
    int row = nbase + (lane & 7) + ((lane >> 4) << 3);
    int q   = ks * 2 + ((lane >> 3) & 1);
    uint32_t qp = (uint32_t)((q & ~7) | ((q ^ row) & 7));
    uint32_t addr = Bb + (uint32_t)(row * 512) + qp * 16;
    ldsm_x4(addr, r);
}

__device__ __forceinline__ void load_a_chunk(unsigned char* sm, int p,
                                             const float* __restrict__ x,
                                             int b0, int s, int c, int t)
{
    const int r = t >> 1, hf = t & 1, rx = r & 7;
    unsigned char* ah = sm + SB_A + p * 32768;
    unsigned char* al = ah + 16384;
    const float* xr = x + ((size_t)(b0 + r) * SS + s) * II + c * 64 + hf * 32;
    #pragma unroll
    for (int jj = 0; jj < 4; jj++) {
        float4 v0 = *(const float4*)(xr + jj * 8);
        float4 v1 = *(const float4*)(xr + jj * 8 + 4);
        uint4 h, l;
        h.x = packbf2(v0.x, v0.y); h.y = packbf2(v0.z, v0.w);
        h.z = packbf2(v1.x, v1.y); h.w = packbf2(v1.z, v1.w);
        l.x = packbf2(v0.x - __bfloat162float(__float2bfloat16(v0.x)),
                      v0.y - __bfloat162float(__float2bfloat16(v0.y)));
        l.y = packbf2(v0.z - __bfloat162float(__float2bfloat16(v0.z)),
                      v0.w - __bfloat162float(__float2bfloat16(v0.w)));
        l.z = packbf2(v1.x - __bfloat162float(__float2bfloat16(v1.x)),
                      v1.y - __bfloat162float(__float2bfloat16(v1.y)));
        l.w = packbf2(v1.z - __bfloat162float(__float2bfloat16(v1.z)),
                      v1.w - __bfloat162float(__float2bfloat16(v1.w)));
        int q = hf * 4 + jj;
        uint32_t off = (uint32_t)(r * 128 + (q ^ rx) * 16);
        *(uint4*)(ah + off) = h;
        *(uint4*)(al + off) = l;
    }
}

__global__ __launch_bounds__(256, 1) void xproj_mma_kernel(
    const float* __restrict__ x,
    const float* __restrict__ b1x, const float* __restrict__ b1a)
{
    extern __shared__ __align__(1024) unsigned char sm[];
    const int t = threadIdx.x;
    const int wid = t >> 5, lane = t & 31;
    const uint32_t smb = smem_u32(sm);

    const int m0 = blockIdx.x * 128;
    const int n0 = blockIdx.y * 128;
    const int s  = m0 >> 8;
    const int b0 = m0 & 255;
    const int mw = (wid & 1) * 64;     // warp m offset (local)
    const int nw = (wid >> 1) * 32;    // warp n offset (local)

    // ---- stage B (hi/lo) with swizzle; bias ----
    #pragma unroll 4
    for (int i = 0; i < 16; i++) {
        int idx = i * 256 + t;
        int rr = idx >> 5, q = idx & 31;
        uint32_t qp = (uint32_t)((q & ~7) | ((q ^ rr) & 7));
        size_t src = (size_t)(n0 + rr) * 256 + q * 8;
        *(uint4*)(sm + SB_BH + rr * 512 + qp * 16) = *(const uint4*)(g_wh + src);
        *(uint4*)(sm + SB_BL + rr * 512 + qp * 16) = *(const uint4*)(g_wl + src);
    }
    if (t < 128)
        ((float*)(sm + SB_BIAS))[t] = b1x[n0 + t] + b1a[n0 + t];

    load_a_chunk(sm, 0, x, b0, s, 0, t);
    __syncthreads();

    float acc[4][4][4];
    #pragma unroll
    for (int mt = 0; mt < 4; mt++)
        #pragma unroll
        for (int nt = 0; nt < 4; nt++)
            #pragma unroll
            for (int e = 0; e < 4; e++) acc[mt][nt][e] = 0.f;

    const uint32_t Bh = smb + SB_BH, Bl = smb + SB_BL;

    #pragma unroll 1
    for (int c = 0; c < 4; c++) {
        const int p = c & 1;
        if (c < 3) load_a_chunk(sm, 1 - p, x, b0, s, c + 1, t);
        const uint32_t Abh = smb + SB_A + p * 32768;
        const uint32_t Abl = Abh + 16384;

        #pragma unroll
        for (int j = 0; j < 4; j++) {
            const int ks = c * 4 + j;
            uint32_t bh[8], bl[8];
            bfrag(Bh, nw,      ks, lane, bh);
            bfrag(Bh, nw + 16, ks, lane, bh + 4);
            bfrag(Bl, nw,      ks, lane, bl);
            bfrag(Bl, nw + 16, ks, lane, bl + 4);
            #pragma unroll
            for (int mt = 0; mt < 4; mt++) {
                uint32_t ah[4], al[4];
                afrag(Abh, mw + mt * 16, j, lane, ah);
                afrag(Abl, mw + mt * 16, j, lane, al);
                #pragma unroll
                for (int nt = 0; nt < 4; nt++) {
                    mma_bf16(acc[mt][nt], ah, bh[nt * 2], bh[nt * 2 + 1]);
                    mma_bf16(acc[mt][nt], ah, bl[nt * 2], bl[nt * 2 + 1]);
                    mma_bf16(acc[mt][nt], al, bh[nt * 2], bh[nt * 2 + 1]);
                }
            }
        }
        __syncthreads();
    }

    // ---- epilogue ----
    const int g = lane >> 2, tig = lane & 3;
    const float* bias_sm = (const float*)(sm + SB_BIAS);
    #pragma unroll
    for (int mt = 0; mt < 4; mt++) {
        const int mrow = m0 + mw + mt * 16 + g;
        #pragma unroll
        for (int nt = 0; nt < 4; nt++) {
            const int nl = nw + nt * 8 + tig * 2;
            const float bz0 = bias_sm[nl], bz1 = bias_sm[nl + 1];
            float2 v0 = make_float2(acc[mt][nt][0] + bz0, acc[mt][nt][1] + bz1);
            float2 v1 = make_float2(acc[mt][nt][2] + bz0, acc[mt][nt][3] + bz1);
            *(float2*)&g_xproj[(size_t)mrow * HH + n0 + nl] = v0;
            *(float2*)&g_xproj[(size_t)(mrow + 8) * HH + n0 + nl] = v1;
        }
    }
}

// ===========================================================================
// Kernel 2: R4 rnn (verbatim — proven 1360 us).
// ===========================================================================
__device__ __forceinline__ void gemv16_s(const float* __restrict__ Wp,
                                         const float4* __restrict__ a, float acc[16])
{
    #pragma unroll
    for (int j = 0; j < 16; j++) acc[j] = 0.f;
    #pragma unroll 8
    for (int k = 0; k < 32; k++) {
        float4 w  = *(const float4*)(Wp + k * 128);
        float4 av = a[k];
        acc[0]  = fmaf(av.x, w.x, acc[0]);  acc[1]  = fmaf(av.x, w.y, acc[1]);
        acc[2]  = fmaf(av.x, w.z, acc[2]);  acc[3]  = fmaf(av.x, w.w, acc[3]);
        acc[4]  = fmaf(av.y, w.x, acc[4]);  acc[5]  = fmaf(av.y, w.y, acc[5]);
        acc[6]  = fmaf(av.y, w.z, acc[6]);  acc[7]  = fmaf(av.y, w.w, acc[7]);
        acc[8]  = fmaf(av.z, w.x, acc[8]);  acc[9]  = fmaf(av.z, w.y, acc[9]);
        acc[10] = fmaf(av.z, w.z, acc[10]); acc[11] = fmaf(av.z, w.w, acc[11]);
        acc[12] = fmaf(av.w, w.x, acc[12]); acc[13] = fmaf(av.w, w.y, acc[13]);
        acc[14] = fmaf(av.w, w.z, acc[14]); acc[15] = fmaf(av.w, w.w, acc[15]);
    }
}
__device__ __forceinline__ void gemv16_g(const float* __restrict__ Wp,
                                         const float4* __restrict__ a, float acc[16])
{
    #pragma unroll
    for (int j = 0; j < 16; j++) acc[j] = 0.f;
    #pragma unroll 16
    for (int k = 0; k < 32; k++) {
        float4 w  = *(const float4*)(Wp + (size_t)k * 256);
        float4 av = a[k];
        acc[0]  = fmaf(av.x, w.x, acc[0]);  acc[1]  = fmaf(av.x, w.y, acc[1]);
        acc[2]  = fmaf(av.x, w.z, acc[2]);  acc[3]  = fmaf(av.x, w.w, acc[3]);
        acc[4]  = fmaf(av.y, w.x, acc[4]);  acc[5]  = fmaf(av.y, w.y, acc[5]);
        acc[6]  = fmaf(av.y, w.z, acc[6]);  acc[7]  = fmaf(av.y, w.w, acc[7]);
        acc[8]  = fmaf(av.z, w.x, acc[8]);  acc[9]  = fmaf(av.z, w.y, acc[9]);
        acc[10] = fmaf(av.z, w.z, acc[10]); acc[11] = fmaf(av.z, w.w, acc[11]);
        acc[12] = fmaf(av.w, w.x, acc[12]); acc[13] = fmaf(av.w, w.y, acc[13]);
        acc[14] = fmaf(av.w, w.z, acc[14]); acc[15] = fmaf(av.w, w.w, acc[15]);
    }
}

#define RSTRIDE 1032
#define SMEM_BYTES (131072 + 65536 + 8192 + 4096 + 16512 + 32)

__device__ __forceinline__ void fill_w(float* dst, const float* __restrict__ W,
                                       int c0, int t, int nk)
{
    const int lane = t & 31, w = t >> 5;
    for (int i = 0; i < nk / 8; i++) {
        int k = i * 8 + w;
        float4 v = *(const float4*)(W + (size_t)k * 256 + c0 + lane * 4);
        *(float4*)(dst + k * 128 + lane * 4) = v;
    }
}

__global__ __launch_bounds__(256, 1) __cluster_dims__(2, 1, 1)
void rnn_kernel(const float* __restrict__ W1a,
                const float* __restrict__ W2x, const float* __restrict__ b2x,
                const float* __restrict__ W2a, const float* __restrict__ b2a,
                const float* __restrict__ Wy,  const float* __restrict__ by,
                float* __restrict__ out)
{
    extern __shared__ __align__(16) unsigned char dsm[];
    float*  ws    = (float*)dsm;
    float*  wy_lo = ws + 32768;
    float4* a4s   = (float4*)(wy_lo + 16384);
    float4* y4s   = a4s + 512;
    float*  red   = (float*)(y4s + 256);
    unsigned long long* mbars = (unsigned long long*)(red + 4 * RSTRIDE);

    const int t  = threadIdx.x;
    const int kq = t >> 5;
    const int cq = t & 31;
    uint32_t rank;
    asm("mov.u32 %0, %%cluster_ctarank;" : "=r"(rank));
    const uint32_t peer = rank ^ 1;
    const int b0 = (blockIdx.x >> 1) * 4;
    const int c0 = (int)rank * 128;
    const bool is_peer = ((uint32_t)(kq >> 2) != rank);

    const int o0    = 2 * t;
    const int row_o = (o0 >> 2) & 3;
    const int coll  = (o0 >> 4) * 4 + (o0 & 3);
    const int col   = c0 + coll;
    const int brow  = b0 + row_o;

    uint32_t mF[2], mRD[2], pF[2], pRD[2];
    mF[0]  = smem_u32(&mbars[0]); mF[1]  = smem_u32(&mbars[1]);
    mRD[0] = smem_u32(&mbars[2]); mRD[1] = smem_u32(&mbars[3]);
    pF[0]  = mapa_peer(mF[0], peer);  pF[1]  = mapa_peer(mF[1], peer);
    pRD[0] = mapa_peer(mRD[0], peer); pRD[1] = mapa_peer(mRD[1], peer);
    uint32_t pa4[2];
    pa4[0] = mapa_peer(smem_u32(&a4s[0]), peer);
    pa4[1] = mapa_peer(smem_u32(&a4s[256]), peer);
    uint32_t py4 = mapa_peer(smem_u32(&y4s[0]), peer);

    if (t == 0) {
        mbar_init(mF[0], 32);  mbar_init(mF[1], 32);
        mbar_init(mRD[0], 32); mbar_init(mRD[1], 32);
    }
    a4s[t]       = make_float4(0.f, 0.f, 0.f, 0.f);
    fill_w(ws, W1a, c0, t, 256);
    __syncthreads();
    cluster_sync_all();
    if (kq == 0) mbar_arrive_cluster(pF[0]);
    if (kq == 1) mbar_arrive_cluster(pRD[1]);

    int fpar[2]  = {0, 0};
    int rdpar[2] = {0, 0};

    const float* wsp   = ws + kq * 32 * 128 + cq * 4;
    const float* wylop = wy_lo + kq * 32 * 128 + cq * 4;

    // ======================= encoder =======================
    for (int s = 0; s < SS; s++) {
        const int p = s & 1, q = p ^ 1;
        float2 xp = __ldcs((const float2*)(g_xproj + ((size_t)s * BB + brow) * HH + col));

        if (is_peer) mbar_wait_par(mF[p], fpar[p]);
        fpar[p] ^= 1;

        float acc[16];
        gemv16_s(wsp, &a4s[p * 256 + kq * 32], acc);
        #pragma unroll
        for (int r = 0; r < 4; r++)
            *(float4*)&red[r * RSTRIDE + kq * 128 + cq * 4] =
                make_float4(acc[r * 4], acc[r * 4 + 1], acc[r * 4 + 2], acc[r * 4 + 3]);
        __syncthreads();
        if (kq == 1) mbar_arrive_cluster(pRD[p]);

        float v0 = 0.f, v1 = 0.f;
        #pragma unroll
        for (int g = 0; g < 8; g++) {
            float2 rv = *(const float2*)&red[row_o * RSTRIDE + g * 128 + coll];
            v0 += rv.x; v1 += rv.y;
        }
        ((float*)&a4s[q * 256 + col])[row_o]     = tanhfast(v0 + xp.x);
        ((float*)&a4s[q * 256 + col + 1])[row_o] = tanhfast(v1 + xp.y);
        __syncthreads();

        if (kq == 0) mbar_wait_par(mRD[q], rdpar[q]);
        rdpar[q] ^= 1;
        if (kq == 0) {
            #pragma unroll
            for (int j = 0; j < 4; j++) {
                int idx = c0 + cq + 32 * j;
                st_cluster_f4(pa4[q] + (uint32_t)idx * 16u, a4s[q * 256 + idx]);
            }
            mbar_arrive_cluster(pF[q]);
        }
    }

    if (is_peer) mbar_wait_par(mF[0], fpar[0]);
    fpar[0] ^= 1;

    // ======================= glue =======================
    float byv0, byv1, bb0, bb1, base00, base01;
    {
        float2 byv = *(const float2*)&by[col];
        byv0 = byv.x; byv1 = byv.y;
        float2 b2xv = *(const float2*)&b2x[col];
        float2 b2av = *(const float2*)&b2a[col];
        bb0 = b2xv.x + b2av.x; bb1 = b2xv.y + b2av.y;

        float acc[16];
        gemv16_g(Wy + (size_t)(kq * 32) * 256 + c0 + cq * 4, &a4s[kq * 32], acc);
        #pragma unroll
        for (int r = 0; r < 4; r++)
            *(float4*)&red[r * RSTRIDE + kq * 128 + cq * 4] =
                make_float4(acc[r * 4], acc[r * 4 + 1], acc[r * 4 + 2], acc[r * 4 + 3]);
        __syncthreads();
        float v0 = 0.f, v1 = 0.f;
        #pragma unroll
        for (int g = 0; g < 8; g++) {
            float2 rv = *(const float2*)&red[row_o * RSTRIDE + g * 128 + coll];
            v0 += rv.x; v1 += rv.y;
        }
        ((float*)&y4s[col])[row_o]     = sigf(v0 + byv0);
        ((float*)&y4s[col + 1])[row_o] = sigf(v1 + byv1);
        __syncthreads();
        if (kq == 0) {
            #pragma unroll
            for (int j = 0; j < 4; j++) {
                int idx = c0 + cq + 32 * j;
                st_cluster_f4(py4 + (uint32_t)idx * 16u, y4s[idx]);
            }
        }
        cluster_sync_all();

        gemv16_g(W2x + (size_t)(kq * 32) * 256 + c0 + cq * 4, y4s + kq * 32, acc);
        #pragma unroll
        for (int r = 0; r < 4; r++)
            *(float4*)&red[r * RSTRIDE + kq * 128 + cq * 4] =
                make_float4(acc[r * 4], acc[r * 4 + 1], acc[r * 4 + 2], acc[r * 4 + 3]);
        __syncthreads();
        v0 = 0.f; v1 = 0.f;
        #pragma unroll
        for (int g = 0; g < 8; g++) {
            float2 rv = *(const float2*)&red[row_o * RSTRIDE + g * 128 + coll];
            v0 += rv.x; v1 += rv.y;
        }
        base00 = v0 + bb0; base01 = v1 + bb1;
        __syncthreads();
    }

    fill_w(ws, W2a, c0, t, 256);
    fill_w(wy_lo, Wy, c0, t, 128);
    __syncthreads();

    // ======================= decoder =======================
    for (int i = 0; i < LL; i++) {
        const int p = i & 1, q = p ^ 1;
        float acc[16];

        gemv16_s(wsp, &a4s[p * 256 + kq * 32], acc);
        #pragma unroll
        for (int r = 0; r < 4; r++)
            *(float4*)&red[r * RSTRIDE + kq * 128 + cq * 4] =
                make_float4(acc[r * 4], acc[r * 4 + 1], acc[r * 4 + 2], acc[r * 4 + 3]);
        __syncthreads();
        if (kq == 1) mbar_arrive_cluster(pRD[p]);

        float v0 = 0.f, v1 = 0.f;
        #pragma unroll
        for (int g = 0; g < 8; g++) {
            float2 rv = *(const float2*)&red[row_o * RSTRIDE + g * 128 + coll];
            v0 += rv.x; v1 += rv.y;
        }
        float bs0 = (i == 0) ? base00 : bb0;
        float bs1 = (i == 0) ? base01 : bb1;
        ((float*)&a4s[q * 256 + col])[row_o]     = tanhfast(v0 + bs0);
        ((float*)&a4s[q * 256 + col + 1])[row_o] = tanhfast(v1 + bs1);
        __syncthreads();

        if (kq == 0) mbar_wait_par(mRD[q], rdpar[q]);
        rdpar[q] ^= 1;
        if (kq == 0) {
            #pragma unroll
            for (int j = 0; j < 4; j++) {
                int idx = c0 + cq + 32 * j;
                st_cluster_f4(pa4[q] + (uint32_t)idx * 16u, a4s[q * 256 + idx]);
            }
            mbar_arrive_cluster(pF[q]);
        }

        if (is_peer) mbar_wait_par(mF[q], fpar[q]);
        fpar[q] ^= 1;

        if (kq < 4) gemv16_s(wylop, &a4s[q * 256 + kq * 32], acc);
        else        gemv16_g(Wy + (size_t)(kq * 32) * 256 + c0 + cq * 4,
                             &a4s[q * 256 + kq * 32], acc);
        #pragma unroll
        for (int r = 0; r < 4; r++)
            *(float4*)&red[r * RSTRIDE + kq * 128 + cq * 4] =
                make_float4(acc[r * 4], acc[r * 4 + 1], acc[r * 4 + 2], acc[r * 4 + 3]);
        __syncthreads();
        v0 = 0.f; v1 = 0.f;
        #pragma unroll
        for (int g = 0; g < 8; g++) {
            float2 rv = *(const float2*)&red[row_o * RSTRIDE + g * 128 + coll];
            v0 += rv.x; v1 += rv.y;
        }
        float2 yo = make_float2(sigf(v0 + byv0), sigf(v1 + byv1));
        *(float2*)&out[((size_t)brow * LL + i) * OO + col] = yo;
        __syncthreads();
    }

    cluster_sync_all();
}

// ---------------------------------------------------------------------------
extern "C" void kernel_launch(void* const* d_in, const int* in_sizes, int n_in,
                              void* d_out, int out_size)
{
    const float* x   = (const float*)d_in[0];
    const float* W1x = (const float*)d_in[1];
    const float* b1x = (const float*)d_in[2];
    const float* W1a = (const float*)d_in[3];
    const float* b1a = (const float*)d_in[4];
    const float* W2x = (const float*)d_in[5];
    const float* b2x = (const float*)d_in[6];
    const float* W2a = (const float*)d_in[7];
    const float* b2a = (const float*)d_in[8];
    const float* Wy  = (const float*)d_in[9];
    const float* by  = (const float*)d_in[10];
    float* out = (float*)d_out;

    (void)in_sizes; (void)n_in; (void)out_size;

    cudaFuncSetAttribute(xproj_mma_kernel,
                         cudaFuncAttributeMaxDynamicSharedMemorySize, XP_SMEM);
    cudaFuncSetAttribute(rnn_kernel,
                         cudaFuncAttributeMaxDynamicSharedMemorySize, SMEM_BYTES);

    wconv_kernel<<<256, 256>>>(W1x);
    dim3 xgrid((BB * SS) / 128, HH / 128);
    xproj_mma_kernel<<<xgrid, 256, XP_SMEM>>>(x, b1x, b1a);
    rnn_kernel<<<BB / 2, 256, SMEM_BYTES>>>(W1a, W2x, b2x, W2a, b2a, Wy, by, out);
}

// round 10
// speedup vs baseline: 1.3411x; 1.0274x over previous
#include <cuda_runtime.h>
#include <cuda_bf16.h>
#include <math.h>
#include <stdint.h>

#define BB 256
#define SS 512
#define II 256
#define HH 256
#define OO 256
#define LL 64

__device__ float g_xproj[(size_t)SS * BB * HH];
__device__ __nv_bfloat16 g_wh[256 * 256];   // W1x^T hi: [n][k]
__device__ __nv_bfloat16 g_wl[256 * 256];   // W1x^T lo: [n][k]

__device__ __forceinline__ float sigf(float x) {
    return __fdividef(1.f, 1.f + __expf(-x));
}
__device__ __forceinline__ float tanhfast(float x) {
    float e = __expf(2.f * x);
    return 1.f - __fdividef(2.f, e + 1.f);
}

// ---------------------------------------------------------------------------
// PTX helpers
// ---------------------------------------------------------------------------
__device__ __forceinline__ uint32_t smem_u32(const void* p) {
    uint32_t r;
    asm("{ .reg .u64 t; cvta.to.shared.u64 t, %1; cvt.u32.u64 %0, t; }" : "=r"(r) : "l"(p));
    return r;
}
__device__ __forceinline__ uint32_t mapa_peer(uint32_t a, uint32_t peer) {
    uint32_t r;
    asm("mapa.shared::cluster.u32 %0, %1, %2;" : "=r"(r) : "r"(a), "r"(peer));
    return r;
}
__device__ __forceinline__ void mbar_init(uint32_t a, uint32_t c) {
    asm volatile("mbarrier.init.shared.b64 [%0], %1;" :: "r"(a), "r"(c) : "memory");
}
__device__ __forceinline__ void mbar_arrive_cluster(uint32_t a) {
    asm volatile("mbarrier.arrive.release.cluster.shared::cluster.b64 _, [%0];"
                 :: "r"(a) : "memory");
}
__device__ __forceinline__ void mbar_wait_par(uint32_t a, uint32_t par) {
    asm volatile(
        "{\n\t.reg .pred P;\n\t"
        "WL%=:\n\t"
        "mbarrier.try_wait.parity.acquire.cluster.shared::cta.b64 P, [%0], %1, 0x989680;\n\t"
        "@P bra WD%=;\n\t"
        "bra WL%=;\n\t"
        "WD%=:\n\t}"
        :: "r"(a), "r"(par) : "memory");
}
__device__ __forceinline__ void st_cluster_f4(uint32_t a, float4 v) {
    asm volatile("st.shared::cluster.v4.b32 [%0], {%1,%2,%3,%4};" :: "r"(a),
                 "r"(__float_as_uint(v.x)), "r"(__float_as_uint(v.y)),
                 "r"(__float_as_uint(v.z)), "r"(__float_as_uint(v.w)) : "memory");
}
__device__ __forceinline__ void cluster_sync_all() {
    asm volatile("barrier.cluster.arrive.aligned;" ::: "memory");
    asm volatile("barrier.cluster.wait.aligned;" ::: "memory");
}
__device__ __forceinline__ void ldsm_x4(uint32_t addr, uint32_t r[4]) {
    asm volatile("ldmatrix.sync.aligned.m8n8.x4.shared.b16 {%0,%1,%2,%3}, [%4];"
                 : "=r"(r[0]), "=r"(r[1]), "=r"(r[2]), "=r"(r[3]) : "r"(addr));
}
__device__ __forceinline__ void ldsm_x2t(uint32_t addr, uint32_t& r0, uint32_t& r1) {
    asm volatile("ldmatrix.sync.aligned.m8n8.x2.trans.shared.b16 {%0,%1}, [%2];"
                 : "=r"(r0), "=r"(r1) : "r"(addr));
}
__device__ __forceinline__ void mma_bf16(float c[4], const uint32_t a[4],
                                         uint32_t b0, uint32_t b1) {
    asm volatile(
        "mma.sync.aligned.m16n8k16.row.col.f32.bf16.bf16.f32 "
        "{%0,%1,%2,%3}, {%4,%5,%6,%7}, {%8,%9}, {%0,%1,%2,%3};"
        : "+f"(c[0]), "+f"(c[1]), "+f"(c[2]), "+f"(c[3])
        : "r"(a[0]), "r"(a[1]), "r"(a[2]), "r"(a[3]), "r"(b0), "r"(b1));
}
__device__ __forceinline__ uint32_t packbf2(float a, float b) {
    __nv_bfloat16 ha = __float2bfloat16(a), hb = __float2bfloat16(b);
    return ((uint32_t)__bfloat16_as_ushort(hb) << 16) | __bfloat16_as_ushort(ha);
}
__device__ __forceinline__ float bfu(uint32_t u) {
    return __bfloat162float(__ushort_as_bfloat16((unsigned short)(u & 0xffffu)));
}

// ===========================================================================
// Kernel 0: W1x -> bf16 hi/lo, transposed to [n][k]
// ===========================================================================
__global__ void wconv_kernel(const float* __restrict__ W1x)
{
    int k = blockIdx.x, n = threadIdx.x;
    float v = W1x[k * 256 + n];
    __nv_bfloat16 h = __float2bfloat16(v);
    __nv_bfloat16 l = __float2bfloat16(v - __bfloat162float(h));
    g_wh[n * 256 + k] = h;
    g_wl[n * 256 + k] = l;
}

// ===========================================================================
// Kernel 1: xproj via mma.sync bf16 hi/lo (R8 verbatim — proven).
// ===========================================================================
#define SB_BH    0
#define SB_BL    65536
#define SB_A     131072
#define SB_BIAS  196608
#define XP_SMEM  197120

__device__ __forceinline__ void afragx(uint32_t Ab, int mbase, int j, int lane,
                                       uint32_t r[4]) {
    int row = mbase + (lane & 15);
    int q   = j * 2 + (lane >> 4);
    uint32_t addr = Ab + (uint32_t)(row * 128 + ((q ^ row) & 7) * 16);
    ldsm_x4(addr, r);
}
__device__ __forceinline__ void bfragx(uint32_t Bb, int nbase, int ks, int lane,
                                       uint32_t r[4]) {
    int row = nbase + (lane & 7) + ((lane >> 4) << 3);
    int q   = ks * 2 + ((lane >> 3) & 1);
    uint32_t qp = (uint32_t)((q & ~7) | ((q ^ row) & 7));
    uint32_t addr = Bb + (uint32_t)(row * 512) + qp * 16;
    ldsm_x4(addr, r);
}

__device__ __forceinline__ void load_a_chunk(unsigned char* sm, int p,
                                             const float* __restrict__ x,
                                             int b0, int s, int c, int t)
{
    const int r = t >> 1, hf = t & 1, rx = r & 7;
    unsigned char* ah = sm + SB_A + p * 32768;
    unsigned char* al = ah + 16384;
    const float* xr = x + ((size_t)(b0 + r) * SS + s) * II + c * 64 + hf * 32;
    #pragma unroll
    for (int jj = 0; jj < 4; jj++) {
        float4 v0 = *(const float4*)(xr + jj * 8);
        float4 v1 = *(const float4*)(xr + jj * 8 + 4);
        uint4 h, l;
        h.x = packbf2(v0.x, v0.y); h.y = packbf2(v0.z, v0.w);
        h.z = packbf2(v1.x, v1.y); h.w = packbf2(v1.z, v1.w);
        l.x = packbf2(v0.x - __bfloat162float(__float2bfloat16(v0.x)),
                      v0.y - __bfloat162float(__float2bfloat16(v0.y)));
        l.y = packbf2(v0.z - __bfloat162float(__float2bfloat16(v0.z)),
                      v0.w - __bfloat162float(__float2bfloat16(v0.w)));
        l.z = packbf2(v1.x - __bfloat162float(__float2bfloat16(v1.x)),
                      v1.y - __bfloat162float(__float2bfloat16(v1.y)));
        l.w = packbf2(v1.z - __bfloat162float(__float2bfloat16(v1.z)),
                      v1.w - __bfloat162float(__float2bfloat16(v1.w)));
        int q = hf * 4 + jj;
        uint32_t off = (uint32_t)(r * 128 + (q ^ rx) * 16);
        *(uint4*)(ah + off) = h;
        *(uint4*)(al + off) = l;
    }
}

__global__ __launch_bounds__(256, 1) void xproj_mma_kernel(
    const float* __restrict__ x,
    const float* __restrict__ b1x, const float* __restrict__ b1a)
{
    extern __shared__ __align__(1024) unsigned char sm[];
    const int t = threadIdx.x;
    const int wid = t >> 5, lane = t & 31;
    const uint32_t smb = smem_u32(sm);

    const int m0 = blockIdx.x * 128;
    const int n0 = blockIdx.y * 128;
    const int s  = m0 >> 8;
    const int b0 = m0 & 255;
    const int mw = (wid & 1) * 64;
    const int nw = (wid >> 1) * 32;

    #pragma unroll 4
    for (int i = 0; i < 16; i++) {
        int idx = i * 256 + t;
        int rr = idx >> 5, q = idx & 31;
        uint32_t qp = (uint32_t)((q & ~7) | ((q ^ rr) & 7));
        size_t src = (size_t)(n0 + rr) * 256 + q * 8;
        *(uint4*)(sm + SB_BH + rr * 512 + qp * 16) = *(const uint4*)(g_wh + src);
        *(uint4*)(sm + SB_BL + rr * 512 + qp * 16) = *(const uint4*)(g_wl + src);
    }
    if (t < 128)
        ((float*)(sm + SB_BIAS))[t] = b1x[n0 + t] + b1a[n0 + t];

    load_a_chunk(sm, 0, x, b0, s, 0, t);
    __syncthreads();

    float acc[4][4][4];
    #pragma unroll
    for (int mt = 0; mt < 4; mt++)
        #pragma unroll
        for (int nt = 0; nt < 4; nt++)
            #pragma unroll
            for (int e = 0; e < 4; e++) acc[mt][nt][e] = 0.f;

    const uint32_t Bh = smb + SB_BH, Bl = smb + SB_BL;

    #pragma unroll 1
    for (int c = 0; c < 4; c++) {
        const int p = c & 1;
        if (c < 3) load_a_chunk(sm, 1 - p, x, b0, s, c + 1, t);
        const uint32_t Abh = smb + SB_A + p * 32768;
        const uint32_t Abl = Abh + 16384;

        #pragma unroll
        for (int j = 0; j < 4; j++) {
            const int ks = c * 4 + j;
            uint32_t bh[8], bl[8];
            bfragx(Bh, nw,      ks, lane, bh);
            bfragx(Bh, nw + 16, ks, lane, bh + 4);
            bfragx(Bl, nw,      ks, lane, bl);
            bfragx(Bl, nw + 16, ks, lane, bl + 4);
            #pragma unroll
            for (int mt = 0; mt < 4; mt++) {
                uint32_t ah[4], al[4];
                afragx(Abh, mw + mt * 16, j, lane, ah);
                afragx(Abl, mw + mt * 16, j, lane, al);
                #pragma unroll
                for (int nt = 0; nt < 4; nt++) {
                    mma_bf16(acc[mt][nt], ah, bh[nt * 2], bh[nt * 2 + 1]);
                    mma_bf16(acc[mt][nt], ah, bl[nt * 2], bl[nt * 2 + 1]);
                    mma_bf16(acc[mt][nt], al, bh[nt * 2], bh[nt * 2 + 1]);
                }
            }
        }
        __syncthreads();
    }

    const int g = lane >> 2, tig = lane & 3;
    const float* bias_sm = (const float*)(sm + SB_BIAS);
    #pragma unroll
    for (int mt = 0; mt < 4; mt++) {
        const int mrow = m0 + mw + mt * 16 + g;
        #pragma unroll
        for (int nt = 0; nt < 4; nt++) {
            const int nl = nw + nt * 8 + tig * 2;
            const float bz0 = bias_sm[nl], bz1 = bias_sm[nl + 1];
            float2 v0 = make_float2(acc[mt][nt][0] + bz0, acc[mt][nt][1] + bz1);
            float2 v1 = make_float2(acc[mt][nt][2] + bz0, acc[mt][nt][3] + bz1);
            *(float2*)&g_xproj[(size_t)mrow * HH + n0 + nl] = v0;
            *(float2*)&g_xproj[(size_t)(mrow + 8) * HH + n0 + nl] = v1;
        }
    }
}

// ===========================================================================
// Kernel 2: RNN. Encoder = tensor-core (mma.sync bf16 hi/lo), decoder = R4 FMA.
// SMEM layout (bytes):
//   0      : encoder A = W1a^T hi [128m x 264k x 2B] (67584)   | decoder ws (131072)
//   67584  : encoder A lo (67584)                               | (ws/wy_lo)
//   131072 :                                                     | wy_lo (65536)
//   196608 : a4s float4[2][256] (8192)
//   204800 : y4s float4[256] (4096)
//   208896 : red (16512, decoder)  | encoder B state: 2 bufs x (hi 4096 + lo 4096)
//   225408 : mbars (32)
// ===========================================================================
#define A_STRIDE 528
#define ALO      67584
#define BOFF     208896
#define MBOFF    225408
#define RNN_SMEM 225440
#define RSTRIDE  1032

__device__ __forceinline__ void gemv16_s(const float* __restrict__ Wp,
                                         const float4* __restrict__ a, float acc[16])
{
    #pragma unroll
    for (int j = 0; j < 16; j++) acc[j] = 0.f;
    #pragma unroll 8
    for (int k = 0; k < 32; k++) {
        float4 w  = *(const float4*)(Wp + k * 128);
        float4 av = a[k];
        acc[0]  = fmaf(av.x, w.x, acc[0]);  acc[1]  = fmaf(av.x, w.y, acc[1]);
        acc[2]  = fmaf(av.x, w.z, acc[2]);  acc[3]  = fmaf(av.x, w.w, acc[3]);
        acc[4]  = fmaf(av.y, w.x, acc[4]);  acc[5]  = fmaf(av.y, w.y, acc[5]);
        acc[6]  = fmaf(av.y, w.z, acc[6]);  acc[7]  = fmaf(av.y, w.w, acc[7]);
        acc[8]  = fmaf(av.z, w.x, acc[8]);  acc[9]  = fmaf(av.z, w.y, acc[9]);
        acc[10] = fmaf(av.z, w.z, acc[10]); acc[11] = fmaf(av.z, w.w, acc[11]);
        acc[12] = fmaf(av.w, w.x, acc[12]); acc[13] = fmaf(av.w, w.y, acc[13]);
        acc[14] = fmaf(av.w, w.z, acc[14]); acc[15] = fmaf(av.w, w.w, acc[15]);
    }
}
__device__ __forceinline__ void gemv16_g(const float* __restrict__ Wp,
                                         const float4* __restrict__ a, float acc[16])
{
    #pragma unroll
    for (int j = 0; j < 16; j++) acc[j] = 0.f;
    #pragma unroll 16
    for (int k = 0; k < 32; k++) {
        float4 w  = *(const float4*)(Wp + (size_t)k * 256);
        float4 av = a[k];
        acc[0]  = fmaf(av.x, w.x, acc[0]);  acc[1]  = fmaf(av.x, w.y, acc[1]);
        acc[2]  = fmaf(av.x, w.z, acc[2]);  acc[3]  = fmaf(av.x, w.w, acc[3]);
        acc[4]  = fmaf(av.y, w.x, acc[4]);  acc[5]  = fmaf(av.y, w.y, acc[5]);
        acc[6]  = fmaf(av.y, w.z, acc[6]);  acc[7]  = fmaf(av.y, w.w, acc[7]);
        acc[8]  = fmaf(av.z, w.x, acc[8]);  acc[9]  = fmaf(av.z, w.y, acc[9]);
        acc[10] = fmaf(av.z, w.z, acc[10]); acc[11] = fmaf(av.z, w.w, acc[11]);
        acc[12] = fmaf(av.w, w.x, acc[12]); acc[13] = fmaf(av.w, w.y, acc[13]);
        acc[14] = fmaf(av.w, w.z, acc[14]); acc[15] = fmaf(av.w, w.w, acc[15]);
    }
}

__device__ __forceinline__ void fill_w(float* dst, const float* __restrict__ W,
                                       int c0, int t, int nk)
{
    const int lane = t & 31, w = t >> 5;
    for (int i = 0; i < nk / 8; i++) {
        int k = i * 8 + w;
        float4 v = *(const float4*)(W + (size_t)k * 256 + c0 + lane * 4);
        *(float4*)(dst + k * 128 + lane * 4) = v;
    }
}

__global__ __launch_bounds__(256, 1) __cluster_dims__(2, 1, 1)
void rnn_kernel(const float* __restrict__ W1a,
                const float* __restrict__ W2x, const float* __restrict__ b2x,
                const float* __restrict__ W2a, const float* __restrict__ b2a,
                const float* __restrict__ Wy,  const float* __restrict__ by,
                float* __restrict__ out)
{
    extern __shared__ __align__(16) unsigned char dsm[];
    float*  ws    = (float*)dsm;
    float*  wy_lo = (float*)(dsm + 131072);
    float4* a4s   = (float4*)(dsm + 196608);
    float4* y4s   = (float4*)(dsm + 204800);
    float*  red   = (float*)(dsm + 208896);
    unsigned long long* mbars = (unsigned long long*)(dsm + MBOFF);

    const int t    = threadIdx.x;
    const int lane = t & 31;
    const int wid  = t >> 5;        // 0..7
    uint32_t rank;
    asm("mov.u32 %0, %%cluster_ctarank;" : "=r"(rank));
    const uint32_t peer = rank ^ 1;
    const int b0 = (blockIdx.x >> 1) * 4;
    const int c0 = (int)rank * 128;
    const uint32_t smb = smem_u32(dsm);

    // encoder thread mapping
    const int mb   = wid * 16;
    const int g    = lane >> 2;
    const int tig  = lane & 3;
    const bool act = (tig < 2);
    const int colg = c0 + mb + g;               // global col of c0/c1
    const int nb   = 2 * tig;                   // batch offset
    const uint32_t aAddrBase = smb + (uint32_t)((mb + (lane & 15)) * A_STRIDE)
                             + (uint32_t)((lane >> 4) * 16);

    // decoder thread mapping (R4)
    const int kq = wid, cq = lane;
    const bool is_peer = ((uint32_t)(kq >> 2) != rank);
    const int o0    = 2 * t;
    const int row_o = (o0 >> 2) & 3;
    const int coll  = (o0 >> 4) * 4 + (o0 & 3);
    const int col   = c0 + coll;
    const int brow  = b0 + row_o;

    // mbarriers
    uint32_t mF[2], mRD[2], pF[2], pRD[2];
    mF[0]  = smem_u32(&mbars[0]); mF[1]  = smem_u32(&mbars[1]);
    mRD[0] = smem_u32(&mbars[2]); mRD[1] = smem_u32(&mbars[3]);
    pF[0]  = mapa_peer(mF[0], peer);  pF[1]  = mapa_peer(mF[1], peer);
    pRD[0] = mapa_peer(mRD[0], peer); pRD[1] = mapa_peer(mRD[1], peer);
    uint32_t pa4[2];
    pa4[0] = mapa_peer(smem_u32(&a4s[0]), peer);
    pa4[1] = mapa_peer(smem_u32(&a4s[256]), peer);
    uint32_t py4 = mapa_peer(smem_u32(&y4s[0]), peer);
    uint32_t pB[2];
    pB[0] = mapa_peer(smb + BOFF, peer);
    pB[1] = mapa_peer(smb + BOFF + 8192, peer);

    if (t == 0) {
        mbar_init(mF[0], 32);  mbar_init(mF[1], 32);
        mbar_init(mRD[0], 32); mbar_init(mRD[1], 32);
    }
    // zero encoder B state (both buffers incl. garbage batch rows 4-7)
    {
        float4 z = make_float4(0.f, 0.f, 0.f, 0.f);
        #pragma unroll
        for (int i = 0; i < 4; i++)
            *(float4*)(dsm + BOFF + (i * 256 + t) * 16) = z;
    }
    // stage A = W1a^T hi/lo  ([m=local col][k], stride 528B)
    {
        const int m = t & 127, hb = t >> 7;
        #pragma unroll 4
        for (int kk = 0; kk < 128; kk++) {
            int k = hb * 128 + kk;
            float v = W1a[(size_t)k * 256 + c0 + m];
            __nv_bfloat16 h = __float2bfloat16(v);
            __nv_bfloat16 l = __float2bfloat16(v - __bfloat162float(h));
            *(unsigned short*)(dsm + m * A_STRIDE + k * 2) = __bfloat16_as_ushort(h);
            *(unsigned short*)(dsm + ALO + m * A_STRIDE + k * 2) = __bfloat16_as_ushort(l);
        }
    }
    __syncthreads();
    cluster_sync_all();
    if (wid == 0) mbar_arrive_cluster(pF[0]);    // prime: initial zeros valid
    if (wid == 1) mbar_arrive_cluster(pRD[1]);   // prime: peer B[1] never read

    int fpar[2]  = {0, 0};
    int rdpar[2] = {0, 0};

    // ======================= encoder (tensor core) =======================
    for (int s = 0; s < SS; s++) {
        const int p = s & 1, q = p ^ 1;
        const uint32_t BpH  = smb + BOFF + (uint32_t)p * 8192;
        const uint32_t BqO  = (uint32_t)BOFF + (uint32_t)q * 8192;

        float xp00 = 0.f, xp01 = 0.f, xp10 = 0.f, xp11 = 0.f;
        if (act) {
            const float* xb = g_xproj + ((size_t)s * BB + (b0 + nb)) * HH;
            xp00 = __ldcs(xb + colg);
            xp01 = __ldcs(xb + HH + colg);
            xp10 = __ldcs(xb + colg + 8);
            xp11 = __ldcs(xb + HH + colg + 8);
        }

        float acc[6][4];
        #pragma unroll
        for (int i = 0; i < 6; i++)
            #pragma unroll
            for (int e = 0; e < 4; e++) acc[i][e] = 0.f;

        #pragma unroll
        for (int hv = 0; hv < 2; hv++) {
            const int kb = hv ? (c0 ^ 128) : c0;     // own half first, peer second
            if (hv) mbar_wait_par(mF[p], fpar[p]);
            #pragma unroll
            for (int j = 0; j < 8; j++) {
                const int k0 = kb + j * 16;
                uint32_t ah[4], al[4], bh0, bh1, bl0, bl1;
                uint32_t aa = aAddrBase + (uint32_t)k0 * 2;
                ldsm_x4(aa, ah);
                ldsm_x4(aa + ALO, al);
                uint32_t ba = BpH + (uint32_t)((k0 + (lane & 15)) * 16);
                ldsm_x2t(ba, bh0, bh1);
                ldsm_x2t(ba + 4096, bl0, bl1);
                const int sel = j & 1;
                mma_bf16(acc[sel],     ah, bh0, bh1);
                mma_bf16(acc[2 + sel], ah, bl0, bl1);
                mma_bf16(acc[4 + sel], al, bh0, bh1);
            }
        }
        fpar[p] ^= 1;
        __syncthreads();                               // sync1: B[p] reads done
        if (wid == 1) mbar_arrive_cluster(pRD[p]);

        if (act) {
            float s0 = acc[0][0]+acc[1][0]+acc[2][0]+acc[3][0]+acc[4][0]+acc[5][0];
            float s1 = acc[0][1]+acc[1][1]+acc[2][1]+acc[3][1]+acc[4][1]+acc[5][1];
            float s2 = acc[0][2]+acc[1][2]+acc[2][2]+acc[3][2]+acc[4][2]+acc[5][2];
            float s3 = acc[0][3]+acc[1][3]+acc[2][3]+acc[3][3]+acc[4][3]+acc[5][3];
            float t00 = tanhfast(s0 + xp00);
            float t01 = tanhfast(s1 + xp01);
            float t10 = tanhfast(s2 + xp10);
            float t11 = tanhfast(s3 + xp11);
            __nv_bfloat16 h00 = __float2bfloat16(t00), h01 = __float2bfloat16(t01);
            __nv_bfloat16 h10 = __float2bfloat16(t10), h11 = __float2bfloat16(t11);
            float l00 = t00 - __bfloat162float(h00), l01 = t01 - __bfloat162float(h01);
            float l10 = t10 - __bfloat162float(h10), l11 = t11 - __bfloat162float(h11);
            unsigned char* bq = dsm + BqO;
            *(uint32_t*)(bq + colg * 16 + tig * 4) =
                ((uint32_t)__bfloat16_as_ushort(h01) << 16) | __bfloat16_as_ushort(h00);
            *(uint32_t*)(bq + (colg + 8) * 16 + tig * 4) =
                ((uint32_t)__bfloat16_as_ushort(h11) << 16) | __bfloat16_as_ushort(h10);
            *(uint32_t*)(bq + 4096 + colg * 16 + tig * 4) = packbf2(l00, l01);
            *(uint32_t*)(bq + 4096 + (colg + 8) * 16 + tig * 4) = packbf2(l10, l11);
        }
        __syncthreads();                               // sync2: local half of B[q]

        if (wid == 0) {
            mbar_wait_par(mRD[q], rdpar[q]);
            const uint32_t pb = pB[q];
            #pragma unroll
            for (int it = 0; it < 4; it++) {
                uint32_t off = (uint32_t)(c0 * 16 + (it * 32 + lane) * 16);
                float4 vh = *(const float4*)(dsm + BqO + off);
                float4 vl = *(const float4*)(dsm + BqO + 4096 + off);
                st_cluster_f4(pb + off, vh);
                st_cluster_f4(pb + 4096 + off, vl);
            }
            mbar_arrive_cluster(pF[q]);
        }
        rdpar[q] ^= 1;
    }

    // final state in B[0]; wait for peer half, then reconstruct fp32 a_last
    mbar_wait_par(mF[0], fpar[0]); fpar[0] ^= 1;
    {
        uint32_t w0h = *(const uint32_t*)(dsm + BOFF + t * 16);
        uint32_t w1h = *(const uint32_t*)(dsm + BOFF + t * 16 + 4);
        uint32_t w0l = *(const uint32_t*)(dsm + BOFF + 4096 + t * 16);
        uint32_t w1l = *(const uint32_t*)(dsm + BOFF + 4096 + t * 16 + 4);
        a4s[t] = make_float4(bfu(w0h) + bfu(w0l), bfu(w0h >> 16) + bfu(w0l >> 16),
                             bfu(w1h) + bfu(w1l), bfu(w1h >> 16) + bfu(w1l >> 16));
    }
    __syncthreads();

    // ======================= glue (R4) =======================
    float byv0, byv1, bb0, bb1, base00, base01;
    {
        float2 byv = *(const float2*)&by[col];
        byv0 = byv.x; byv1 = byv.y;
        float2 b2xv = *(const float2*)&b2x[col];
        float2 b2av = *(const float2*)&b2a[col];
        bb0 = b2xv.x + b2av.x; bb1 = b2xv.y + b2av.y;

        float acc[16];
        gemv16_g(Wy + (size_t)(kq * 32) * 256 + c0 + cq * 4, &a4s[kq * 32], acc);
        #pragma unroll
        for (int r = 0; r < 4; r++)
            *(float4*)&red[r * RSTRIDE + kq * 128 + cq * 4] =
                make_float4(acc[r * 4], acc[r * 4 + 1], acc[r * 4 + 2], acc[r * 4 + 3]);
        __syncthreads();
        float v0 = 0.f, v1 = 0.f;
        #pragma unroll
        for (int gg = 0; gg < 8; gg++) {
            float2 rv = *(const float2*)&red[row_o * RSTRIDE + gg * 128 + coll];
            v0 += rv.x; v1 += rv.y;
        }
        ((float*)&y4s[col])[row_o]     = sigf(v0 + byv0);
        ((float*)&y4s[col + 1])[row_o] = sigf(v1 + byv1);
        __syncthreads();
        if (kq == 0) {
            #pragma unroll
            for (int j = 0; j < 4; j++) {
                int idx = c0 + cq + 32 * j;
                st_cluster_f4(py4 + (uint32_t)idx * 16u, y4s[idx]);
            }
        }
        cluster_sync_all();

        gemv16_g(W2x + (size_t)(kq * 32) * 256 + c0 + cq * 4, y4s + kq * 32, acc);
        #pragma unroll
        for (int r = 0; r < 4; r++)
            *(float4*)&red[r * RSTRIDE + kq * 128 + cq * 4] =
                make_float4(acc[r * 4], acc[r * 4 + 1], acc[r * 4 + 2], acc[r * 4 + 3]);
        __syncthreads();
        v0 = 0.f; v1 = 0.f;
        #pragma unroll
        for (int gg = 0; gg < 8; gg++) {
            float2 rv = *(const float2*)&red[row_o * RSTRIDE + gg * 128 + coll];
            v0 += rv.x; v1 += rv.y;
        }
        base00 = v0 + bb0; base01 = v1 + bb1;
        __syncthreads();
    }

    // restage weights for decoder
    fill_w(ws, W2a, c0, t, 256);
    fill_w(wy_lo, Wy, c0, t, 128);
    __syncthreads();

    const float* wsp   = ws + kq * 32 * 128 + cq * 4;
    const float* wylop = wy_lo + kq * 32 * 128 + cq * 4;

    // ======================= decoder (R4) =======================
    for (int i = 0; i < LL; i++) {
        const int p = i & 1, q = p ^ 1;
        float acc[16];

        gemv16_s(wsp, &a4s[p * 256 + kq * 32], acc);
        #pragma unroll
        for (int r = 0; r < 4; r++)
            *(float4*)&red[r * RSTRIDE + kq * 128 + cq * 4] =
                make_float4(acc[r * 4], acc[r * 4 + 1], acc[r * 4 + 2], acc[r * 4 + 3]);
        __syncthreads();
        if (kq == 1) mbar_arrive_cluster(pRD[p]);

        float v0 = 0.f, v1 = 0.f;
        #pragma unroll
        for (int gg = 0; gg < 8; gg++) {
            float2 rv = *(const float2*)&red[row_o * RSTRIDE + gg * 128 + coll];
            v0 += rv.x; v1 += rv.y;
        }
        float bs0 = (i == 0) ? base00 : bb0;
        float bs1 = (i == 0) ? base01 : bb1;
        ((float*)&a4s[q * 256 + col])[row_o]     = tanhfast(v0 + bs0);
        ((float*)&a4s[q * 256 + col + 1])[row_o] = tanhfast(v1 + bs1);
        __syncthreads();

        if (kq == 0) mbar_wait_par(mRD[q], rdpar[q]);
        rdpar[q] ^= 1;
        if (kq == 0) {
            #pragma unroll
            for (int j = 0; j < 4; j++) {
                int idx = c0 + cq + 32 * j;
                st_cluster_f4(pa4[q] + (uint32_t)idx * 16u, a4s[q * 256 + idx]);
            }
            mbar_arrive_cluster(pF[q]);
        }

        if (is_peer) mbar_wait_par(mF[q], fpar[q]);
        fpar[q] ^= 1;

        if (kq < 4) gemv16_s(wylop, &a4s[q * 256 + kq * 32], acc);
        else        gemv16_g(Wy + (size_t)(kq * 32) * 256 + c0 + cq * 4,
                             &a4s[q * 256 + kq * 32], acc);
        #pragma unroll
        for (int r = 0; r < 4; r++)
            *(float4*)&red[r * RSTRIDE + kq * 128 + cq * 4] =
                make_float4(acc[r * 4], acc[r * 4 + 1], acc[r * 4 + 2], acc[r * 4 + 3]);
        __syncthreads();
        v0 = 0.f; v1 = 0.f;
        #pragma unroll
        for (int gg = 0; gg < 8; gg++) {
            float2 rv = *(const float2*)&red[row_o * RSTRIDE + gg * 128 + coll];
            v0 += rv.x; v1 += rv.y;
        }
        float2 yo = make_float2(sigf(v0 + byv0), sigf(v1 + byv1));
        *(float2*)&out[((size_t)brow * LL + i) * OO + col] = yo;
        __syncthreads();
    }

    cluster_sync_all();
}

// ---------------------------------------------------------------------------
extern "C" void kernel_launch(void* const* d_in, const int* in_sizes, int n_in,
                              void* d_out, int out_size)
{
    const float* x   = (const float*)d_in[0];
    const float* W1x = (const float*)d_in[1];
    const float* b1x = (const float*)d_in[2];
    const float* W1a = (const float*)d_in[3];
    const float* b1a = (const float*)d_in[4];
    const float* W2x = (const float*)d_in[5];
    const float* b2x = (const float*)d_in[6];
    const float* W2a = (const float*)d_in[7];
    const float* b2a = (const float*)d_in[8];
    const float* Wy  = (const float*)d_in[9];
    const float* by  = (const float*)d_in[10];
    float* out = (float*)d_out;

    (void)in_sizes; (void)n_in; (void)out_size;

    cudaFuncSetAttribute(xproj_mma_kernel,
                         cudaFuncAttributeMaxDynamicSharedMemorySize, XP_SMEM);
    cudaFuncSetAttribute(rnn_kernel,
                         cudaFuncAttributeMaxDynamicSharedMemorySize, RNN_SMEM);

    wconv_kernel<<<256, 256>>>(W1x);
    dim3 xgrid((BB * SS) / 128, HH / 128);
    xproj_mma_kernel<<<xgrid, 256, XP_SMEM>>>(x, b1x, b1a);
    rnn_kernel<<<BB / 2, 256, RNN_SMEM>>>(W1a, W2x, b2x, W2a, b2a, Wy, by, out);
}

// round 11
// speedup vs baseline: 1.3468x; 1.0042x over previous
#include <cuda_runtime.h>
#include <cuda_bf16.h>
#include <math.h>
#include <stdint.h>

#define BB 256
#define SS 512
#define II 256
#define HH 256
#define OO 256
#define LL 64

__device__ float g_xproj[(size_t)SS * BB * HH];
__device__ __nv_bfloat16 g_wh[256 * 256];   // W1x^T hi: [n][k]
__device__ __nv_bfloat16 g_wl[256 * 256];   // W1x^T lo: [n][k]

__device__ __forceinline__ float sigf(float x) {
    return __fdividef(1.f, 1.f + __expf(-x));
}
__device__ __forceinline__ float tanhfast(float x) {
    float e = __expf(2.f * x);
    return 1.f - __fdividef(2.f, e + 1.f);
}

// ---------------------------------------------------------------------------
// PTX helpers
// ---------------------------------------------------------------------------
__device__ __forceinline__ uint32_t smem_u32(const void* p) {
    uint32_t r;
    asm("{ .reg .u64 t; cvta.to.shared.u64 t, %1; cvt.u32.u64 %0, t; }" : "=r"(r) : "l"(p));
    return r;
}
__device__ __forceinline__ uint32_t mapa_peer(uint32_t a, uint32_t peer) {
    uint32_t r;
    asm("mapa.shared::cluster.u32 %0, %1, %2;" : "=r"(r) : "r"(a), "r"(peer));
    return r;
}
__device__ __forceinline__ void mbar_init(uint32_t a, uint32_t c) {
    asm volatile("mbarrier.init.shared.b64 [%0], %1;" :: "r"(a), "r"(c) : "memory");
}
__device__ __forceinline__ void mbar_arrive_cluster(uint32_t a) {
    asm volatile("mbarrier.arrive.release.cluster.shared::cluster.b64 _, [%0];"
                 :: "r"(a) : "memory");
}
__device__ __forceinline__ void mbar_wait_par(uint32_t a, uint32_t par) {
    asm volatile(
        "{\n\t.reg .pred P;\n\t"
        "WL%=:\n\t"
        "mbarrier.try_wait.parity.acquire.cluster.shared::cta.b64 P, [%0], %1, 0x989680;\n\t"
        "@P bra WD%=;\n\t"
        "bra WL%=;\n\t"
        "WD%=:\n\t}"
        :: "r"(a), "r"(par) : "memory");
}
__device__ __forceinline__ void st_cluster_f4(uint32_t a, float4 v) {
    asm volatile("st.shared::cluster.v4.b32 [%0], {%1,%2,%3,%4};" :: "r"(a),
                 "r"(__float_as_uint(v.x)), "r"(__float_as_uint(v.y)),
                 "r"(__float_as_uint(v.z)), "r"(__float_as_uint(v.w)) : "memory");
}
__device__ __forceinline__ void cluster_sync_all() {
    asm volatile("barrier.cluster.arrive.aligned;" ::: "memory");
    asm volatile("barrier.cluster.wait.aligned;" ::: "memory");
}
__device__ __forceinline__ void ldsm_x4(uint32_t addr, uint32_t r[4]) {
    asm volatile("ldmatrix.sync.aligned.m8n8.x4.shared.b16 {%0,%1,%2,%3}, [%4];"
                 : "=r"(r[0]), "=r"(r[1]), "=r"(r[2]), "=r"(r[3]) : "r"(addr));
}
__device__ __forceinline__ void ldsm_x2t(uint32_t addr, uint32_t& r0, uint32_t& r1) {
    asm volatile("ldmatrix.sync.aligned.m8n8.x2.trans.shared.b16 {%0,%1}, [%2];"
                 : "=r"(r0), "=r"(r1) : "r"(addr));
}
__device__ __forceinline__ void mma_bf16(float c[4], const uint32_t a[4],
                                         uint32_t b0, uint32_t b1) {
    asm volatile(
        "mma.sync.aligned.m16n8k16.row.col.f32.bf16.bf16.f32 "
        "{%0,%1,%2,%3}, {%4,%5,%6,%7}, {%8,%9}, {%0,%1,%2,%3};"
        : "+f"(c[0]), "+f"(c[1]), "+f"(c[2]), "+f"(c[3])
        : "r"(a[0]), "r"(a[1]), "r"(a[2]), "r"(a[3]), "r"(b0), "r"(b1));
}
__device__ __forceinline__ uint32_t packbf2(float a, float b) {
    __nv_bfloat16 ha = __float2bfloat16(a), hb = __float2bfloat16(b);
    return ((uint32_t)__bfloat16_as_ushort(hb) << 16) | __bfloat16_as_ushort(ha);
}
__device__ __forceinline__ float bfu(uint32_t u) {
    return __bfloat162float(__ushort_as_bfloat16((unsigned short)(u & 0xffffu)));
}

// ===========================================================================
// Kernel 0: W1x -> bf16 hi/lo, transposed to [n][k]
// ===========================================================================
__global__ void wconv_kernel(const float* __restrict__ W1x)
{
    int k = blockIdx.x, n = threadIdx.x;
    float v = W1x[k * 256 + n];
    __nv_bfloat16 h = __float2bfloat16(v);
    __nv_bfloat16 l = __float2bfloat16(v - __bfloat162float(h));
    g_wh[n * 256 + k] = h;
    g_wl[n * 256 + k] = l;
}

// ===========================================================================
// Kernel 1: xproj via mma.sync bf16 hi/lo (R8 verbatim — proven).
// ===========================================================================
#define SB_BH    0
#define SB_BL    65536
#define SB_A     131072
#define SB_BIAS  196608
#define XP_SMEM  197120

__device__ __forceinline__ void afragx(uint32_t Ab, int mbase, int j, int lane,
                                       uint32_t r[4]) {
    int row = mbase + (lane & 15);
    int q   = j * 2 + (lane >> 4);
    uint32_t addr = Ab + (uint32_t)(row * 128 + ((q ^ row) & 7) * 16);
    ldsm_x4(addr, r);
}
__device__ __forceinline__ void bfragx(uint32_t Bb, int nbase, int ks, int lane,
                                       uint32_t r[4]) {
    int row = nbase + (lane & 7) + ((lane >> 4) << 3);
    int q   = ks * 2 + ((lane >> 3) & 1);
    uint32_t qp = (uint32_t)((q & ~7) | ((q ^ row) & 7));
    uint32_t addr = Bb + (uint32_t)(row * 512) + qp * 16;
    ldsm_x4(addr, r);
}

__device__ __forceinline__ void load_a_chunk(unsigned char* sm, int p,
                                             const float* __restrict__ x,
                                             int b0, int s, int c, int t)
{
    const int r = t >> 1, hf = t & 1, rx = r & 7;
    unsigned char* ah = sm + SB_A + p * 32768;
    unsigned char* al = ah + 16384;
    const float* xr = x + ((size_t)(b0 + r) * SS + s) * II + c * 64 + hf * 32;
    #pragma unroll
    for (int jj = 0; jj < 4; jj++) {
        float4 v0 = *(const float4*)(xr + jj * 8);
        float4 v1 = *(const float4*)(xr + jj * 8 + 4);
        uint4 h, l;
        h.x = packbf2(v0.x, v0.y); h.y = packbf2(v0.z, v0.w);
        h.z = packbf2(v1.x, v1.y); h.w = packbf2(v1.z, v1.w);
        l.x = packbf2(v0.x - __bfloat162float(__float2bfloat16(v0.x)),
                      v0.y - __bfloat162float(__float2bfloat16(v0.y)));
        l.y = packbf2(v0.z - __bfloat162float(__float2bfloat16(v0.z)),
                      v0.w - __bfloat162float(__float2bfloat16(v0.w)));
        l.z = packbf2(v1.x - __bfloat162float(__float2bfloat16(v1.x)),
                      v1.y - __bfloat162float(__float2bfloat16(v1.y)));
        l.w = packbf2(v1.z - __bfloat162float(__float2bfloat16(v1.z)),
                      v1.w - __bfloat162float(__float2bfloat16(v1.w)));
        int q = hf * 4 + jj;
        uint32_t off = (uint32_t)(r * 128 + (q ^ rx) * 16);
        *(uint4*)(ah + off) = h;
        *(uint4*)(al + off) = l;
    }
}

__global__ __launch_bounds__(256, 1) void xproj_mma_kernel(
    const float* __restrict__ x,
    const float* __restrict__ b1x, const float* __restrict__ b1a)
{
    extern __shared__ __align__(1024) unsigned char sm[];
    const int t = threadIdx.x;
    const int wid = t >> 5, lane = t & 31;
    const uint32_t smb = smem_u32(sm);

    const int m0 = blockIdx.x * 128;
    const int n0 = blockIdx.y * 128;
    const int s  = m0 >> 8;
    const int b0 = m0 & 255;
    const int mw = (wid & 1) * 64;
    const int nw = (wid >> 1) * 32;

    #pragma unroll 4
    for (int i = 0; i < 16; i++) {
        int idx = i * 256 + t;
        int rr = idx >> 5, q = idx & 31;
        uint32_t qp = (uint32_t)((q & ~7) | ((q ^ rr) & 7));
        size_t src = (size_t)(n0 + rr) * 256 + q * 8;
        *(uint4*)(sm + SB_BH + rr * 512 + qp * 16) = *(const uint4*)(g_wh + src);
        *(uint4*)(sm + SB_BL + rr * 512 + qp * 16) = *(const uint4*)(g_wl + src);
    }
    if (t < 128)
        ((float*)(sm + SB_BIAS))[t] = b1x[n0 + t] + b1a[n0 + t];

    load_a_chunk(sm, 0, x, b0, s, 0, t);
    __syncthreads();

    float acc[4][4][4];
    #pragma unroll
    for (int mt = 0; mt < 4; mt++)
        #pragma unroll
        for (int nt = 0; nt < 4; nt++)
            #pragma unroll
            for (int e = 0; e < 4; e++) acc[mt][nt][e] = 0.f;

    const uint32_t Bh = smb + SB_BH, Bl = smb + SB_BL;

    #pragma unroll 1
    for (int c = 0; c < 4; c++) {
        const int p = c & 1;
        if (c < 3) load_a_chunk(sm, 1 - p, x, b0, s, c + 1, t);
        const uint32_t Abh = smb + SB_A + p * 32768;
        const uint32_t Abl = Abh + 16384;

        #pragma unroll
        for (int j = 0; j < 4; j++) {
            const int ks = c * 4 + j;
            uint32_t bh[8], bl[8];
            bfragx(Bh, nw,      ks, lane, bh);
            bfragx(Bh, nw + 16, ks, lane, bh + 4);
            bfragx(Bl, nw,      ks, lane, bl);
            bfragx(Bl, nw + 16, ks, lane, bl + 4);
            #pragma unroll
            for (int mt = 0; mt < 4; mt++) {
                uint32_t ah[4], al[4];
                afragx(Abh, mw + mt * 16, j, lane, ah);
                afragx(Abl, mw + mt * 16, j, lane, al);
                #pragma unroll
                for (int nt = 0; nt < 4; nt++) {
                    mma_bf16(acc[mt][nt], ah, bh[nt * 2], bh[nt * 2 + 1]);
                    mma_bf16(acc[mt][nt], ah, bl[nt * 2], bl[nt * 2 + 1]);
                    mma_bf16(acc[mt][nt], al, bh[nt * 2], bh[nt * 2 + 1]);
                }
            }
        }
        __syncthreads();
    }

    const int g = lane >> 2, tig = lane & 3;
    const float* bias_sm = (const float*)(sm + SB_BIAS);
    #pragma unroll
    for (int mt = 0; mt < 4; mt++) {
        const int mrow = m0 + mw + mt * 16 + g;
        #pragma unroll
        for (int nt = 0; nt < 4; nt++) {
            const int nl = nw + nt * 8 + tig * 2;
            const float bz0 = bias_sm[nl], bz1 = bias_sm[nl + 1];
            float2 v0 = make_float2(acc[mt][nt][0] + bz0, acc[mt][nt][1] + bz1);
            float2 v1 = make_float2(acc[mt][nt][2] + bz0, acc[mt][nt][3] + bz1);
            *(float2*)&g_xproj[(size_t)mrow * HH + n0 + nl] = v0;
            *(float2*)&g_xproj[(size_t)(mrow + 8) * HH + n0 + nl] = v1;
        }
    }
}

// ===========================================================================
// Kernel 2: RNN. Encoder = tensor-core (mma.sync bf16 hi/lo), decoder = R4 FMA.
// SMEM layout (bytes):
//   0      : encoder A = W1a^T hi [128m x 264k x 2B] (67584)   | decoder ws (131072)
//   67584  : encoder A lo (67584)                               | (ws/wy_lo)
//   131072 :                                                     | wy_lo (65536)
//   196608 : a4s float4[2][256] (8192)
//   204800 : y4s float4[256] (4096)
//   208896 : red (16512, decoder)  | encoder B state: 2 bufs x (hi 4096 + lo 4096)
//   225408 : mbars (32)
// ===========================================================================
#define A_STRIDE 528
#define ALO      67584
#define BOFF     208896
#define MBOFF    225408
#define RNN_SMEM 225440
#define RSTRIDE  1032

__device__ __forceinline__ void gemv16_s(const float* __restrict__ Wp,
                                         const float4* __restrict__ a, float acc[16])
{
    #pragma unroll
    for (int j = 0; j < 16; j++) acc[j] = 0.f;
    #pragma unroll 8
    for (int k = 0; k < 32; k++) {
        float4 w  = *(const float4*)(Wp + k * 128);
        float4 av = a[k];
        acc[0]  = fmaf(av.x, w.x, acc[0]);  acc[1]  = fmaf(av.x, w.y, acc[1]);
        acc[2]  = fmaf(av.x, w.z, acc[2]);  acc[3]  = fmaf(av.x, w.w, acc[3]);
        acc[4]  = fmaf(av.y, w.x, acc[4]);  acc[5]  = fmaf(av.y, w.y, acc[5]);
        acc[6]  = fmaf(av.y, w.z, acc[6]);  acc[7]  = fmaf(av.y, w.w, acc[7]);
        acc[8]  = fmaf(av.z, w.x, acc[8]);  acc[9]  = fmaf(av.z, w.y, acc[9]);
        acc[10] = fmaf(av.z, w.z, acc[10]); acc[11] = fmaf(av.z, w.w, acc[11]);
        acc[12] = fmaf(av.w, w.x, acc[12]); acc[13] = fmaf(av.w, w.y, acc[13]);
        acc[14] = fmaf(av.w, w.z, acc[14]); acc[15] = fmaf(av.w, w.w, acc[15]);
    }
}
__device__ __forceinline__ void gemv16_g(const float* __restrict__ Wp,
                                         const float4* __restrict__ a, float acc[16])
{
    #pragma unroll
    for (int j = 0; j < 16; j++) acc[j] = 0.f;
    #pragma unroll 16
    for (int k = 0; k < 32; k++) {
        float4 w  = *(const float4*)(Wp + (size_t)k * 256);
        float4 av = a[k];
        acc[0]  = fmaf(av.x, w.x, acc[0]);  acc[1]  = fmaf(av.x, w.y, acc[1]);
        acc[2]  = fmaf(av.x, w.z, acc[2]);  acc[3]  = fmaf(av.x, w.w, acc[3]);
        acc[4]  = fmaf(av.y, w.x, acc[4]);  acc[5]  = fmaf(av.y, w.y, acc[5]);
        acc[6]  = fmaf(av.y, w.z, acc[6]);  acc[7]  = fmaf(av.y, w.w, acc[7]);
        acc[8]  = fmaf(av.z, w.x, acc[8]);  acc[9]  = fmaf(av.z, w.y, acc[9]);
        acc[10] = fmaf(av.z, w.z, acc[10]); acc[11] = fmaf(av.z, w.w, acc[11]);
        acc[12] = fmaf(av.w, w.x, acc[12]); acc[13] = fmaf(av.w, w.y, acc[13]);
        acc[14] = fmaf(av.w, w.z, acc[14]); acc[15] = fmaf(av.w, w.w, acc[15]);
    }
}

__device__ __forceinline__ void fill_w(float* dst, const float* __restrict__ W,
                                       int c0, int t, int nk)
{
    const int lane = t & 31, w = t >> 5;
    for (int i = 0; i < nk / 8; i++) {
        int k = i * 8 + w;
        float4 v = *(const float4*)(W + (size_t)k * 256 + c0 + lane * 4);
        *(float4*)(dst + k * 128 + lane * 4) = v;
    }
}

__global__ __launch_bounds__(256, 1) __cluster_dims__(2, 1, 1)
void rnn_kernel(const float* __restrict__ W1a,
                const float* __restrict__ W2x, const float* __restrict__ b2x,
                const float* __restrict__ W2a, const float* __restrict__ b2a,
                const float* __restrict__ Wy,  const float* __restrict__ by,
                float* __restrict__ out)
{
    extern __shared__ __align__(16) unsigned char dsm[];
    float*  ws    = (float*)dsm;
    float*  wy_lo = (float*)(dsm + 131072);
    float4* a4s   = (float4*)(dsm + 196608);
    float4* y4s   = (float4*)(dsm + 204800);
    float*  red   = (float*)(dsm + 208896);
    unsigned long long* mbars = (unsigned long long*)(dsm + MBOFF);

    const int t    = threadIdx.x;
    const int lane = t & 31;
    const int wid  = t >> 5;        // 0..7
    uint32_t rank;
    asm("mov.u32 %0, %%cluster_ctarank;" : "=r"(rank));
    const uint32_t peer = rank ^ 1;
    const int b0 = (blockIdx.x >> 1) * 4;
    const int c0 = (int)rank * 128;
    const uint32_t smb = smem_u32(dsm);

    // encoder thread mapping
    const int mb   = wid * 16;
    const int g    = lane >> 2;
    const int tig  = lane & 3;
    const bool act = (tig < 2);
    const int colg = c0 + mb + g;               // global col of c0/c1
    const int nb   = 2 * tig;                   // batch offset
    const uint32_t aAddrBase = smb + (uint32_t)((mb + (lane & 15)) * A_STRIDE)
                             + (uint32_t)((lane >> 4) * 16);

    // decoder thread mapping (R4)
    const int kq = wid, cq = lane;
    const bool is_peer = ((uint32_t)(kq >> 2) != rank);
    const int o0    = 2 * t;
    const int row_o = (o0 >> 2) & 3;
    const int coll  = (o0 >> 4) * 4 + (o0 & 3);
    const int col   = c0 + coll;
    const int brow  = b0 + row_o;

    // mbarriers
    uint32_t mF[2], mRD[2], pF[2], pRD[2];
    mF[0]  = smem_u32(&mbars[0]); mF[1]  = smem_u32(&mbars[1]);
    mRD[0] = smem_u32(&mbars[2]); mRD[1] = smem_u32(&mbars[3]);
    pF[0]  = mapa_peer(mF[0], peer);  pF[1]  = mapa_peer(mF[1], peer);
    pRD[0] = mapa_peer(mRD[0], peer); pRD[1] = mapa_peer(mRD[1], peer);
    uint32_t pa4[2];
    pa4[0] = mapa_peer(smem_u32(&a4s[0]), peer);
    pa4[1] = mapa_peer(smem_u32(&a4s[256]), peer);
    uint32_t py4 = mapa_peer(smem_u32(&y4s[0]), peer);
    uint32_t pB[2];
    pB[0] = mapa_peer(smb + BOFF, peer);
    pB[1] = mapa_peer(smb + BOFF + 8192, peer);

    if (t == 0) {
        mbar_init(mF[0], 32);  mbar_init(mF[1], 32);
        mbar_init(mRD[0], 32); mbar_init(mRD[1], 32);
    }
    // zero encoder B state (both buffers incl. garbage batch rows 4-7)
    {
        float4 z = make_float4(0.f, 0.f, 0.f, 0.f);
        #pragma unroll
        for (int i = 0; i < 4; i++)
            *(float4*)(dsm + BOFF + (i * 256 + t) * 16) = z;
    }
    // stage A = W1a^T hi/lo  ([m=local col][k], stride 528B)
    {
        const int m = t & 127, hb = t >> 7;
        #pragma unroll 4
        for (int kk = 0; kk < 128; kk++) {
            int k = hb * 128 + kk;
            float v = W1a[(size_t)k * 256 + c0 + m];
            __nv_bfloat16 h = __float2bfloat16(v);
            __nv_bfloat16 l = __float2bfloat16(v - __bfloat162float(h));
            *(unsigned short*)(dsm + m * A_STRIDE + k * 2) = __bfloat16_as_ushort(h);
            *(unsigned short*)(dsm + ALO + m * A_STRIDE + k * 2) = __bfloat16_as_ushort(l);
        }
    }
    __syncthreads();
    cluster_sync_all();
    if (wid == 0) mbar_arrive_cluster(pF[0]);    // prime: initial zeros valid
    if (wid == 1) mbar_arrive_cluster(pRD[1]);   // prime: peer B[1] never read

    int fpar[2]  = {0, 0};
    int rdpar[2] = {0, 0};

    // ======================= encoder (tensor core) =======================
    for (int s = 0; s < SS; s++) {
        const int p = s & 1, q = p ^ 1;
        const uint32_t BpH  = smb + BOFF + (uint32_t)p * 8192;
        const uint32_t BqO  = (uint32_t)BOFF + (uint32_t)q * 8192;

        float xp00 = 0.f, xp01 = 0.f, xp10 = 0.f, xp11 = 0.f;
        if (act) {
            const float* xb = g_xproj + ((size_t)s * BB + (b0 + nb)) * HH;
            xp00 = __ldcs(xb + colg);
            xp01 = __ldcs(xb + HH + colg);
            xp10 = __ldcs(xb + colg + 8);
            xp11 = __ldcs(xb + HH + colg + 8);
        }

        float acc[6][4];
        #pragma unroll
        for (int i = 0; i < 6; i++)
            #pragma unroll
            for (int e = 0; e < 4; e++) acc[i][e] = 0.f;

        #pragma unroll
        for (int hv = 0; hv < 2; hv++) {
            const int kb = hv ? (c0 ^ 128) : c0;     // own half first, peer second
            if (hv) mbar_wait_par(mF[p], fpar[p]);
            #pragma unroll
            for (int j = 0; j < 8; j++) {
                const int k0 = kb + j * 16;
                uint32_t ah[4], al[4], bh0, bh1, bl0, bl1;
                uint32_t aa = aAddrBase + (uint32_t)k0 * 2;
                ldsm_x4(aa, ah);
                ldsm_x4(aa + ALO, al);
                uint32_t ba = BpH + (uint32_t)((k0 + (lane & 15)) * 16);
                ldsm_x2t(ba, bh0, bh1);
                ldsm_x2t(ba + 4096, bl0, bl1);
                const int sel = j & 1;
                mma_bf16(acc[sel],     ah, bh0, bh1);
                mma_bf16(acc[2 + sel], ah, bl0, bl1);
                mma_bf16(acc[4 + sel], al, bh0, bh1);
            }
        }
        fpar[p] ^= 1;
        __syncthreads();                               // sync1: B[p] reads done
        if (wid == 1) mbar_arrive_cluster(pRD[p]);

        if (act) {
            float s0 = acc[0][0]+acc[1][0]+acc[2][0]+acc[3][0]+acc[4][0]+acc[5][0];
            float s1 = acc[0][1]+acc[1][1]+acc[2][1]+acc[3][1]+acc[4][1]+acc[5][1];
            float s2 = acc[0][2]+acc[1][2]+acc[2][2]+acc[3][2]+acc[4][2]+acc[5][2];
            float s3 = acc[0][3]+acc[1][3]+acc[2][3]+acc[3][3]+acc[4][3]+acc[5][3];
            float t00 = tanhfast(s0 + xp00);
            float t01 = tanhfast(s1 + xp01);
            float t10 = tanhfast(s2 + xp10);
            float t11 = tanhfast(s3 + xp11);
            __nv_bfloat16 h00 = __float2bfloat16(t00), h01 = __float2bfloat16(t01);
            __nv_bfloat16 h10 = __float2bfloat16(t10), h11 = __float2bfloat16(t11);
            float l00 = t00 - __bfloat162float(h00), l01 = t01 - __bfloat162float(h01);
            float l10 = t10 - __bfloat162float(h10), l11 = t11 - __bfloat162float(h11);
            unsigned char* bq = dsm + BqO;
            *(uint32_t*)(bq + colg * 16 + tig * 4) =
                ((uint32_t)__bfloat16_as_ushort(h01) << 16) | __bfloat16_as_ushort(h00);
            *(uint32_t*)(bq + (colg + 8) * 16 + tig * 4) =
                ((uint32_t)__bfloat16_as_ushort(h11) << 16) | __bfloat16_as_ushort(h10);
            *(uint32_t*)(bq + 4096 + colg * 16 + tig * 4) = packbf2(l00, l01);
            *(uint32_t*)(bq + 4096 + (colg + 8) * 16 + tig * 4) = packbf2(l10, l11);
        }
        __syncthreads();                               // sync2: local half of B[q]

        if (wid == 0) {
            mbar_wait_par(mRD[q], rdpar[q]);
            const uint32_t pb = pB[q];
            #pragma unroll
            for (int it = 0; it < 4; it++) {
                uint32_t off = (uint32_t)(c0 * 16 + (it * 32 + lane) * 16);
                float4 vh = *(const float4*)(dsm + BqO + off);
                float4 vl = *(const float4*)(dsm + BqO + 4096 + off);
                st_cluster_f4(pb + off, vh);
                st_cluster_f4(pb + 4096 + off, vl);
            }
            mbar_arrive_cluster(pF[q]);
        }
        rdpar[q] ^= 1;
    }

    // final state in B[0]; wait for peer half, then reconstruct fp32 a_last
    mbar_wait_par(mF[0], fpar[0]); fpar[0] ^= 1;
    {
        uint32_t w0h = *(const uint32_t*)(dsm + BOFF + t * 16);
        uint32_t w1h = *(const uint32_t*)(dsm + BOFF + t * 16 + 4);
        uint32_t w0l = *(const uint32_t*)(dsm + BOFF + 4096 + t * 16);
        uint32_t w1l = *(const uint32_t*)(dsm + BOFF + 4096 + t * 16 + 4);
        a4s[t] = make_float4(bfu(w0h) + bfu(w0l), bfu(w0h >> 16) + bfu(w0l >> 16),
                             bfu(w1h) + bfu(w1l), bfu(w1h >> 16) + bfu(w1l >> 16));
    }
    __syncthreads();

    // ======================= glue (R4) =======================
    float byv0, byv1, bb0, bb1, base00, base01;
    {
        float2 byv = *(const float2*)&by[col];
        byv0 = byv.x; byv1 = byv.y;
        float2 b2xv = *(const float2*)&b2x[col];
        float2 b2av = *(const float2*)&b2a[col];
        bb0 = b2xv.x + b2av.x; bb1 = b2xv.y + b2av.y;

        float acc[16];
        gemv16_g(Wy + (size_t)(kq * 32) * 256 + c0 + cq * 4, &a4s[kq * 32], acc);
        #pragma unroll
        for (int r = 0; r < 4; r++)
            *(float4*)&red[r * RSTRIDE + kq * 128 + cq * 4] =
                make_float4(acc[r * 4], acc[r * 4 + 1], acc[r * 4 + 2], acc[r * 4 + 3]);
        __syncthreads();
        float v0 = 0.f, v1 = 0.f;
        #pragma unroll
        for (int gg = 0; gg < 8; gg++) {
            float2 rv = *(const float2*)&red[row_o * RSTRIDE + gg * 128 + coll];
            v0 += rv.x; v1 += rv.y;
        }
        ((float*)&y4s[col])[row_o]     = sigf(v0 + byv0);
        ((float*)&y4s[col + 1])[row_o] = sigf(v1 + byv1);
        __syncthreads();
        if (kq == 0) {
            #pragma unroll
            for (int j = 0; j < 4; j++) {
                int idx = c0 + cq + 32 * j;
                st_cluster_f4(py4 + (uint32_t)idx * 16u, y4s[idx]);
            }
        }
        cluster_sync_all();

        gemv16_g(W2x + (size_t)(kq * 32) * 256 + c0 + cq * 4, y4s + kq * 32, acc);
        #pragma unroll
        for (int r = 0; r < 4; r++)
            *(float4*)&red[r * RSTRIDE + kq * 128 + cq * 4] =
                make_float4(acc[r * 4], acc[r * 4 + 1], acc[r * 4 + 2], acc[r * 4 + 3]);
        __syncthreads();
        v0 = 0.f; v1 = 0.f;
        #pragma unroll
        for (int gg = 0; gg < 8; gg++) {
            float2 rv = *(const float2*)&red[row_o * RSTRIDE + gg * 128 + coll];
            v0 += rv.x; v1 += rv.y;
        }
        base00 = v0 + bb0; base01 = v1 + bb1;
        __syncthreads();
    }

    // restage weights for decoder
    fill_w(ws, W2a, c0, t, 256);
    fill_w(wy_lo, Wy, c0, t, 128);
    __syncthreads();

    const float* wsp   = ws + kq * 32 * 128 + cq * 4;
    const float* wylop = wy_lo + kq * 32 * 128 + cq * 4;

    // ======================= decoder (R4) =======================
    for (int i = 0; i < LL; i++) {
        const int p = i & 1, q = p ^ 1;
        float acc[16];

        gemv16_s(wsp, &a4s[p * 256 + kq * 32], acc);
        #pragma unroll
        for (int r = 0; r < 4; r++)
            *(float4*)&red[r * RSTRIDE + kq * 128 + cq * 4] =
                make_float4(acc[r * 4], acc[r * 4 + 1], acc[r * 4 + 2], acc[r * 4 + 3]);
        __syncthreads();
        if (kq == 1) mbar_arrive_cluster(pRD[p]);

        float v0 = 0.f, v1 = 0.f;
        #pragma unroll
        for (int gg = 0; gg < 8; gg++) {
            float2 rv = *(const float2*)&red[row_o * RSTRIDE + gg * 128 + coll];
            v0 += rv.x; v1 += rv.y;
        }
        float bs0 = (i == 0) ? base00 : bb0;
        float bs1 = (i == 0) ? base01 : bb1;
        ((float*)&a4s[q * 256 + col])[row_o]     = tanhfast(v0 + bs0);
        ((float*)&a4s[q * 256 + col + 1])[row_o] = tanhfast(v1 + bs1);
        __syncthreads();

        if (kq == 0) mbar_wait_par(mRD[q], rdpar[q]);
        rdpar[q] ^= 1;
        if (kq == 0) {
            #pragma unroll
            for (int j = 0; j < 4; j++) {
                int idx = c0 + cq + 32 * j;
                st_cluster_f4(pa4[q] + (uint32_t)idx * 16u, a4s[q * 256 + idx]);
            }
            mbar_arrive_cluster(pF[q]);
        }

        if (is_peer) mbar_wait_par(mF[q], fpar[q]);
        fpar[q] ^= 1;

        if (kq < 4) gemv16_s(wylop, &a4s[q * 256 + kq * 32], acc);
        else        gemv16_g(Wy + (size_t)(kq * 32) * 256 + c0 + cq * 4,
                             &a4s[q * 256 + kq * 32], acc);
        #pragma unroll
        for (int r = 0; r < 4; r++)
            *(float4*)&red[r * RSTRIDE + kq * 128 + cq * 4] =
                make_float4(acc[r * 4], acc[r * 4 + 1], acc[r * 4 + 2], acc[r * 4 + 3]);
        __syncthreads();
        v0 = 0.f; v1 = 0.f;
        #pragma unroll
        for (int gg = 0; gg < 8; gg++) {
            float2 rv = *(const float2*)&red[row_o * RSTRIDE + gg * 128 + coll];
            v0 += rv.x; v1 += rv.y;
        }
        float2 yo = make_float2(sigf(v0 + byv0), sigf(v1 + byv1));
        *(float2*)&out[((size_t)brow * LL + i) * OO + col] = yo;
        __syncthreads();
    }

    cluster_sync_all();
}

// ---------------------------------------------------------------------------
extern "C" void kernel_launch(void* const* d_in, const int* in_sizes, int n_in,
                              void* d_out, int out_size)
{
    const float* x   = (const float*)d_in[0];
    const float* W1x = (const float*)d_in[1];
    const float* b1x = (const float*)d_in[2];
    const float* W1a = (const float*)d_in[3];
    const float* b1a = (const float*)d_in[4];
    const float* W2x = (const float*)d_in[5];
    const float* b2x = (const float*)d_in[6];
    const float* W2a = (const float*)d_in[7];
    const float* b2a = (const float*)d_in[8];
    const float* Wy  = (const float*)d_in[9];
    const float* by  = (const float*)d_in[10];
    float* out = (float*)d_out;

    (void)in_sizes; (void)n_in; (void)out_size;

    cudaFuncSetAttribute(xproj_mma_kernel,
                         cudaFuncAttributeMaxDynamicSharedMemorySize, XP_SMEM);
    cudaFuncSetAttribute(rnn_kernel,
                         cudaFuncAttributeMaxDynamicSharedMemorySize, RNN_SMEM);

    wconv_kernel<<<256, 256>>>(W1x);
    dim3 xgrid((BB * SS) / 128, HH / 128);
    xproj_mma_kernel<<<xgrid, 256, XP_SMEM>>>(x, b1x, b1a);
    rnn_kernel<<<BB / 2, 256, RNN_SMEM>>>(W1a, W2x, b2x, W2a, b2a, Wy, by, out);
}

// round 12
// speedup vs baseline: 1.6667x; 1.2376x over previous
#include <cuda_runtime.h>
#include <cuda_bf16.h>
#include <math.h>
#include <stdint.h>

#define BB 256
#define SS 512
#define II 256
#define HH 256
#define OO 256
#define LL 64

__device__ float g_xproj[(size_t)SS * BB * HH];
__device__ __nv_bfloat16 g_wh[256 * 256];
__device__ __nv_bfloat16 g_wl[256 * 256];

__device__ __forceinline__ float sigf(float x) {
    return __fdividef(1.f, 1.f + __expf(-x));
}
__device__ __forceinline__ float tanhfast(float x) {
    float e = __expf(2.f * x);
    return 1.f - __fdividef(2.f, e + 1.f);
}

__device__ __forceinline__ uint32_t smem_u32(const void* p) {
    uint32_t r;
    asm("{ .reg .u64 t; cvta.to.shared.u64 t, %1; cvt.u32.u64 %0, t; }" : "=r"(r) : "l"(p));
    return r;
}
__device__ __forceinline__ uint32_t mapa_peer(uint32_t a, uint32_t peer) {
    uint32_t r;
    asm("mapa.shared::cluster.u32 %0, %1, %2;" : "=r"(r) : "r"(a), "r"(peer));
    return r;
}
__device__ __forceinline__ void mbar_init(uint32_t a, uint32_t c) {
    asm volatile("mbarrier.init.shared.b64 [%0], %1;" :: "r"(a), "r"(c) : "memory");
}
__device__ __forceinline__ void mbar_arrive_local(uint32_t a) {
    asm volatile("mbarrier.arrive.release.cta.shared::cta.b64 _, [%0];"
                 :: "r"(a) : "memory");
}
__device__ __forceinline__ void mbar_arrive_cluster(uint32_t a) {
    asm volatile("mbarrier.arrive.release.cluster.shared::cluster.b64 _, [%0];"
                 :: "r"(a) : "memory");
}
__device__ __forceinline__ void mbar_wait_par(uint32_t a, uint32_t par) {
    asm volatile(
        "{\n\t.reg .pred P;\n\t"
        "WL%=:\n\t"
        "mbarrier.try_wait.parity.acquire.cluster.shared::cta.b64 P, [%0], %1, 0x989680;\n\t"
        "@P bra WD%=;\n\t"
        "bra WL%=;\n\t"
        "WD%=:\n\t}"
        :: "r"(a), "r"(par) : "memory");
}
__device__ __forceinline__ void st_cluster_f4(uint32_t a, float4 v) {
    asm volatile("st.shared::cluster.v4.b32 [%0], {%1,%2,%3,%4};" :: "r"(a),
                 "r"(__float_as_uint(v.x)), "r"(__float_as_uint(v.y)),
                 "r"(__float_as_uint(v.z)), "r"(__float_as_uint(v.w)) : "memory");
}
__device__ __forceinline__ void st_cluster_u32(uint32_t a, uint32_t v) {
    asm volatile("st.shared::cluster.b32 [%0], %1;" :: "r"(a), "r"(v) : "memory");
}
__device__ __forceinline__ void cluster_sync_all() {
    asm volatile("barrier.cluster.arrive.aligned;" ::: "memory");
    asm volatile("barrier.cluster.wait.aligned;" ::: "memory");
}
__device__ __forceinline__ void ldsm_x4(uint32_t addr, uint32_t r[4]) {
    asm volatile("ldmatrix.sync.aligned.m8n8.x4.shared.b16 {%0,%1,%2,%3}, [%4];"
                 : "=r"(r[0]), "=r"(r[1]), "=r"(r[2]), "=r"(r[3]) : "r"(addr));
}
__device__ __forceinline__ void ldsm_x2t(uint32_t addr, uint32_t& r0, uint32_t& r1) {
    asm volatile("ldmatrix.sync.aligned.m8n8.x2.trans.shared.b16 {%0,%1}, [%2];"
                 : "=r"(r0), "=r"(r1) : "r"(addr));
}
__device__ __forceinline__ void mma_bf16(float c[4], const uint32_t a[4],
                                         uint32_t b0, uint32_t b1) {
    asm volatile(
        "mma.sync.aligned.m16n8k16.row.col.f32.bf16.bf16.f32 "
        "{%0,%1,%2,%3}, {%4,%5,%6,%7}, {%8,%9}, {%0,%1,%2,%3};"
        : "+f"(c[0]), "+f"(c[1]), "+f"(c[2]), "+f"(c[3])
        : "r"(a[0]), "r"(a[1]), "r"(a[2]), "r"(a[3]), "r"(b0), "r"(b1));
}
__device__ __forceinline__ uint32_t packbf2(float a, float b) {
    __nv_bfloat16 ha = __float2bfloat16(a), hb = __float2bfloat16(b);
    return ((uint32_t)__bfloat16_as_ushort(hb) << 16) | __bfloat16_as_ushort(ha);
}
__device__ __forceinline__ float bfu(uint32_t u) {
    return __bfloat162float(__ushort_as_bfloat16((unsigned short)(u & 0xffffu)));
}

// ===========================================================================
// Kernel 0: W1x -> bf16 hi/lo, transposed to [n][k]
// ===========================================================================
__global__ void wconv_kernel(const float* __restrict__ W1x)
{
    int k = blockIdx.x, n = threadIdx.x;
    float v = W1x[k * 256 + n];
    __nv_bfloat16 h = __float2bfloat16(v);
    __nv_bfloat16 l = __float2bfloat16(v - __bfloat162float(h));
    g_wh[n * 256 + k] = h;
    g_wl[n * 256 + k] = l;
}

// ===========================================================================
// Kernel 1: xproj via mma.sync bf16 hi/lo (R8 verbatim — proven).
// ===========================================================================
#define SB_BH    0
#define SB_BL    65536
#define SB_A     131072
#define SB_BIAS  196608
#define XP_SMEM  197120

__device__ __forceinline__ void afragx(uint32_t Ab, int mbase, int j, int lane,
                                       uint32_t r[4]) {
    int row = mbase + (lane & 15);
    int q   = j * 2 + (lane >> 4);
    uint32_t addr = Ab + (uint32_t)(row * 128 + ((q ^ row) & 7) * 16);
    ldsm_x4(addr, r);
}
__device__ __forceinline__ void bfragx(uint32_t Bb, int nbase, int ks, int lane,
                                       uint32_t r[4]) {
    int row = nbase + (lane & 7) + ((lane >> 4) << 3);
    int q   = ks * 2 + ((lane >> 3) & 1);
    uint32_t qp = (uint32_t)((q & ~7) | ((q ^ row) & 7));
    uint32_t addr = Bb + (uint32_t)(row * 512) + qp * 16;
    ldsm_x4(addr, r);
}

__device__ __forceinline__ void load_a_chunk(unsigned char* sm, int p,
                                             const float* __restrict__ x,
                                             int b0, int s, int c, int t)
{
    const int r = t >> 1, hf = t & 1, rx = r & 7;
    unsigned char* ah = sm + SB_A + p * 32768;
    unsigned char* al = ah + 16384;
    const float* xr = x + ((size_t)(b0 + r) * SS + s) * II + c * 64 + hf * 32;
    #pragma unroll
    for (int jj = 0; jj < 4; jj++) {
        float4 v0 = *(const float4*)(xr + jj * 8);
        float4 v1 = *(const float4*)(xr + jj * 8 + 4);
        uint4 h, l;
        h.x = packbf2(v0.x, v0.y); h.y = packbf2(v0.z, v0.w);
        h.z = packbf2(v1.x, v1.y); h.w = packbf2(v1.z, v1.w);
        l.x = packbf2(v0.x - bfu(h.x), v0.y - bfu(h.x >> 16));
        l.y = packbf2(v0.z - bfu(h.y), v0.w - bfu(h.y >> 16));
        l.z = packbf2(v1.x - bfu(h.z), v1.y - bfu(h.z >> 16));
        l.w = packbf2(v1.z - bfu(h.w), v1.w - bfu(h.w >> 16));
        int q = hf * 4 + jj;
        uint32_t off = (uint32_t)(r * 128 + (q ^ rx) * 16);
        *(uint4*)(ah + off) = h;
        *(uint4*)(al + off) = l;
    }
}

__global__ __launch_bounds__(256, 1) void xproj_mma_kernel(
    const float* __restrict__ x,
    const float* __restrict__ b1x, const float* __restrict__ b1a)
{
    extern __shared__ __align__(1024) unsigned char sm[];
    const int t = threadIdx.x;
    const int wid = t >> 5, lane = t & 31;
    const uint32_t smb = smem_u32(sm);

    const int m0 = blockIdx.x * 128;
    const int n0 = blockIdx.y * 128;
    const int s  = m0 >> 8;
    const int b0 = m0 & 255;
    const int mw = (wid & 1) * 64;
    const int nw = (wid >> 1) * 32;

    #pragma unroll 4
    for (int i = 0; i < 16; i++) {
        int idx = i * 256 + t;
        int rr = idx >> 5, q = idx & 31;
        uint32_t qp = (uint32_t)((q & ~7) | ((q ^ rr) & 7));
        size_t src = (size_t)(n0 + rr) * 256 + q * 8;
        *(uint4*)(sm + SB_BH + rr * 512 + qp * 16) = *(const uint4*)(g_wh + src);
        *(uint4*)(sm + SB_BL + rr * 512 + qp * 16) = *(const uint4*)(g_wl + src);
    }
    if (t < 128)
        ((float*)(sm + SB_BIAS))[t] = b1x[n0 + t] + b1a[n0 + t];

    load_a_chunk(sm, 0, x, b0, s, 0, t);
    __syncthreads();

    float acc[4][4][4];
    #pragma unroll
    for (int mt = 0; mt < 4; mt++)
        #pragma unroll
        for (int nt = 0; nt < 4; nt++)
            #pragma unroll
            for (int e = 0; e < 4; e++) acc[mt][nt][e] = 0.f;

    const uint32_t Bh = smb + SB_BH, Bl = smb + SB_BL;

    #pragma unroll 1
    for (int c = 0; c < 4; c++) {
        const int p = c & 1;
        if (c < 3) load_a_chunk(sm, 1 - p, x, b0, s, c + 1, t);
        const uint32_t Abh = smb + SB_A + p * 32768;
        const uint32_t Abl = Abh + 16384;

        #pragma unroll
        for (int j = 0; j < 4; j++) {
            const int ks = c * 4 + j;
            uint32_t bh[8], bl[8];
            bfragx(Bh, nw,      ks, lane, bh);
            bfragx(Bh, nw + 16, ks, lane, bh + 4);
            bfragx(Bl, nw,      ks, lane, bl);
            bfragx(Bl, nw + 16, ks, lane, bl + 4);
            #pragma unroll
            for (int mt = 0; mt < 4; mt++) {
                uint32_t ah[4], al[4];
                afragx(Abh, mw + mt * 16, j, lane, ah);
                afragx(Abl, mw + mt * 16, j, lane, al);
                #pragma unroll
                for (int nt = 0; nt < 4; nt++) {
                    mma_bf16(acc[mt][nt], ah, bh[nt * 2], bh[nt * 2 + 1]);
                    mma_bf16(acc[mt][nt], ah, bl[nt * 2], bl[nt * 2 + 1]);
                    mma_bf16(acc[mt][nt], al, bh[nt * 2], bh[nt * 2 + 1]);
                }
            }
        }
        __syncthreads();
    }

    const int g = lane >> 2, tig = lane & 3;
    const float* bias_sm = (const float*)(sm + SB_BIAS);
    #pragma unroll
    for (int mt = 0; mt < 4; mt++) {
        const int mrow = m0 + mw + mt * 16 + g;
        #pragma unroll
        for (int nt = 0; nt < 4; nt++) {
            const int nl = nw + nt * 8 + tig * 2;
            const float bz0 = bias_sm[nl], bz1 = bias_sm[nl + 1];
            float2 v0 = make_float2(acc[mt][nt][0] + bz0, acc[mt][nt][1] + bz1);
            float2 v1 = make_float2(acc[mt][nt][2] + bz0, acc[mt][nt][3] + bz1);
            *(float2*)&g_xproj[(size_t)mrow * HH + n0 + nl] = v0;
            *(float2*)&g_xproj[(size_t)(mrow + 8) * HH + n0 + nl] = v1;
        }
    }
}

// ===========================================================================
// Kernel 2: RNN. Encoder: tensor-core, 4-deep state ring, fused per-thread
// DSMEM push, 1 wait + 1 BAR per step. Decoder/glue: R4 (fresh barriers).
// SMEM (bytes):
//   0..135168       enc A = W1a^T hi/lo (stride 528)   | dec ws [0..131072)
//   135168..167936  state ring: 4 x (hi 4096 + lo 4096)| dec wy_lo [131072..196608)
//   196608 a4s[2][256]f4 | 204800 y4s[256]f4 | 208896 red | 225408 mbars[8]
// ===========================================================================
#define A_STRIDE 528
#define ALO      67584
#define RING(i)  (135168 + (i) * 8192)
#define A4OFF    196608
#define Y4OFF    204800
#define REDOFF   208896
#define MBOFF    225408
#define RNN_SMEM 225472
#define RSTRIDE  1032

__device__ __forceinline__ void gemv16_s(const float* __restrict__ Wp,
                                         const float4* __restrict__ a, float acc[16])
{
    #pragma unroll
    for (int j = 0; j < 16; j++) acc[j] = 0.f;
    #pragma unroll 8
    for (int k = 0; k < 32; k++) {
        float4 w  = *(const float4*)(Wp + k * 128);
        float4 av = a[k];
        acc[0]  = fmaf(av.x, w.x, acc[0]);  acc[1]  = fmaf(av.x, w.y, acc[1]);
        acc[2]  = fmaf(av.x, w.z, acc[2]);  acc[3]  = fmaf(av.x, w.w, acc[3]);
        acc[4]  = fmaf(av.y, w.x, acc[4]);  acc[5]  = fmaf(av.y, w.y, acc[5]);
        acc[6]  = fmaf(av.y, w.z, acc[6]);  acc[7]  = fmaf(av.y, w.w, acc[7]);
        acc[8]  = fmaf(av.z, w.x, acc[8]);  acc[9]  = fmaf(av.z, w.y, acc[9]);
        acc[10] = fmaf(av.z, w.z, acc[10]); acc[11] = fmaf(av.z, w.w, acc[11]);
        acc[12] = fmaf(av.w, w.x, acc[12]); acc[13] = fmaf(av.w, w.y, acc[13]);
        acc[14] = fmaf(av.w, w.z, acc[14]); acc[15] = fmaf(av.w, w.w, acc[15]);
    }
}
__device__ __forceinline__ void gemv16_g(const float* __restrict__ Wp,
                                         const float4* __restrict__ a, float acc[16])
{
    #pragma unroll
    for (int j = 0; j < 16; j++) acc[j] = 0.f;
    #pragma unroll 16
    for (int k = 0; k < 32; k++) {
        float4 w  = *(const float4*)(Wp + (size_t)k * 256);
        float4 av = a[k];
        acc[0]  = fmaf(av.x, w.x, acc[0]);  acc[1]  = fmaf(av.x, w.y, acc[1]);
        acc[2]  = fmaf(av.x, w.z, acc[2]);  acc[3]  = fmaf(av.x, w.w, acc[3]);
        acc[4]  = fmaf(av.y, w.x, acc[4]);  acc[5]  = fmaf(av.y, w.y, acc[5]);
        acc[6]  = fmaf(av.y, w.z, acc[6]);  acc[7]  = fmaf(av.y, w.w, acc[7]);
        acc[8]  = fmaf(av.z, w.x, acc[8]);  acc[9]  = fmaf(av.z, w.y, acc[9]);
        acc[10] = fmaf(av.z, w.z, acc[10]); acc[11] = fmaf(av.z, w.w, acc[11]);
        acc[12] = fmaf(av.w, w.x, acc[12]); acc[13] = fmaf(av.w, w.y, acc[13]);
        acc[14] = fmaf(av.w, w.z, acc[14]); acc[15] = fmaf(av.w, w.w, acc[15]);
    }
}
__device__ __forceinline__ void fill_w(float* dst, const float* __restrict__ W,
                                       int c0, int t, int nk)
{
    const int lane = t & 31, w = t >> 5;
    for (int i = 0; i < nk / 8; i++) {
        int k = i * 8 + w;
        float4 v = *(const float4*)(W + (size_t)k * 256 + c0 + lane * 4);
        *(float4*)(dst + k * 128 + lane * 4) = v;
    }
}

__global__ __launch_bounds__(256, 1) __cluster_dims__(2, 1, 1)
void rnn_kernel(const float* __restrict__ W1a,
                const float* __restrict__ W2x, const float* __restrict__ b2x,
                const float* __restrict__ W2a, const float* __restrict__ b2a,
                const float* __restrict__ Wy,  const float* __restrict__ by,
                float* __restrict__ out)
{
    extern __shared__ __align__(16) unsigned char dsm[];
    float*  ws    = (float*)dsm;
    float*  wy_lo = (float*)(dsm + 131072);
    float4* a4s   = (float4*)(dsm + A4OFF);
    float4* y4s   = (float4*)(dsm + Y4OFF);
    float*  red   = (float*)(dsm + REDOFF);
    unsigned long long* mbars = (unsigned long long*)(dsm + MBOFF);

    const int t    = threadIdx.x;
    const int lane = t & 31;
    const int wid  = t >> 5;
    uint32_t rank;
    asm("mov.u32 %0, %%cluster_ctarank;" : "=r"(rank));
    const uint32_t peer = rank ^ 1;
    const int b0 = (blockIdx.x >> 1) * 4;
    const int c0 = (int)rank * 128;
    const uint32_t smb = smem_u32(dsm);

    // encoder mapping
    const int mb   = wid * 16;
    const int g    = lane >> 2;
    const int tig  = lane & 3;
    const bool act = (tig < 2);
    const int colg = c0 + mb + g;
    const int nb   = 2 * tig;
    const uint32_t aAddrBase = smb + (uint32_t)((mb + (lane & 15)) * A_STRIDE)
                             + (uint32_t)((lane >> 4) * 16);

    // decoder mapping (R4)
    const int kq = wid, cq = lane;
    const bool is_peer = ((uint32_t)(kq >> 2) != rank);
    const int o0    = 2 * t;
    const int row_o = (o0 >> 2) & 3;
    const int coll  = (o0 >> 4) * 4 + (o0 & 3);
    const int col   = c0 + coll;
    const int brow  = b0 + row_o;

    // barriers: [0..3] encF (count 128), [4,5] decF (32), [6,7] decRD (32)
    uint32_t eF[4], peF[4], pRG[4];
    #pragma unroll
    for (int i = 0; i < 4; i++) {
        eF[i]  = smem_u32(&mbars[i]);
        peF[i] = mapa_peer(eF[i], peer);
        pRG[i] = mapa_peer(smb + (uint32_t)RING(i), peer);
    }
    uint32_t dF[2], dRD[2], pdF[2], pdRD[2];
    dF[0]  = smem_u32(&mbars[4]); dF[1]  = smem_u32(&mbars[5]);
    dRD[0] = smem_u32(&mbars[6]); dRD[1] = smem_u32(&mbars[7]);
    pdF[0]  = mapa_peer(dF[0], peer);  pdF[1]  = mapa_peer(dF[1], peer);
    pdRD[0] = mapa_peer(dRD[0], peer); pdRD[1] = mapa_peer(dRD[1], peer);
    uint32_t pa4[2];
    pa4[0] = mapa_peer(smb + A4OFF, peer);
    pa4[1] = mapa_peer(smb + A4OFF + 4096, peer);
    uint32_t py4 = mapa_peer(smb + Y4OFF, peer);

    if (t == 0) {
        mbar_init(eF[0], 128); mbar_init(eF[1], 128);
        mbar_init(eF[2], 128); mbar_init(eF[3], 128);
        mbar_init(dF[0], 32);  mbar_init(dF[1], 32);
        mbar_init(dRD[0], 32); mbar_init(dRD[1], 32);
    }
    // zero ring slot 3 (initial state)
    {
        uint4 z = make_uint4(0, 0, 0, 0);
        *(uint4*)(dsm + RING(3) + t * 16) = z;
        *(uint4*)(dsm + RING(3) + (t + 256) * 16) = z;
    }
    // stage A = W1a^T hi/lo
    {
        const int m = t & 127, hb = t >> 7;
        #pragma unroll 4
        for (int kk = 0; kk < 128; kk++) {
            int k = hb * 128 + kk;
            float v = W1a[(size_t)k * 256 + c0 + m];
            __nv_bfloat16 h = __float2bfloat16(v);
            __nv_bfloat16 l = __float2bfloat16(v - __bfloat162float(h));
            *(unsigned short*)(dsm + m * A_STRIDE + k * 2) = __bfloat16_as_ushort(h);
            *(unsigned short*)(dsm + ALO + m * A_STRIDE + k * 2) = __bfloat16_as_ushort(l);
        }
    }
    __syncthreads();
    cluster_sync_all();
    if (act) mbar_arrive_local(eF[3]);           // prime slot 3 (128 arrives)
    if (wid == 5) mbar_arrive_cluster(pdRD[1]);  // decoder prime

    // xp prefetch for s=0
    float xc00 = 0.f, xc01 = 0.f, xc10 = 0.f, xc11 = 0.f;
    if (act) {
        const float* xb = g_xproj + (size_t)(b0 + nb) * HH;
        xc00 = __ldcs(xb + colg);
        xc01 = __ldcs(xb + (size_t)HH + colg);
        xc10 = __ldcs(xb + colg + 8);
        xc11 = __ldcs(xb + (size_t)HH + colg + 8);
    }

    int fp0 = 0, fp1 = 0, fp2 = 0, fp3 = 0;

    // ======================= encoder =======================
    auto enc_step = [&](int s, uint32_t eFr, int& fpr, uint32_t bsr, uint32_t bsw,
                        uint32_t pbsw, uint32_t pefw) {
        // prefetch next step's xproj
        float xn00 = 0.f, xn01 = 0.f, xn10 = 0.f, xn11 = 0.f;
        if (act && s + 1 < SS) {
            const float* xb = g_xproj + ((size_t)(s + 1) * BB + (b0 + nb)) * HH;
            xn00 = __ldcs(xb + colg);
            xn01 = __ldcs(xb + (size_t)HH + colg);
            xn10 = __ldcs(xb + colg + 8);
            xn11 = __ldcs(xb + (size_t)HH + colg + 8);
        }

        float acc[6][4];
        #pragma unroll
        for (int i = 0; i < 6; i++)
            #pragma unroll
            for (int e = 0; e < 4; e++) acc[i][e] = 0.f;

        const uint32_t Bsr = smb + bsr;
        // own half first (covered by step BAR)
        #pragma unroll
        for (int j = 0; j < 8; j++) {
            const int k0 = c0 + j * 16;
            uint32_t ah[4], al[4], bh0, bh1, bl0, bl1;
            uint32_t aa = aAddrBase + (uint32_t)k0 * 2;
            ldsm_x4(aa, ah);
            ldsm_x4(aa + ALO, al);
            uint32_t ba = Bsr + (uint32_t)((k0 + (lane & 15)) * 16);
            ldsm_x2t(ba, bh0, bh1);
            ldsm_x2t(ba + 4096, bl0, bl1);
            const int sel = j & 1;
            mma_bf16(acc[sel],     ah, bh0, bh1);
            mma_bf16(acc[2 + sel], ah, bl0, bl1);
            mma_bf16(acc[4 + sel], al, bh0, bh1);
        }
        // peer half after single pre-armed wait
        mbar_wait_par(eFr, fpr); fpr ^= 1;
        #pragma unroll
        for (int j = 0; j < 8; j++) {
            const int k0 = (c0 ^ 128) + j * 16;
            uint32_t ah[4], al[4], bh0, bh1, bl0, bl1;
            uint32_t aa = aAddrBase + (uint32_t)k0 * 2;
            ldsm_x4(aa, ah);
            ldsm_x4(aa + ALO, al);
            uint32_t ba = Bsr + (uint32_t)((k0 + (lane & 15)) * 16);
            ldsm_x2t(ba, bh0, bh1);
            ldsm_x2t(ba + 4096, bl0, bl1);
            const int sel = j & 1;
            mma_bf16(acc[sel],     ah, bh0, bh1);
            mma_bf16(acc[2 + sel], ah, bl0, bl1);
            mma_bf16(acc[4 + sel], al, bh0, bh1);
        }

        if (act) {
            float s0 = acc[0][0]+acc[1][0]+acc[2][0]+acc[3][0]+acc[4][0]+acc[5][0];
            float s1 = acc[0][1]+acc[1][1]+acc[2][1]+acc[3][1]+acc[4][1]+acc[5][1];
            float s2 = acc[0][2]+acc[1][2]+acc[2][2]+acc[3][2]+acc[4][2]+acc[5][2];
            float s3 = acc[0][3]+acc[1][3]+acc[2][3]+acc[3][3]+acc[4][3]+acc[5][3];
            float t00 = tanhfast(s0 + xc00);
            float t01 = tanhfast(s1 + xc01);
            float t10 = tanhfast(s2 + xc10);
            float t11 = tanhfast(s3 + xc11);
            uint32_t hA = packbf2(t00, t01);
            uint32_t hB = packbf2(t10, t11);
            uint32_t lA = packbf2(t00 - bfu(hA), t01 - bfu(hA >> 16));
            uint32_t lB = packbf2(t10 - bfu(hB), t11 - bfu(hB >> 16));
            const uint32_t o1 = (uint32_t)(colg * 16 + tig * 4);
            const uint32_t o2 = (uint32_t)((colg + 8) * 16 + tig * 4);
            *(uint32_t*)(dsm + bsw + o1) = hA;
            *(uint32_t*)(dsm + bsw + o2) = hB;
            *(uint32_t*)(dsm + bsw + 4096 + o1) = lA;
            *(uint32_t*)(dsm + bsw + 4096 + o2) = lB;
            st_cluster_u32(pbsw + o1, hA);
            st_cluster_u32(pbsw + o2, hB);
            st_cluster_u32(pbsw + 4096 + o1, lA);
            st_cluster_u32(pbsw + 4096 + o2, lB);
            mbar_arrive_cluster(pefw);     // per-producer release (128 total)
        }
        __syncthreads();                   // local half of new slot visible
        xc00 = xn00; xc01 = xn01; xc10 = xn10; xc11 = xn11;
    };

    #pragma unroll 1
    for (int sb = 0; sb < SS; sb += 4) {
        enc_step(sb + 0, eF[3], fp3, RING(3), RING(0), pRG[0], peF[0]);
        enc_step(sb + 1, eF[0], fp0, RING(0), RING(1), pRG[1], peF[1]);
        enc_step(sb + 2, eF[1], fp1, RING(1), RING(2), pRG[2], peF[2]);
        enc_step(sb + 3, eF[2], fp2, RING(2), RING(3), pRG[3], peF[3]);
    }

    // a_last in slot 3; wait peer half, reconstruct fp32
    mbar_wait_par(eF[3], fp3);
    {
        uint32_t w0h = *(const uint32_t*)(dsm + RING(3) + t * 16);
        uint32_t w1h = *(const uint32_t*)(dsm + RING(3) + t * 16 + 4);
        uint32_t w0l = *(const uint32_t*)(dsm + RING(3) + 4096 + t * 16);
        uint32_t w1l = *(const uint32_t*)(dsm + RING(3) + 4096 + t * 16 + 4);
        a4s[t] = make_float4(bfu(w0h) + bfu(w0l), bfu(w0h >> 16) + bfu(w0l >> 16),
                             bfu(w1h) + bfu(w1l), bfu(w1h >> 16) + bfu(w1l >> 16));
    }
    __syncthreads();

    int dfp[2]  = {0, 0};
    int drdp[2] = {0, 0};

    // ======================= glue (R4) =======================
    float byv0, byv1, bb0, bb1, base00, base01;
    {
        float2 byv = *(const float2*)&by[col];
        byv0 = byv.x; byv1 = byv.y;
        float2 b2xv = *(const float2*)&b2x[col];
        float2 b2av = *(const float2*)&b2a[col];
        bb0 = b2xv.x + b2av.x; bb1 = b2xv.y + b2av.y;

        float acc[16];
        gemv16_g(Wy + (size_t)(kq * 32) * 256 + c0 + cq * 4, &a4s[kq * 32], acc);
        #pragma unroll
        for (int r = 0; r < 4; r++)
            *(float4*)&red[r * RSTRIDE + kq * 128 + cq * 4] =
                make_float4(acc[r * 4], acc[r * 4 + 1], acc[r * 4 + 2], acc[r * 4 + 3]);
        __syncthreads();
        float v0 = 0.f, v1 = 0.f;
        #pragma unroll
        for (int gg = 0; gg < 8; gg++) {
            float2 rv = *(const float2*)&red[row_o * RSTRIDE + gg * 128 + coll];
            v0 += rv.x; v1 += rv.y;
        }
        ((float*)&y4s[col])[row_o]     = sigf(v0 + byv0);
        ((float*)&y4s[col + 1])[row_o] = sigf(v1 + byv1);
        __syncthreads();
        if (kq == 0) {
            #pragma unroll
            for (int j = 0; j < 4; j++) {
                int idx = c0 + cq + 32 * j;
                st_cluster_f4(py4 + (uint32_t)idx * 16u, y4s[idx]);
            }
        }
        cluster_sync_all();

        gemv16_g(W2x + (size_t)(kq * 32) * 256 + c0 + cq * 4, y4s + kq * 32, acc);
        #pragma unroll
        for (int r = 0; r < 4; r++)
            *(float4*)&red[r * RSTRIDE + kq * 128 + cq * 4] =
                make_float4(acc[r * 4], acc[r * 4 + 1], acc[r * 4 + 2], acc[r * 4 + 3]);
        __syncthreads();
        v0 = 0.f; v1 = 0.f;
        #pragma unroll
        for (int gg = 0; gg < 8; gg++) {
            float2 rv = *(const float2*)&red[row_o * RSTRIDE + gg * 128 + coll];
            v0 += rv.x; v1 += rv.y;
        }
        base00 = v0 + bb0; base01 = v1 + bb1;
        __syncthreads();
    }

    fill_w(ws, W2a, c0, t, 256);
    fill_w(wy_lo, Wy, c0, t, 128);
    __syncthreads();

    const float* wsp   = ws + kq * 32 * 128 + cq * 4;
    const float* wylop = wy_lo + kq * 32 * 128 + cq * 4;

    // ======================= decoder (R4) =======================
    for (int i = 0; i < LL; i++) {
        const int p = i & 1, q = p ^ 1;
        float acc[16];

        gemv16_s(wsp, &a4s[p * 256 + kq * 32], acc);
        #pragma unroll
        for (int r = 0; r < 4; r++)
            *(float4*)&red[r * RSTRIDE + kq * 128 + cq * 4] =
                make_float4(acc[r * 4], acc[r * 4 + 1], acc[r * 4 + 2], acc[r * 4 + 3]);
        __syncthreads();
        if (kq == 1) mbar_arrive_cluster(pdRD[p]);

        float v0 = 0.f, v1 = 0.f;
        #pragma unroll
        for (int gg = 0; gg < 8; gg++) {
            float2 rv = *(const float2*)&red[row_o * RSTRIDE + gg * 128 + coll];
            v0 += rv.x; v1 += rv.y;
        }
        float bs0 = (i == 0) ? base00 : bb0;
        float bs1 = (i == 0) ? base01 : bb1;
        ((float*)&a4s[q * 256 + col])[row_o]     = tanhfast(v0 + bs0);
        ((float*)&a4s[q * 256 + col + 1])[row_o] = tanhfast(v1 + bs1);
        __syncthreads();

        if (kq == 0) mbar_wait_par(dRD[q], drdp[q]);
        drdp[q] ^= 1;
        if (kq == 0) {
            #pragma unroll
            for (int j = 0; j < 4; j++) {
                int idx = c0 + cq + 32 * j;
                st_cluster_f4(pa4[q] + (uint32_t)idx * 16u, a4s[q * 256 + idx]);
            }
            mbar_arrive_cluster(pdF[q]);
        }

        if (is_peer) mbar_wait_par(dF[q], dfp[q]);
        dfp[q] ^= 1;

        if (kq < 4) gemv16_s(wylop, &a4s[q * 256 + kq * 32], acc);
        else        gemv16_g(Wy + (size_t)(kq * 32) * 256 + c0 + cq * 4,
                             &a4s[q * 256 + kq * 32], acc);
        #pragma unroll
        for (int r = 0; r < 4; r++)
            *(float4*)&red[r * RSTRIDE + kq * 128 + cq * 4] =
                make_float4(acc[r * 4], acc[r * 4 + 1], acc[r * 4 + 2], acc[r * 4 + 3]);
        __syncthreads();
        v0 = 0.f; v1 = 0.f;
        #pragma unroll
        for (int gg = 0; gg < 8; gg++) {
            float2 rv = *(const float2*)&red[row_o * RSTRIDE + gg * 128 + coll];
            v0 += rv.x; v1 += rv.y;
        }
        float2 yo = make_float2(sigf(v0 + byv0), sigf(v1 + byv1));
        *(float2*)&out[((size_t)brow * LL + i) * OO + col] = yo;
        __syncthreads();
    }

    cluster_sync_all();
}

// ---------------------------------------------------------------------------
extern "C" void kernel_launch(void* const* d_in, const int* in_sizes, int n_in,
                              void* d_out, int out_size)
{
    const float* x   = (const float*)d_in[0];
    const float* W1x = (const float*)d_in[1];
    const float* b1x = (const float*)d_in[2];
    const float* W1a = (const float*)d_in[3];
    const float* b1a = (const float*)d_in[4];
    const float* W2x = (const float*)d_in[5];
    const float* b2x = (const float*)d_in[6];
    const float* W2a = (const float*)d_in[7];
    const float* b2a = (const float*)d_in[8];
    const float* Wy  = (const float*)d_in[9];
    const float* by  = (const float*)d_in[10];
    float* out = (float*)d_out;

    (void)in_sizes; (void)n_in; (void)out_size;

    cudaFuncSetAttribute(xproj_mma_kernel,
                         cudaFuncAttributeMaxDynamicSharedMemorySize, XP_SMEM);
    cudaFuncSetAttribute(rnn_kernel,
                         cudaFuncAttributeMaxDynamicSharedMemorySize, RNN_SMEM);

    wconv_kernel<<<256, 256>>>(W1x);
    dim3 xgrid((BB * SS) / 128, HH / 128);
    xproj_mma_kernel<<<xgrid, 256, XP_SMEM>>>(x, b1x, b1a);
    rnn_kernel<<<BB / 2, 256, RNN_SMEM>>>(W1a, W2x, b2x, W2a, b2a, Wy, by, out);
}

// round 13
// speedup vs baseline: 1.7625x; 1.0575x over previous
#include <cuda_runtime.h>
#include <cuda_bf16.h>
#include <math.h>
#include <stdint.h>

#define BB 256
#define SS 512
#define II 256
#define HH 256
#define OO 256
#define LL 64

__device__ float g_xproj[(size_t)SS * BB * HH];
__device__ float g_ahist[(size_t)BB * LL * HH];     // decoder states [b*64+i][h]
__device__ __nv_bfloat16 g_wh[256 * 256];           // W1x^T hi [n][k]
__device__ __nv_bfloat16 g_wl[256 * 256];
__device__ __nv_bfloat16 g_wyh[256 * 256];          // Wy^T hi [n][k]
__device__ __nv_bfloat16 g_wyl[256 * 256];

__device__ __forceinline__ float sigf(float x) {
    return __fdividef(1.f, 1.f + __expf(-x));
}
__device__ __forceinline__ float tanhfast(float x) {
    float e = __expf(2.f * x);
    return 1.f - __fdividef(2.f, e + 1.f);
}

__device__ __forceinline__ uint32_t smem_u32(const void* p) {
    uint32_t r;
    asm("{ .reg .u64 t; cvta.to.shared.u64 t, %1; cvt.u32.u64 %0, t; }" : "=r"(r) : "l"(p));
    return r;
}
__device__ __forceinline__ uint32_t mapa_peer(uint32_t a, uint32_t peer) {
    uint32_t r;
    asm("mapa.shared::cluster.u32 %0, %1, %2;" : "=r"(r) : "r"(a), "r"(peer));
    return r;
}
__device__ __forceinline__ void mbar_init(uint32_t a, uint32_t c) {
    asm volatile("mbarrier.init.shared.b64 [%0], %1;" :: "r"(a), "r"(c) : "memory");
}
__device__ __forceinline__ void mbar_arrive_local(uint32_t a) {
    asm volatile("mbarrier.arrive.release.cta.shared::cta.b64 _, [%0];"
                 :: "r"(a) : "memory");
}
__device__ __forceinline__ void mbar_arrive_cluster(uint32_t a) {
    asm volatile("mbarrier.arrive.release.cluster.shared::cluster.b64 _, [%0];"
                 :: "r"(a) : "memory");
}
__device__ __forceinline__ void mbar_wait_par(uint32_t a, uint32_t par) {
    asm volatile(
        "{\n\t.reg .pred P;\n\t"
        "WL%=:\n\t"
        "mbarrier.try_wait.parity.acquire.cluster.shared::cta.b64 P, [%0], %1, 0x989680;\n\t"
        "@P bra WD%=;\n\t"
        "bra WL%=;\n\t"
        "WD%=:\n\t}"
        :: "r"(a), "r"(par) : "memory");
}
__device__ __forceinline__ void st_cluster_f4(uint32_t a, float4 v) {
    asm volatile("st.shared::cluster.v4.b32 [%0], {%1,%2,%3,%4};" :: "r"(a),
                 "r"(__float_as_uint(v.x)), "r"(__float_as_uint(v.y)),
                 "r"(__float_as_uint(v.z)), "r"(__float_as_uint(v.w)) : "memory");
}
__device__ __forceinline__ void st_cluster_u32(uint32_t a, uint32_t v) {
    asm volatile("st.shared::cluster.b32 [%0], %1;" :: "r"(a), "r"(v) : "memory");
}
__device__ __forceinline__ void cluster_sync_all() {
    asm volatile("barrier.cluster.arrive.aligned;" ::: "memory");
    asm volatile("barrier.cluster.wait.aligned;" ::: "memory");
}
__device__ __forceinline__ void ldsm_x4(uint32_t addr, uint32_t r[4]) {
    asm volatile("ldmatrix.sync.aligned.m8n8.x4.shared.b16 {%0,%1,%2,%3}, [%4];"
                 : "=r"(r[0]), "=r"(r[1]), "=r"(r[2]), "=r"(r[3]) : "r"(addr));
}
__device__ __forceinline__ void ldsm_x2t(uint32_t addr, uint32_t& r0, uint32_t& r1) {
    asm volatile("ldmatrix.sync.aligned.m8n8.x2.trans.shared.b16 {%0,%1}, [%2];"
                 : "=r"(r0), "=r"(r1) : "r"(addr));
}
__device__ __forceinline__ void mma_bf16(float c[4], const uint32_t a[4],
                                         uint32_t b0, uint32_t b1) {
    asm volatile(
        "mma.sync.aligned.m16n8k16.row.col.f32.bf16.bf16.f32 "
        "{%0,%1,%2,%3}, {%4,%5,%6,%7}, {%8,%9}, {%0,%1,%2,%3};"
        : "+f"(c[0]), "+f"(c[1]), "+f"(c[2]), "+f"(c[3])
        : "r"(a[0]), "r"(a[1]), "r"(a[2]), "r"(a[3]), "r"(b0), "r"(b1));
}
__device__ __forceinline__ uint32_t packbf2(float a, float b) {
    __nv_bfloat16 ha = __float2bfloat16(a), hb = __float2bfloat16(b);
    return ((uint32_t)__bfloat16_as_ushort(hb) << 16) | __bfloat16_as_ushort(ha);
}
__device__ __forceinline__ float bfu(uint32_t u) {
    return __bfloat162float(__ushort_as_bfloat16((unsigned short)(u & 0xffffu)));
}

// ===========================================================================
// Kernel 0a/0b: W1x / Wy -> bf16 hi/lo, transposed to [n][k]
// ===========================================================================
__global__ void wconv_kernel(const float* __restrict__ W1x)
{
    int k = blockIdx.x, n = threadIdx.x;
    float v = W1x[k * 256 + n];
    __nv_bfloat16 h = __float2bfloat16(v);
    __nv_bfloat16 l = __float2bfloat16(v - __bfloat162float(h));
    g_wh[n * 256 + k] = h;
    g_wl[n * 256 + k] = l;
}
__global__ void wconv_wy_kernel(const float* __restrict__ Wy)
{
    int k = blockIdx.x, n = threadIdx.x;
    float v = Wy[k * 256 + n];
    __nv_bfloat16 h = __float2bfloat16(v);
    __nv_bfloat16 l = __float2bfloat16(v - __bfloat162float(h));
    g_wyh[n * 256 + k] = h;
    g_wyl[n * 256 + k] = l;
}

// ===========================================================================
// Shared GEMM pieces (R8-proven)
// ===========================================================================
#define SB_BH    0
#define SB_BL    65536
#define SB_A     131072
#define SB_BIAS  196608
#define XP_SMEM  197120

__device__ __forceinline__ void afragx(uint32_t Ab, int mbase, int j, int lane,
                                       uint32_t r[4]) {
    int row = mbase + (lane & 15);
    int q   = j * 2 + (lane >> 4);
    uint32_t addr = Ab + (uint32_t)(row * 128 + ((q ^ row) & 7) * 16);
    ldsm_x4(addr, r);
}
__device__ __forceinline__ void bfragx(uint32_t Bb, int nbase, int ks, int lane,
                                       uint32_t r[4]) {
    int row = nbase + (lane & 7) + ((lane >> 4) << 3);
    int q   = ks * 2 + ((lane >> 3) & 1);
    uint32_t qp = (uint32_t)((q & ~7) | ((q ^ row) & 7));
    uint32_t addr = Bb + (uint32_t)(row * 512) + qp * 16;
    ldsm_x4(addr, r);
}

// A chunk loader from an fp32 row-major [rows][256] matrix slice
__device__ __forceinline__ void load_a_rows(unsigned char* sm, int p,
                                            const float* __restrict__ Arows,
                                            int c, int t)
{
    const int r = t >> 1, hf = t & 1, rx = r & 7;
    unsigned char* ah = sm + SB_A + p * 32768;
    unsigned char* al = ah + 16384;
    const float* xr = Arows + (size_t)r * 256 + c * 64 + hf * 32;
    #pragma unroll
    for (int jj = 0; jj < 4; jj++) {
        float4 v0 = *(const float4*)(xr + jj * 8);
        float4 v1 = *(const float4*)(xr + jj * 8 + 4);
        uint4 h, l;
        h.x = packbf2(v0.x, v0.y); h.y = packbf2(v0.z, v0.w);
        h.z = packbf2(v1.x, v1.y); h.w = packbf2(v1.z, v1.w);
        l.x = packbf2(v0.x - bfu(h.x), v0.y - bfu(h.x >> 16));
        l.y = packbf2(v0.z - bfu(h.y), v0.w - bfu(h.y >> 16));
        l.z = packbf2(v1.x - bfu(h.z), v1.y - bfu(h.z >> 16));
        l.w = packbf2(v1.z - bfu(h.w), v1.w - bfu(h.w >> 16));
        int q = hf * 4 + jj;
        uint32_t off = (uint32_t)(r * 128 + (q ^ rx) * 16);
        *(uint4*)(ah + off) = h;
        *(uint4*)(al + off) = l;
    }
}

// GEMM body: D[128 x 128] = A(fp32 rows, staged hi/lo) @ Bt(hi/lo), 3-term.
// mode 0: xproj epilogue (acc + bias -> g_xproj rows = m0)
// mode 1: y epilogue (sigmoid(acc + by) -> out rows = m0)
template <int MODE>
__device__ __forceinline__ void gemm128(const float* __restrict__ Arows, int m0,
                                        const __nv_bfloat16* __restrict__ Wth,
                                        const __nv_bfloat16* __restrict__ Wtl,
                                        const float* __restrict__ bias1,
                                        const float* __restrict__ bias2,
                                        int n0, float* __restrict__ outp)
{
    extern __shared__ __align__(1024) unsigned char sm[];
    const int t = threadIdx.x;
    const int wid = t >> 5, lane = t & 31;
    const uint32_t smb = smem_u32(sm);
    const int mw = (wid & 1) * 64;
    const int nw = (wid >> 1) * 32;

    #pragma unroll 4
    for (int i = 0; i < 16; i++) {
        int idx = i * 256 + t;
        int rr = idx >> 5, q = idx & 31;
        uint32_t qp = (uint32_t)((q & ~7) | ((q ^ rr) & 7));
        size_t src = (size_t)(n0 + rr) * 256 + q * 8;
        *(uint4*)(sm + SB_BH + rr * 512 + qp * 16) = *(const uint4*)(Wth + src);
        *(uint4*)(sm + SB_BL + rr * 512 + qp * 16) = *(const uint4*)(Wtl + src);
    }
    if (t < 128) {
        float b = bias1[n0 + t];
        if (bias2) b += bias2[n0 + t];
        ((float*)(sm + SB_BIAS))[t] = b;
    }
    load_a_rows(sm, 0, Arows, 0, t);
    __syncthreads();

    float acc[4][4][4];
    #pragma unroll
    for (int mt = 0; mt < 4; mt++)
        #pragma unroll
        for (int nt = 0; nt < 4; nt++)
            #pragma unroll
            for (int e = 0; e < 4; e++) acc[mt][nt][e] = 0.f;

    const uint32_t Bh = smb + SB_BH, Bl = smb + SB_BL;

    #pragma unroll 1
    for (int c = 0; c < 4; c++) {
        const int p = c & 1;
        if (c < 3) load_a_rows(sm, 1 - p, Arows, c + 1, t);
        const uint32_t Abh = smb + SB_A + p * 32768;
        const uint32_t Abl = Abh + 16384;
        #pragma unroll
        for (int j = 0; j < 4; j++) {
            const int ks = c * 4 + j;
            uint32_t bh[8], bl[8];
            bfragx(Bh, nw,      ks, lane, bh);
            bfragx(Bh, nw + 16, ks, lane, bh + 4);
            bfragx(Bl, nw,      ks, lane, bl);
            bfragx(Bl, nw + 16, ks, lane, bl + 4);
            #pragma unroll
            for (int mt = 0; mt < 4; mt++) {
                uint32_t ah[4], al[4];
                afragx(Abh, mw + mt * 16, j, lane, ah);
                afragx(Abl, mw + mt * 16, j, lane, al);
                #pragma unroll
                for (int nt = 0; nt < 4; nt++) {
                    mma_bf16(acc[mt][nt], ah, bh[nt * 2], bh[nt * 2 + 1]);
                    mma_bf16(acc[mt][nt], ah, bl[nt * 2], bl[nt * 2 + 1]);
                    mma_bf16(acc[mt][nt], al, bh[nt * 2], bh[nt * 2 + 1]);
                }
            }
        }
        __syncthreads();
    }

    const int g = lane >> 2, tig = lane & 3;
    const float* bias_sm = (const float*)(sm + SB_BIAS);
    #pragma unroll
    for (int mt = 0; mt < 4; mt++) {
        const int mrow = m0 + mw + mt * 16 + g;
        #pragma unroll
        for (int nt = 0; nt < 4; nt++) {
            const int nl = nw + nt * 8 + tig * 2;
            const float bz0 = bias_sm[nl], bz1 = bias_sm[nl + 1];
            float2 v0, v1;
            if (MODE == 0) {
                v0 = make_float2(acc[mt][nt][0] + bz0, acc[mt][nt][1] + bz1);
                v1 = make_float2(acc[mt][nt][2] + bz0, acc[mt][nt][3] + bz1);
            } else {
                v0 = make_float2(sigf(acc[mt][nt][0] + bz0), sigf(acc[mt][nt][1] + bz1));
                v1 = make_float2(sigf(acc[mt][nt][2] + bz0), sigf(acc[mt][nt][3] + bz1));
            }
            *(float2*)&outp[(size_t)mrow * 256 + n0 + nl] = v0;
            *(float2*)&outp[(size_t)(mrow + 8) * 256 + n0 + nl] = v1;
        }
    }
}

// xproj: rows m = s*256 + b ; A rows come from x[(b0+r)*SS + s]*II
__global__ __launch_bounds__(256, 1) void xproj_mma_kernel(
    const float* __restrict__ x,
    const float* __restrict__ b1x, const float* __restrict__ b1a)
{
    const int m0 = blockIdx.x * 128;
    const int n0 = blockIdx.y * 128;
    const int s  = m0 >> 8;
    const int b0 = m0 & 255;
    // x rows for (b0+r, s): row stride = SS*II, but gemm128 expects stride 256.
    // x[(b0+r)*SS + s][k] has row-to-row stride SS*256 floats; build base ptr and
    // use a custom stride by faking: we inline a variant here instead.
    // (A rows are NOT stride-256; use dedicated loader.)
    extern __shared__ __align__(1024) unsigned char sm[];
    const int t = threadIdx.x;
    const int wid = t >> 5, lane = t & 31;
    const uint32_t smb = smem_u32(sm);
    const int mw = (wid & 1) * 64;
    const int nw = (wid >> 1) * 32;

    #pragma unroll 4
    for (int i = 0; i < 16; i++) {
        int idx = i * 256 + t;
        int rr = idx >> 5, q = idx & 31;
        uint32_t qp = (uint32_t)((q & ~7) | ((q ^ rr) & 7));
        size_t src = (size_t)(n0 + rr) * 256 + q * 8;
        *(uint4*)(sm + SB_BH + rr * 512 + qp * 16) = *(const uint4*)(g_wh + src);
        *(uint4*)(sm + SB_BL + rr * 512 + qp * 16) = *(const uint4*)(g_wl + src);
    }
    if (t < 128)
        ((float*)(sm + SB_BIAS))[t] = b1x[n0 + t] + b1a[n0 + t];

    auto load_chunk = [&](int p, int c) {
        const int r = t >> 1, hf = t & 1, rx = r & 7;
        unsigned char* ah = sm + SB_A + p * 32768;
        unsigned char* al = ah + 16384;
        const float* xr = x + ((size_t)(b0 + r) * SS + s) * II + c * 64 + hf * 32;
        #pragma unroll
        for (int jj = 0; jj < 4; jj++) {
            float4 v0 = *(const float4*)(xr + jj * 8);
            float4 v1 = *(const float4*)(xr + jj * 8 + 4);
            uint4 h, l;
            h.x = packbf2(v0.x, v0.y); h.y = packbf2(v0.z, v0.w);
            h.z = packbf2(v1.x, v1.y); h.w = packbf2(v1.z, v1.w);
            l.x = packbf2(v0.x - bfu(h.x), v0.y - bfu(h.x >> 16));
            l.y = packbf2(v0.z - bfu(h.y), v0.w - bfu(h.y >> 16));
            l.z = packbf2(v1.x - bfu(h.z), v1.y - bfu(h.z >> 16));
            l.w = packbf2(v1.z - bfu(h.w), v1.w - bfu(h.w >> 16));
            int q = hf * 4 + jj;
            uint32_t off = (uint32_t)(r * 128 + (q ^ rx) * 16);
            *(uint4*)(ah + off) = h;
            *(uint4*)(al + off) = l;
        }
    };

    load_chunk(0, 0);
    __syncthreads();

    float acc[4][4][4];
    #pragma unroll
    for (int mt = 0; mt < 4; mt++)
        #pragma unroll
        for (int nt = 0; nt < 4; nt++)
            #pragma unroll
            for (int e = 0; e < 4; e++) acc[mt][nt][e] = 0.f;

    const uint32_t Bh = smb + SB_BH, Bl = smb + SB_BL;

    #pragma unroll 1
    for (int c = 0; c < 4; c++) {
        const int p = c & 1;
        if (c < 3) load_chunk(1 - p, c + 1);
        const uint32_t Abh = smb + SB_A + p * 32768;
        const uint32_t Abl = Abh + 16384;
        #pragma unroll
        for (int j = 0; j < 4; j++) {
            const int ks = c * 4 + j;
            uint32_t bh[8], bl[8];
            bfragx(Bh, nw,      ks, lane, bh);
            bfragx(Bh, nw + 16, ks, lane, bh + 4);
            bfragx(Bl, nw,      ks, lane, bl);
            bfragx(Bl, nw + 16, ks, lane, bl + 4);
            #pragma unroll
            for (int mt = 0; mt < 4; mt++) {
                uint32_t ah[4], al[4];
                afragx(Abh, mw + mt * 16, j, lane, ah);
                afragx(Abl, mw + mt * 16, j, lane, al);
                #pragma unroll
                for (int nt = 0; nt < 4; nt++) {
                    mma_bf16(acc[mt][nt], ah, bh[nt * 2], bh[nt * 2 + 1]);
                    mma_bf16(acc[mt][nt], ah, bl[nt * 2], bl[nt * 2 + 1]);
                    mma_bf16(acc[mt][nt], al, bh[nt * 2], bh[nt * 2 + 1]);
                }
            }
        }
        __syncthreads();
    }

    const int g = lane >> 2, tig = lane & 3;
    const float* bias_sm = (const float*)(sm + SB_BIAS);
    #pragma unroll
    for (int mt = 0; mt < 4; mt++) {
        const int mrow = m0 + mw + mt * 16 + g;
        #pragma unroll
        for (int nt = 0; nt < 4; nt++) {
            const int nl = nw + nt * 8 + tig * 2;
            const float bz0 = bias_sm[nl], bz1 = bias_sm[nl + 1];
            float2 v0 = make_float2(acc[mt][nt][0] + bz0, acc[mt][nt][1] + bz1);
            float2 v1 = make_float2(acc[mt][nt][2] + bz0, acc[mt][nt][3] + bz1);
            *(float2*)&g_xproj[(size_t)mrow * HH + n0 + nl] = v0;
            *(float2*)&g_xproj[(size_t)(mrow + 8) * HH + n0 + nl] = v1;
        }
    }
}

// Y GEMM: out = sigmoid(a_hist @ Wy + by), rows = b*64+i (stride-256 A — gemm128)
__global__ __launch_bounds__(256, 1) void y_mma_kernel(
    const float* __restrict__ by, float* __restrict__ out)
{
    gemm128<1>(g_ahist + (size_t)blockIdx.x * 128 * 256, blockIdx.x * 128,
               g_wyh, g_wyl, by, nullptr, blockIdx.y * 128, out);
}

// ===========================================================================
// Kernel 2: RNN. Encoder + decoder = tensor-core ring (R11 protocol).
// ===========================================================================
#define A_STRIDE 528
#define ALO      67584
#define RING(i)  (135168 + (i) * 8192)
#define A4OFF    196608
#define Y4OFF    204800
#define REDOFF   208896
#define MBOFF    225408
#define BASEOFF  225472
#define RNN_SMEM 229568
#define RSTRIDE  1032

__device__ __forceinline__ void gemv16_g(const float* __restrict__ Wp,
                                         const float4* __restrict__ a, float acc[16])
{
    #pragma unroll
    for (int j = 0; j < 16; j++) acc[j] = 0.f;
    #pragma unroll 16
    for (int k = 0; k < 32; k++) {
        float4 w  = *(const float4*)(Wp + (size_t)k * 256);
        float4 av = a[k];
        acc[0]  = fmaf(av.x, w.x, acc[0]);  acc[1]  = fmaf(av.x, w.y, acc[1]);
        acc[2]  = fmaf(av.x, w.z, acc[2]);  acc[3]  = fmaf(av.x, w.w, acc[3]);
        acc[4]  = fmaf(av.y, w.x, acc[4]);  acc[5]  = fmaf(av.y, w.y, acc[5]);
        acc[6]  = fmaf(av.y, w.z, acc[6]);  acc[7]  = fmaf(av.y, w.w, acc[7]);
        acc[8]  = fmaf(av.z, w.x, acc[8]);  acc[9]  = fmaf(av.z, w.y, acc[9]);
        acc[10] = fmaf(av.z, w.z, acc[10]); acc[11] = fmaf(av.z, w.w, acc[11]);
        acc[12] = fmaf(av.w, w.x, acc[12]); acc[13] = fmaf(av.w, w.y, acc[13]);
        acc[14] = fmaf(av.w, w.z, acc[14]); acc[15] = fmaf(av.w, w.w, acc[15]);
    }
}

__global__ __launch_bounds__(256, 1) __cluster_dims__(2, 1, 1)
void rnn_kernel(const float* __restrict__ W1a,
                const float* __restrict__ W2x, const float* __restrict__ b2x,
                const float* __restrict__ W2a, const float* __restrict__ b2a,
                const float* __restrict__ Wy,  const float* __restrict__ by)
{
    extern __shared__ __align__(16) unsigned char dsm[];
    float4* a4s   = (float4*)(dsm + A4OFF);
    float4* y4s   = (float4*)(dsm + Y4OFF);
    float*  red   = (float*)(dsm + REDOFF);
    float*  basef = (float*)(dsm + BASEOFF);
    unsigned long long* mbars = (unsigned long long*)(dsm + MBOFF);

    const int t    = threadIdx.x;
    const int lane = t & 31;
    const int wid  = t >> 5;
    uint32_t rank;
    asm("mov.u32 %0, %%cluster_ctarank;" : "=r"(rank));
    const uint32_t peer = rank ^ 1;
    const int b0 = (blockIdx.x >> 1) * 4;
    const int c0 = (int)rank * 128;
    const uint32_t smb = smem_u32(dsm);

    // ring thread mapping
    const int mb   = wid * 16;
    const int g    = lane >> 2;
    const int tig  = lane & 3;
    const bool act = (tig < 2);
    const int colg = c0 + mb + g;
    const int nb   = 2 * tig;
    const uint32_t aAddrBase = smb + (uint32_t)((mb + (lane & 15)) * A_STRIDE)
                             + (uint32_t)((lane >> 4) * 16);

    // glue mapping (R4)
    const int kq = wid, cq = lane;
    const int o0    = 2 * t;
    const int row_o = (o0 >> 2) & 3;
    const int coll  = (o0 >> 4) * 4 + (o0 & 3);
    const int col   = c0 + coll;

    uint32_t eF[4], peF[4], pRG[4];
    #pragma unroll
    for (int i = 0; i < 4; i++) {
        eF[i]  = smem_u32(&mbars[i]);
        peF[i] = mapa_peer(eF[i], peer);
        pRG[i] = mapa_peer(smb + (uint32_t)RING(i), peer);
    }
    uint32_t py4 = mapa_peer(smb + Y4OFF, peer);

    if (t == 0) {
        mbar_init(eF[0], 128); mbar_init(eF[1], 128);
        mbar_init(eF[2], 128); mbar_init(eF[3], 128);
    }
    {
        uint4 z = make_uint4(0, 0, 0, 0);
        *(uint4*)(dsm + RING(3) + t * 16) = z;
        *(uint4*)(dsm + RING(3) + (t + 256) * 16) = z;
    }
    // stage A = W1a^T hi/lo
    {
        const int m = t & 127, hb = t >> 7;
        #pragma unroll 4
        for (int kk = 0; kk < 128; kk++) {
            int k = hb * 128 + kk;
            float v = W1a[(size_t)k * 256 + c0 + m];
            __nv_bfloat16 h = __float2bfloat16(v);
            __nv_bfloat16 l = __float2bfloat16(v - __bfloat162float(h));
            *(unsigned short*)(dsm + m * A_STRIDE + k * 2) = __bfloat16_as_ushort(h);
            *(unsigned short*)(dsm + ALO + m * A_STRIDE + k * 2) = __bfloat16_as_ushort(l);
        }
    }
    __syncthreads();
    cluster_sync_all();
    if (act) mbar_arrive_local(eF[3]);

    float xc00 = 0.f, xc01 = 0.f, xc10 = 0.f, xc11 = 0.f;
    if (act) {
        const float* xb = g_xproj + (size_t)(b0 + nb) * HH;
        xc00 = __ldcs(xb + colg);
        xc01 = __ldcs(xb + (size_t)HH + colg);
        xc10 = __ldcs(xb + colg + 8);
        xc11 = __ldcs(xb + (size_t)HH + colg + 8);
    }

    int fp0 = 0, fp1 = 0, fp2 = 0, fp3 = 0;

    // ring step core: returns 6x4 acc sums for act threads
    auto ring_mma = [&](uint32_t eFr, int& fpr, uint32_t bsr, bool skipwait,
                        float sums[4]) {
        float acc[6][4];
        #pragma unroll
        for (int i = 0; i < 6; i++)
            #pragma unroll
            for (int e = 0; e < 4; e++) acc[i][e] = 0.f;
        const uint32_t Bsr = smb + bsr;
        #pragma unroll
        for (int j = 0; j < 8; j++) {
            const int k0 = c0 + j * 16;
            uint32_t ah[4], al[4], bh0, bh1, bl0, bl1;
            uint32_t aa = aAddrBase + (uint32_t)k0 * 2;
            ldsm_x4(aa, ah);
            ldsm_x4(aa + ALO, al);
            uint32_t ba = Bsr + (uint32_t)((k0 + (lane & 15)) * 16);
            ldsm_x2t(ba, bh0, bh1);
            ldsm_x2t(ba + 4096, bl0, bl1);
            const int sel = j & 1;
            mma_bf16(acc[sel],     ah, bh0, bh1);
            mma_bf16(acc[2 + sel], ah, bl0, bl1);
            mma_bf16(acc[4 + sel], al, bh0, bh1);
        }
        if (!skipwait) { mbar_wait_par(eFr, fpr); fpr ^= 1; }
        #pragma unroll
        for (int j = 0; j < 8; j++) {
            const int k0 = (c0 ^ 128) + j * 16;
            uint32_t ah[4], al[4], bh0, bh1, bl0, bl1;
            uint32_t aa = aAddrBase + (uint32_t)k0 * 2;
            ldsm_x4(aa, ah);
            ldsm_x4(aa + ALO, al);
            uint32_t ba = Bsr + (uint32_t)((k0 + (lane & 15)) * 16);
            ldsm_x2t(ba, bh0, bh1);
            ldsm_x2t(ba + 4096, bl0, bl1);
            const int sel = j & 1;
            mma_bf16(acc[sel],     ah, bh0, bh1);
            mma_bf16(acc[2 + sel], ah, bl0, bl1);
            mma_bf16(acc[4 + sel], al, bh0, bh1);
        }
        #pragma unroll
        for (int e = 0; e < 4; e++)
            sums[e] = acc[0][e] + acc[1][e] + acc[2][e] + acc[3][e]
                    + acc[4][e] + acc[5][e];
    };

    auto push_state = [&](uint32_t bsw, uint32_t pbsw, uint32_t pefw,
                          float t00, float t01, float t10, float t11) {
        uint32_t hA = packbf2(t00, t01);
        uint32_t hB = packbf2(t10, t11);
        uint32_t lA = packbf2(t00 - bfu(hA), t01 - bfu(hA >> 16));
        uint32_t lB = packbf2(t10 - bfu(hB), t11 - bfu(hB >> 16));
        const uint32_t o1 = (uint32_t)(colg * 16 + tig * 4);
        const uint32_t o2 = (uint32_t)((colg + 8) * 16 + tig * 4);
        *(uint32_t*)(dsm + bsw + o1) = hA;
        *(uint32_t*)(dsm + bsw + o2) = hB;
        *(uint32_t*)(dsm + bsw + 4096 + o1) = lA;
        *(uint32_t*)(dsm + bsw + 4096 + o2) = lB;
        st_cluster_u32(pbsw + o1, hA);
        st_cluster_u32(pbsw + o2, hB);
        st_cluster_u32(pbsw + 4096 + o1, lA);
        st_cluster_u32(pbsw + 4096 + o2, lB);
        mbar_arrive_cluster(pefw);
    };

    // ======================= encoder =======================
    auto enc_step = [&](int s, uint32_t eFr, int& fpr, uint32_t bsr, uint32_t bsw,
                        uint32_t pbsw, uint32_t pefw) {
        float xn00 = 0.f, xn01 = 0.f, xn10 = 0.f, xn11 = 0.f;
        if (act && s + 1 < SS) {
            const float* xb = g_xproj + ((size_t)(s + 1) * BB + (b0 + nb)) * HH;
            xn00 = __ldcs(xb + colg);
            xn01 = __ldcs(xb + (size_t)HH + colg);
            xn10 = __ldcs(xb + colg + 8);
            xn11 = __ldcs(xb + (size_t)HH + colg + 8);
        }
        float sums[4];
        ring_mma(eFr, fpr, bsr, false, sums);
        if (act) {
            push_state(bsw, pbsw, pefw,
                       tanhfast(sums[0] + xc00), tanhfast(sums[1] + xc01),
                       tanhfast(sums[2] + xc10), tanhfast(sums[3] + xc11));
        }
        __syncthreads();
        xc00 = xn00; xc01 = xn01; xc10 = xn10; xc11 = xn11;
    };

    #pragma unroll 1
    for (int sb = 0; sb < SS; sb += 4) {
        enc_step(sb + 0, eF[3], fp3, RING(3), RING(0), pRG[0], peF[0]);
        enc_step(sb + 1, eF[0], fp0, RING(0), RING(1), pRG[1], peF[1]);
        enc_step(sb + 2, eF[1], fp1, RING(1), RING(2), pRG[2], peF[2]);
        enc_step(sb + 3, eF[2], fp2, RING(2), RING(3), pRG[3], peF[3]);
    }

    // a_last in slot 3
    mbar_wait_par(eF[3], fp3); fp3 ^= 1;
    {
        uint32_t w0h = *(const uint32_t*)(dsm + RING(3) + t * 16);
        uint32_t w1h = *(const uint32_t*)(dsm + RING(3) + t * 16 + 4);
        uint32_t w0l = *(const uint32_t*)(dsm + RING(3) + 4096 + t * 16);
        uint32_t w1l = *(const uint32_t*)(dsm + RING(3) + 4096 + t * 16 + 4);
        a4s[t] = make_float4(bfu(w0h) + bfu(w0l), bfu(w0h >> 16) + bfu(w0l >> 16),
                             bfu(w1h) + bfu(w1l), bfu(w1h >> 16) + bfu(w1l >> 16));
    }
    __syncthreads();

    // ======================= glue: y0, base =======================
    {
        float2 byv = *(const float2*)&by[col];
        float2 b2xv = *(const float2*)&b2x[col];
        float2 b2av = *(const float2*)&b2a[col];
        float bb0 = b2xv.x + b2av.x, bb1 = b2xv.y + b2av.y;

        float acc[16];
        gemv16_g(Wy + (size_t)(kq * 32) * 256 + c0 + cq * 4, &a4s[kq * 32], acc);
        #pragma unroll
        for (int r = 0; r < 4; r++)
            *(float4*)&red[r * RSTRIDE + kq * 128 + cq * 4] =
                make_float4(acc[r * 4], acc[r * 4 + 1], acc[r * 4 + 2], acc[r * 4 + 3]);
        __syncthreads();
        float v0 = 0.f, v1 = 0.f;
        #pragma unroll
        for (int gg = 0; gg < 8; gg++) {
            float2 rv = *(const float2*)&red[row_o * RSTRIDE + gg * 128 + coll];
            v0 += rv.x; v1 += rv.y;
        }
        ((float*)&y4s[col])[row_o]     = sigf(v0 + byv.x);
        ((float*)&y4s[col + 1])[row_o] = sigf(v1 + byv.y);
        __syncthreads();
        if (kq == 0) {
            #pragma unroll
            for (int j = 0; j < 4; j++) {
                int idx = c0 + cq + 32 * j;
                st_cluster_f4(py4 + (uint32_t)idx * 16u, y4s[idx]);
            }
        }
        cluster_sync_all();

        gemv16_g(W2x + (size_t)(kq * 32) * 256 + c0 + cq * 4, y4s + kq * 32, acc);
        #pragma unroll
        for (int r = 0; r < 4; r++)
            *(float4*)&red[r * RSTRIDE + kq * 128 + cq * 4] =
                make_float4(acc[r * 4], acc[r * 4 + 1], acc[r * 4 + 2], acc[r * 4 + 3]);
        __syncthreads();
        v0 = 0.f; v1 = 0.f;
        #pragma unroll
        for (int gg = 0; gg < 8; gg++) {
            float2 rv = *(const float2*)&red[row_o * RSTRIDE + gg * 128 + coll];
            v0 += rv.x; v1 += rv.y;
        }
        basef[row_o * 256 + coll]     = v0 + bb0;   // local col index
        basef[row_o * 256 + coll + 1] = v1 + bb1;
        __syncthreads();
    }

    // restage A = W2a^T hi/lo
    {
        const int m = t & 127, hb = t >> 7;
        #pragma unroll 4
        for (int kk = 0; kk < 128; kk++) {
            int k = hb * 128 + kk;
            float v = W2a[(size_t)k * 256 + c0 + m];
            __nv_bfloat16 h = __float2bfloat16(v);
            __nv_bfloat16 l = __float2bfloat16(v - __bfloat162float(h));
            *(unsigned short*)(dsm + m * A_STRIDE + k * 2) = __bfloat16_as_ushort(h);
            *(unsigned short*)(dsm + ALO + m * A_STRIDE + k * 2) = __bfloat16_as_ushort(l);
        }
    }
    __syncthreads();

    // decoder biases for act threads (basef indexed by LOCAL col)
    const int mbg = mb + g;                 // local col of colg
    float bbA = 0.f, bbB = 0.f;
    if (act) {
        bbA = b2x[colg] + b2a[colg];
        bbB = b2x[colg + 8] + b2a[colg + 8];
    }

    // ======================= decoder (ring continues) =======================
    auto dec_step = [&](int i, uint32_t eFr, int& fpr, uint32_t bsr, uint32_t bsw,
                        uint32_t pbsw, uint32_t pefw, bool skipwait) {
        float sums[4];
        ring_mma(eFr, fpr, bsr, skipwait, sums);
        if (act) {
            float a00, a01, a10, a11;
            if (i == 0) {
                a00 = basef[nb * 256 + mbg];
                a01 = basef[(nb + 1) * 256 + mbg];
                a10 = basef[nb * 256 + mbg + 8];
                a11 = basef[(nb + 1) * 256 + mbg + 8];
            } else {
                a00 = bbA; a01 = bbA; a10 = bbB; a11 = bbB;
            }
            float t00 = tanhfast(sums[0] + a00);
            float t01 = tanhfast(sums[1] + a01);
            float t10 = tanhfast(sums[2] + a10);
            float t11 = tanhfast(sums[3] + a11);
            // record state for deferred Y GEMM
            g_ahist[((size_t)(b0 + nb) * LL + i) * 256 + colg]          = t00;
            g_ahist[((size_t)(b0 + nb + 1) * LL + i) * 256 + colg]      = t01;
            g_ahist[((size_t)(b0 + nb) * LL + i) * 256 + colg + 8]      = t10;
            g_ahist[((size_t)(b0 + nb + 1) * LL + i) * 256 + colg + 8]  = t11;
            push_state(bsw, pbsw, pefw, t00, t01, t10, t11);
        }
        __syncthreads();
    };

    #pragma unroll 1
    for (int ib = 0; ib < 16; ib++) {
        const int i0 = ib * 4;
        dec_step(i0 + 0, eF[3], fp3, RING(3), RING(0), pRG[0], peF[0], ib == 0);
        dec_step(i0 + 1, eF[0], fp0, RING(0), RING(1), pRG[1], peF[1], false);
        dec_step(i0 + 2, eF[1], fp1, RING(1), RING(2), pRG[2], peF[2], false);
        dec_step(i0 + 3, eF[2], fp2, RING(2), RING(3), pRG[3], peF[3], false);
    }

    cluster_sync_all();
}

// ---------------------------------------------------------------------------
extern "C" void kernel_launch(void* const* d_in, const int* in_sizes, int n_in,
                              void* d_out, int out_size)
{
    const float* x   = (const float*)d_in[0];
    const float* W1x = (const float*)d_in[1];
    const float* b1x = (const float*)d_in[2];
    const float* W1a = (const float*)d_in[3];
    const float* b1a = (const float*)d_in[4];
    const float* W2x = (const float*)d_in[5];
    const float* b2x = (const float*)d_in[6];
    const float* W2a = (const float*)d_in[7];
    const float* b2a = (const float*)d_in[8];
    const float* Wy  = (const float*)d_in[9];
    const float* by  = (const float*)d_in[10];
    float* out = (float*)d_out;

    (void)in_sizes; (void)n_in; (void)out_size;

    cudaFuncSetAttribute(xproj_mma_kernel,
                         cudaFuncAttributeMaxDynamicSharedMemorySize, XP_SMEM);
    cudaFuncSetAttribute(y_mma_kernel,
                         cudaFuncAttributeMaxDynamicSharedMemorySize, XP_SMEM);
    cudaFuncSetAttribute(rnn_kernel,
                         cudaFuncAttributeMaxDynamicSharedMemorySize, RNN_SMEM);

    wconv_kernel<<<256, 256>>>(W1x);
    wconv_wy_kernel<<<256, 256>>>(Wy);
    dim3 xgrid((BB * SS) / 128, HH / 128);
    xproj_mma_kernel<<<xgrid, 256, XP_SMEM>>>(x, b1x, b1a);
    rnn_kernel<<<BB / 2, 256, RNN_SMEM>>>(W1a, W2x, b2x, W2a, b2a, Wy, by);
    dim3 ygrid((BB * LL) / 128, OO / 128);
    y_mma_kernel<<<ygrid, 256, XP_SMEM>>>(by, out);
}

// round 14
// speedup vs baseline: 2.0616x; 1.1697x over previous
#include <cuda_runtime.h>
#include <cuda_bf16.h>
#include <math.h>
#include <stdint.h>

#define BB 256
#define SS 512
#define II 256
#define HH 256
#define OO 256
#define LL 64

__device__ float g_xproj[(size_t)SS * BB * HH];
__device__ float g_ahist[(size_t)BB * LL * HH];     // decoder states [b*64+i][h]
__device__ __nv_bfloat16 g_wh[256 * 256];           // W1x^T hi [n][k]
__device__ __nv_bfloat16 g_wl[256 * 256];
__device__ __nv_bfloat16 g_wyh[256 * 256];          // Wy^T hi [n][k]
__device__ __nv_bfloat16 g_wyl[256 * 256];

__device__ __forceinline__ float sigf(float x) {
    return __fdividef(1.f, 1.f + __expf(-x));
}
__device__ __forceinline__ float tanhfast(float x) {
    float e = __expf(2.f * x);
    return 1.f - __fdividef(2.f, e + 1.f);
}

__device__ __forceinline__ uint32_t smem_u32(const void* p) {
    uint32_t r;
    asm("{ .reg .u64 t; cvta.to.shared.u64 t, %1; cvt.u32.u64 %0, t; }" : "=r"(r) : "l"(p));
    return r;
}
__device__ __forceinline__ uint32_t mapa_peer(uint32_t a, uint32_t peer) {
    uint32_t r;
    asm("mapa.shared::cluster.u32 %0, %1, %2;" : "=r"(r) : "r"(a), "r"(peer));
    return r;
}
__device__ __forceinline__ void mbar_init(uint32_t a, uint32_t c) {
    asm volatile("mbarrier.init.shared.b64 [%0], %1;" :: "r"(a), "r"(c) : "memory");
}
__device__ __forceinline__ void mbar_arrive_local(uint32_t a) {
    asm volatile("mbarrier.arrive.release.cta.shared::cta.b64 _, [%0];"
                 :: "r"(a) : "memory");
}
__device__ __forceinline__ void mbar_arrive_cluster(uint32_t a) {
    asm volatile("mbarrier.arrive.release.cluster.shared::cluster.b64 _, [%0];"
                 :: "r"(a) : "memory");
}
__device__ __forceinline__ void mbar_wait_par(uint32_t a, uint32_t par) {
    asm volatile(
        "{\n\t.reg .pred P;\n\t"
        "WL%=:\n\t"
        "mbarrier.try_wait.parity.acquire.cluster.shared::cta.b64 P, [%0], %1, 0x989680;\n\t"
        "@P bra WD%=;\n\t"
        "bra WL%=;\n\t"
        "WD%=:\n\t}"
        :: "r"(a), "r"(par) : "memory");
}
__device__ __forceinline__ void st_cluster_f4(uint32_t a, float4 v) {
    asm volatile("st.shared::cluster.v4.b32 [%0], {%1,%2,%3,%4};" :: "r"(a),
                 "r"(__float_as_uint(v.x)), "r"(__float_as_uint(v.y)),
                 "r"(__float_as_uint(v.z)), "r"(__float_as_uint(v.w)) : "memory");
}
__device__ __forceinline__ void st_cluster_u32(uint32_t a, uint32_t v) {
    asm volatile("st.shared::cluster.b32 [%0], %1;" :: "r"(a), "r"(v) : "memory");
}
__device__ __forceinline__ void cluster_sync_all() {
    asm volatile("barrier.cluster.arrive.aligned;" ::: "memory");
    asm volatile("barrier.cluster.wait.aligned;" ::: "memory");
}
__device__ __forceinline__ void ldsm_x4(uint32_t addr, uint32_t r[4]) {
    asm volatile("ldmatrix.sync.aligned.m8n8.x4.shared.b16 {%0,%1,%2,%3}, [%4];"
                 : "=r"(r[0]), "=r"(r[1]), "=r"(r[2]), "=r"(r[3]) : "r"(addr));
}
__device__ __forceinline__ void ldsm_x2t(uint32_t addr, uint32_t& r0, uint32_t& r1) {
    asm volatile("ldmatrix.sync.aligned.m8n8.x2.trans.shared.b16 {%0,%1}, [%2];"
                 : "=r"(r0), "=r"(r1) : "r"(addr));
}
__device__ __forceinline__ void mma_bf16(float c[4], const uint32_t a[4],
                                         uint32_t b0, uint32_t b1) {
    asm volatile(
        "mma.sync.aligned.m16n8k16.row.col.f32.bf16.bf16.f32 "
        "{%0,%1,%2,%3}, {%4,%5,%6,%7}, {%8,%9}, {%0,%1,%2,%3};"
        : "+f"(c[0]), "+f"(c[1]), "+f"(c[2]), "+f"(c[3])
        : "r"(a[0]), "r"(a[1]), "r"(a[2]), "r"(a[3]), "r"(b0), "r"(b1));
}
__device__ __forceinline__ uint32_t packbf2(float a, float b) {
    __nv_bfloat16 ha = __float2bfloat16(a), hb = __float2bfloat16(b);
    return ((uint32_t)__bfloat16_as_ushort(hb) << 16) | __bfloat16_as_ushort(ha);
}
__device__ __forceinline__ float bfu(uint32_t u) {
    return __bfloat162float(__ushort_as_bfloat16((unsigned short)(u & 0xffffu)));
}

// ===========================================================================
// Kernel 0a/0b: W1x / Wy -> bf16 hi/lo, transposed to [n][k]
// ===========================================================================
__global__ void wconv_kernel(const float* __restrict__ W1x)
{
    int k = blockIdx.x, n = threadIdx.x;
    float v = W1x[k * 256 + n];
    __nv_bfloat16 h = __float2bfloat16(v);
    __nv_bfloat16 l = __float2bfloat16(v - __bfloat162float(h));
    g_wh[n * 256 + k] = h;
    g_wl[n * 256 + k] = l;
}
__global__ void wconv_wy_kernel(const float* __restrict__ Wy)
{
    int k = blockIdx.x, n = threadIdx.x;
    float v = Wy[k * 256 + n];
    __nv_bfloat16 h = __float2bfloat16(v);
    __nv_bfloat16 l = __float2bfloat16(v - __bfloat162float(h));
    g_wyh[n * 256 + k] = h;
    g_wyl[n * 256 + k] = l;
}

// ===========================================================================
// Shared GEMM pieces (R8-proven)
// ===========================================================================
#define SB_BH    0
#define SB_BL    65536
#define SB_A     131072
#define SB_BIAS  196608
#define XP_SMEM  197120

__device__ __forceinline__ void afragx(uint32_t Ab, int mbase, int j, int lane,
                                       uint32_t r[4]) {
    int row = mbase + (lane & 15);
    int q   = j * 2 + (lane >> 4);
    uint32_t addr = Ab + (uint32_t)(row * 128 + ((q ^ row) & 7) * 16);
    ldsm_x4(addr, r);
}
__device__ __forceinline__ void bfragx(uint32_t Bb, int nbase, int ks, int lane,
                                       uint32_t r[4]) {
    int row = nbase + (lane & 7) + ((lane >> 4) << 3);
    int q   = ks * 2 + ((lane >> 3) & 1);
    uint32_t qp = (uint32_t)((q & ~7) | ((q ^ row) & 7));
    uint32_t addr = Bb + (uint32_t)(row * 512) + qp * 16;
    ldsm_x4(addr, r);
}

__device__ __forceinline__ void load_a_rows(unsigned char* sm, int p,
                                            const float* __restrict__ Arows,
                                            int c, int t)
{
    const int r = t >> 1, hf = t & 1, rx = r & 7;
    unsigned char* ah = sm + SB_A + p * 32768;
    unsigned char* al = ah + 16384;
    const float* xr = Arows + (size_t)r * 256 + c * 64 + hf * 32;
    #pragma unroll
    for (int jj = 0; jj < 4; jj++) {
        float4 v0 = *(const float4*)(xr + jj * 8);
        float4 v1 = *(const float4*)(xr + jj * 8 + 4);
        uint4 h, l;
        h.x = packbf2(v0.x, v0.y); h.y = packbf2(v0.z, v0.w);
        h.z = packbf2(v1.x, v1.y); h.w = packbf2(v1.z, v1.w);
        l.x = packbf2(v0.x - bfu(h.x), v0.y - bfu(h.x >> 16));
        l.y = packbf2(v0.z - bfu(h.y), v0.w - bfu(h.y >> 16));
        l.z = packbf2(v1.x - bfu(h.z), v1.y - bfu(h.z >> 16));
        l.w = packbf2(v1.z - bfu(h.w), v1.w - bfu(h.w >> 16));
        int q = hf * 4 + jj;
        uint32_t off = (uint32_t)(r * 128 + (q ^ rx) * 16);
        *(uint4*)(ah + off) = h;
        *(uint4*)(al + off) = l;
    }
}

template <int MODE>
__device__ __forceinline__ void gemm128(const float* __restrict__ Arows, int m0,
                                        const __nv_bfloat16* __restrict__ Wth,
                                        const __nv_bfloat16* __restrict__ Wtl,
                                        const float* __restrict__ bias1,
                                        const float* __restrict__ bias2,
                                        int n0, float* __restrict__ outp)
{
    extern __shared__ __align__(1024) unsigned char sm[];
    const int t = threadIdx.x;
    const int wid = t >> 5, lane = t & 31;
    const uint32_t smb = smem_u32(sm);
    const int mw = (wid & 1) * 64;
    const int nw = (wid >> 1) * 32;

    #pragma unroll 4
    for (int i = 0; i < 16; i++) {
        int idx = i * 256 + t;
        int rr = idx >> 5, q = idx & 31;
        uint32_t qp = (uint32_t)((q & ~7) | ((q ^ rr) & 7));
        size_t src = (size_t)(n0 + rr) * 256 + q * 8;
        *(uint4*)(sm + SB_BH + rr * 512 + qp * 16) = *(const uint4*)(Wth + src);
        *(uint4*)(sm + SB_BL + rr * 512 + qp * 16) = *(const uint4*)(Wtl + src);
    }
    if (t < 128) {
        float b = bias1[n0 + t];
        if (bias2) b += bias2[n0 + t];
        ((float*)(sm + SB_BIAS))[t] = b;
    }
    load_a_rows(sm, 0, Arows, 0, t);
    __syncthreads();

    float acc[4][4][4];
    #pragma unroll
    for (int mt = 0; mt < 4; mt++)
        #pragma unroll
        for (int nt = 0; nt < 4; nt++)
            #pragma unroll
            for (int e = 0; e < 4; e++) acc[mt][nt][e] = 0.f;

    const uint32_t Bh = smb + SB_BH, Bl = smb + SB_BL;

    #pragma unroll 1
    for (int c = 0; c < 4; c++) {
        const int p = c & 1;
        if (c < 3) load_a_rows(sm, 1 - p, Arows, c + 1, t);
        const uint32_t Abh = smb + SB_A + p * 32768;
        const uint32_t Abl = Abh + 16384;
        #pragma unroll
        for (int j = 0; j < 4; j++) {
            const int ks = c * 4 + j;
            uint32_t bh[8], bl[8];
            bfragx(Bh, nw,      ks, lane, bh);
            bfragx(Bh, nw + 16, ks, lane, bh + 4);
            bfragx(Bl, nw,      ks, lane, bl);
            bfragx(Bl, nw + 16, ks, lane, bl + 4);
            #pragma unroll
            for (int mt = 0; mt < 4; mt++) {
                uint32_t ah[4], al[4];
                afragx(Abh, mw + mt * 16, j, lane, ah);
                afragx(Abl, mw + mt * 16, j, lane, al);
                #pragma unroll
                for (int nt = 0; nt < 4; nt++) {
                    mma_bf16(acc[mt][nt], ah, bh[nt * 2], bh[nt * 2 + 1]);
                    mma_bf16(acc[mt][nt], ah, bl[nt * 2], bl[nt * 2 + 1]);
                    mma_bf16(acc[mt][nt], al, bh[nt * 2], bh[nt * 2 + 1]);
                }
            }
        }
        __syncthreads();
    }

    const int g = lane >> 2, tig = lane & 3;
    const float* bias_sm = (const float*)(sm + SB_BIAS);
    #pragma unroll
    for (int mt = 0; mt < 4; mt++) {
        const int mrow = m0 + mw + mt * 16 + g;
        #pragma unroll
        for (int nt = 0; nt < 4; nt++) {
            const int nl = nw + nt * 8 + tig * 2;
            const float bz0 = bias_sm[nl], bz1 = bias_sm[nl + 1];
            float2 v0, v1;
            if (MODE == 0) {
                v0 = make_float2(acc[mt][nt][0] + bz0, acc[mt][nt][1] + bz1);
                v1 = make_float2(acc[mt][nt][2] + bz0, acc[mt][nt][3] + bz1);
            } else {
                v0 = make_float2(sigf(acc[mt][nt][0] + bz0), sigf(acc[mt][nt][1] + bz1));
                v1 = make_float2(sigf(acc[mt][nt][2] + bz0), sigf(acc[mt][nt][3] + bz1));
            }
            *(float2*)&outp[(size_t)mrow * 256 + n0 + nl] = v0;
            *(float2*)&outp[(size_t)(mrow + 8) * 256 + n0 + nl] = v1;
        }
    }
}

__global__ __launch_bounds__(256, 1) void xproj_mma_kernel(
    const float* __restrict__ x,
    const float* __restrict__ b1x, const float* __restrict__ b1a)
{
    const int m0 = blockIdx.x * 128;
    const int n0 = blockIdx.y * 128;
    const int s  = m0 >> 8;
    const int b0 = m0 & 255;
    extern __shared__ __align__(1024) unsigned char sm[];
    const int t = threadIdx.x;
    const int wid = t >> 5, lane = t & 31;
    const uint32_t smb = smem_u32(sm);
    const int mw = (wid & 1) * 64;
    const int nw = (wid >> 1) * 32;

    #pragma unroll 4
    for (int i = 0; i < 16; i++) {
        int idx = i * 256 + t;
        int rr = idx >> 5, q = idx & 31;
        uint32_t qp = (uint32_t)((q & ~7) | ((q ^ rr) & 7));
        size_t src = (size_t)(n0 + rr) * 256 + q * 8;
        *(uint4*)(sm + SB_BH + rr * 512 + qp * 16) = *(const uint4*)(g_wh + src);
        *(uint4*)(sm + SB_BL + rr * 512 + qp * 16) = *(const uint4*)(g_wl + src);
    }
    if (t < 128)
        ((float*)(sm + SB_BIAS))[t] = b1x[n0 + t] + b1a[n0 + t];

    auto load_chunk = [&](int p, int c) {
        const int r = t >> 1, hf = t & 1, rx = r & 7;
        unsigned char* ah = sm + SB_A + p * 32768;
        unsigned char* al = ah + 16384;
        const float* xr = x + ((size_t)(b0 + r) * SS + s) * II + c * 64 + hf * 32;
        #pragma unroll
        for (int jj = 0; jj < 4; jj++) {
            float4 v0 = *(const float4*)(xr + jj * 8);
            float4 v1 = *(const float4*)(xr + jj * 8 + 4);
            uint4 h, l;
            h.x = packbf2(v0.x, v0.y); h.y = packbf2(v0.z, v0.w);
            h.z = packbf2(v1.x, v1.y); h.w = packbf2(v1.z, v1.w);
            l.x = packbf2(v0.x - bfu(h.x), v0.y - bfu(h.x >> 16));
            l.y = packbf2(v0.z - bfu(h.y), v0.w - bfu(h.y >> 16));
            l.z = packbf2(v1.x - bfu(h.z), v1.y - bfu(h.z >> 16));
            l.w = packbf2(v1.z - bfu(h.w), v1.w - bfu(h.w >> 16));
            int q = hf * 4 + jj;
            uint32_t off = (uint32_t)(r * 128 + (q ^ rx) * 16);
            *(uint4*)(ah + off) = h;
            *(uint4*)(al + off) = l;
        }
    };

    load_chunk(0, 0);
    __syncthreads();

    float acc[4][4][4];
    #pragma unroll
    for (int mt = 0; mt < 4; mt++)
        #pragma unroll
        for (int nt = 0; nt < 4; nt++)
            #pragma unroll
            for (int e = 0; e < 4; e++) acc[mt][nt][e] = 0.f;

    const uint32_t Bh = smb + SB_BH, Bl = smb + SB_BL;

    #pragma unroll 1
    for (int c = 0; c < 4; c++) {
        const int p = c & 1;
        if (c < 3) load_chunk(1 - p, c + 1);
        const uint32_t Abh = smb + SB_A + p * 32768;
        const uint32_t Abl = Abh + 16384;
        #pragma unroll
        for (int j = 0; j < 4; j++) {
            const int ks = c * 4 + j;
            uint32_t bh[8], bl[8];
            bfragx(Bh, nw,      ks, lane, bh);
            bfragx(Bh, nw + 16, ks, lane, bh + 4);
            bfragx(Bl, nw,      ks, lane, bl);
            bfragx(Bl, nw + 16, ks, lane, bl + 4);
            #pragma unroll
            for (int mt = 0; mt < 4; mt++) {
                uint32_t ah[4], al[4];
                afragx(Abh, mw + mt * 16, j, lane, ah);
                afragx(Abl, mw + mt * 16, j, lane, al);
                #pragma unroll
                for (int nt = 0; nt < 4; nt++) {
                    mma_bf16(acc[mt][nt], ah, bh[nt * 2], bh[nt * 2 + 1]);
                    mma_bf16(acc[mt][nt], ah, bl[nt * 2], bl[nt * 2 + 1]);
                    mma_bf16(acc[mt][nt], al, bh[nt * 2], bh[nt * 2 + 1]);
                }
            }
        }
        __syncthreads();
    }

    const int g = lane >> 2, tig = lane & 3;
    const float* bias_sm = (const float*)(sm + SB_BIAS);
    #pragma unroll
    for (int mt = 0; mt < 4; mt++) {
        const int mrow = m0 + mw + mt * 16 + g;
        #pragma unroll
        for (int nt = 0; nt < 4; nt++) {
            const int nl = nw + nt * 8 + tig * 2;
            const float bz0 = bias_sm[nl], bz1 = bias_sm[nl + 1];
            float2 v0 = make_float2(acc[mt][nt][0] + bz0, acc[mt][nt][1] + bz1);
            float2 v1 = make_float2(acc[mt][nt][2] + bz0, acc[mt][nt][3] + bz1);
            *(float2*)&g_xproj[(size_t)mrow * HH + n0 + nl] = v0;
            *(float2*)&g_xproj[(size_t)(mrow + 8) * HH + n0 + nl] = v1;
        }
    }
}

__global__ __launch_bounds__(256, 1) void y_mma_kernel(
    const float* __restrict__ by, float* __restrict__ out)
{
    gemm128<1>(g_ahist + (size_t)blockIdx.x * 128 * 256, blockIdx.x * 128,
               g_wyh, g_wyl, by, nullptr, blockIdx.y * 128, out);
}

// ===========================================================================
// Kernel 2: RNN ring with REGISTER-RESIDENT weight fragments.
// ===========================================================================
#define A_STRIDE 528
#define ALO      67584
#define RING(i)  (135168 + (i) * 8192)
#define A4OFF    196608
#define Y4OFF    204800
#define REDOFF   208896
#define MBOFF    225408
#define BASEOFF  225472
#define RNN_SMEM 229568
#define RSTRIDE  1032

__device__ __forceinline__ void gemv16_g(const float* __restrict__ Wp,
                                         const float4* __restrict__ a, float acc[16])
{
    #pragma unroll
    for (int j = 0; j < 16; j++) acc[j] = 0.f;
    #pragma unroll 16
    for (int k = 0; k < 32; k++) {
        float4 w  = *(const float4*)(Wp + (size_t)k * 256);
        float4 av = a[k];
        acc[0]  = fmaf(av.x, w.x, acc[0]);  acc[1]  = fmaf(av.x, w.y, acc[1]);
        acc[2]  = fmaf(av.x, w.z, acc[2]);  acc[3]  = fmaf(av.x, w.w, acc[3]);
        acc[4]  = fmaf(av.y, w.x, acc[4]);  acc[5]  = fmaf(av.y, w.y, acc[5]);
        acc[6]  = fmaf(av.y, w.z, acc[6]);  acc[7]  = fmaf(av.y, w.w, acc[7]);
        acc[8]  = fmaf(av.z, w.x, acc[8]);  acc[9]  = fmaf(av.z, w.y, acc[9]);
        acc[10] = fmaf(av.z, w.z, acc[10]); acc[11] = fmaf(av.z, w.w, acc[11]);
        acc[12] = fmaf(av.w, w.x, acc[12]); acc[13] = fmaf(av.w, w.y, acc[13]);
        acc[14] = fmaf(av.w, w.z, acc[14]); acc[15] = fmaf(av.w, w.w, acc[15]);
    }
}

__global__ __launch_bounds__(256, 1) __cluster_dims__(2, 1, 1)
void rnn_kernel(const float* __restrict__ W1a,
                const float* __restrict__ W2x, const float* __restrict__ b2x,
                const float* __restrict__ W2a, const float* __restrict__ b2a,
                const float* __restrict__ Wy,  const float* __restrict__ by)
{
    extern __shared__ __align__(16) unsigned char dsm[];
    float4* a4s   = (float4*)(dsm + A4OFF);
    float4* y4s   = (float4*)(dsm + Y4OFF);
    float*  red   = (float*)(dsm + REDOFF);
    float*  basef = (float*)(dsm + BASEOFF);
    unsigned long long* mbars = (unsigned long long*)(dsm + MBOFF);

    const int t    = threadIdx.x;
    const int lane = t & 31;
    const int wid  = t >> 5;
    uint32_t rank;
    asm("mov.u32 %0, %%cluster_ctarank;" : "=r"(rank));
    const uint32_t peer = rank ^ 1;
    const int b0 = (blockIdx.x >> 1) * 4;
    const int c0 = (int)rank * 128;
    const uint32_t smb = smem_u32(dsm);

    const int mb   = wid * 16;
    const int g    = lane >> 2;
    const int tig  = lane & 3;
    const bool act = (tig < 2);
    const int colg = c0 + mb + g;
    const int nb   = 2 * tig;
    const uint32_t aAddrBase = smb + (uint32_t)((mb + (lane & 15)) * A_STRIDE)
                             + (uint32_t)((lane >> 4) * 16);

    const int kq = wid, cq = lane;
    const int o0    = 2 * t;
    const int row_o = (o0 >> 2) & 3;
    const int coll  = (o0 >> 4) * 4 + (o0 & 3);
    const int col   = c0 + coll;

    uint32_t eF[4], peF[4], pRG[4];
    #pragma unroll
    for (int i = 0; i < 4; i++) {
        eF[i]  = smem_u32(&mbars[i]);
        peF[i] = mapa_peer(eF[i], peer);
        pRG[i] = mapa_peer(smb + (uint32_t)RING(i), peer);
    }
    uint32_t py4 = mapa_peer(smb + Y4OFF, peer);

    if (t == 0) {
        mbar_init(eF[0], 128); mbar_init(eF[1], 128);
        mbar_init(eF[2], 128); mbar_init(eF[3], 128);
    }
    {
        uint4 z = make_uint4(0, 0, 0, 0);
        *(uint4*)(dsm + RING(3) + t * 16) = z;
        *(uint4*)(dsm + RING(3) + (t + 256) * 16) = z;
    }
    // stage A = W1a^T hi/lo into SMEM (transient; registers loaded below)
    {
        const int m = t & 127, hb = t >> 7;
        #pragma unroll 4
        for (int kk = 0; kk < 128; kk++) {
            int k = hb * 128 + kk;
            float v = W1a[(size_t)k * 256 + c0 + m];
            __nv_bfloat16 h = __float2bfloat16(v);
            __nv_bfloat16 l = __float2bfloat16(v - __bfloat162float(h));
            *(unsigned short*)(dsm + m * A_STRIDE + k * 2) = __bfloat16_as_ushort(h);
            *(unsigned short*)(dsm + ALO + m * A_STRIDE + k * 2) = __bfloat16_as_ushort(l);
        }
    }
    __syncthreads();

    // ---- register-resident weight fragments (own-half tiles 0..7, peer 8..15)
    uint32_t ah_r[64], al_r[64];
    auto load_a_regs = [&]() {
        #pragma unroll
        for (int j = 0; j < 8; j++) {
            uint32_t aa = aAddrBase + (uint32_t)((c0 + j * 16) * 2);
            ldsm_x4(aa, &ah_r[j * 4]);
            ldsm_x4(aa + ALO, &al_r[j * 4]);
        }
        #pragma unroll
        for (int j = 0; j < 8; j++) {
            uint32_t aa = aAddrBase + (uint32_t)(((c0 ^ 128) + j * 16) * 2);
            ldsm_x4(aa, &ah_r[(8 + j) * 4]);
            ldsm_x4(aa + ALO, &al_r[(8 + j) * 4]);
        }
    };
    load_a_regs();

    cluster_sync_all();
    if (act) mbar_arrive_local(eF[3]);

    float xc00 = 0.f, xc01 = 0.f, xc10 = 0.f, xc11 = 0.f;
    if (act) {
        const float* xb = g_xproj + (size_t)(b0 + nb) * HH;
        xc00 = __ldcs(xb + colg);
        xc01 = __ldcs(xb + (size_t)HH + colg);
        xc10 = __ldcs(xb + colg + 8);
        xc11 = __ldcs(xb + (size_t)HH + colg + 8);
    }

    int fp0 = 0, fp1 = 0, fp2 = 0, fp3 = 0;

    // ring step core: A from registers, B (state) from SMEM ring slot
    auto ring_mma = [&](uint32_t eFr, int& fpr, uint32_t bsr, bool skipwait,
                        float sums[4]) {
        float acc[6][4];
        #pragma unroll
        for (int i = 0; i < 6; i++)
            #pragma unroll
            for (int e = 0; e < 4; e++) acc[i][e] = 0.f;
        const uint32_t Bsr = smb + bsr;
        #pragma unroll
        for (int j = 0; j < 8; j++) {
            const int k0 = c0 + j * 16;
            uint32_t bh0, bh1, bl0, bl1;
            uint32_t ba = Bsr + (uint32_t)((k0 + (lane & 15)) * 16);
            ldsm_x2t(ba, bh0, bh1);
            ldsm_x2t(ba + 4096, bl0, bl1);
            const int sel = j & 1;
            mma_bf16(acc[sel],     &ah_r[j * 4], bh0, bh1);
            mma_bf16(acc[2 + sel], &ah_r[j * 4], bl0, bl1);
            mma_bf16(acc[4 + sel], &al_r[j * 4], bh0, bh1);
        }
        if (!skipwait) { mbar_wait_par(eFr, fpr); fpr ^= 1; }
        #pragma unroll
        for (int j = 0; j < 8; j++) {
            const int k0 = (c0 ^ 128) + j * 16;
            uint32_t bh0, bh1, bl0, bl1;
            uint32_t ba = Bsr + (uint32_t)((k0 + (lane & 15)) * 16);
            ldsm_x2t(ba, bh0, bh1);
            ldsm_x2t(ba + 4096, bl0, bl1);
            const int sel = j & 1;
            mma_bf16(acc[sel],     &ah_r[(8 + j) * 4], bh0, bh1);
            mma_bf16(acc[2 + sel], &ah_r[(8 + j) * 4], bl0, bl1);
            mma_bf16(acc[4 + sel], &al_r[(8 + j) * 4], bh0, bh1);
        }
        #pragma unroll
        for (int e = 0; e < 4; e++)
            sums[e] = acc[0][e] + acc[1][e] + acc[2][e] + acc[3][e]
                    + acc[4][e] + acc[5][e];
    };

    auto push_state = [&](uint32_t bsw, uint32_t pbsw, uint32_t pefw,
                          float t00, float t01, float t10, float t11) {
        uint32_t hA = packbf2(t00, t01);
        uint32_t hB = packbf2(t10, t11);
        uint32_t lA = packbf2(t00 - bfu(hA), t01 - bfu(hA >> 16));
        uint32_t lB = packbf2(t10 - bfu(hB), t11 - bfu(hB >> 16));
        const uint32_t o1 = (uint32_t)(colg * 16 + tig * 4);
        const uint32_t o2 = (uint32_t)((colg + 8) * 16 + tig * 4);
        *(uint32_t*)(dsm + bsw + o1) = hA;
        *(uint32_t*)(dsm + bsw + o2) = hB;
        *(uint32_t*)(dsm + bsw + 4096 + o1) = lA;
        *(uint32_t*)(dsm + bsw + 4096 + o2) = lB;
        st_cluster_u32(pbsw + o1, hA);
        st_cluster_u32(pbsw + o2, hB);
        st_cluster_u32(pbsw + 4096 + o1, lA);
        st_cluster_u32(pbsw + 4096 + o2, lB);
        mbar_arrive_cluster(pefw);
    };

    // ======================= encoder =======================
    auto enc_step = [&](int s, uint32_t eFr, int& fpr, uint32_t bsr, uint32_t bsw,
                        uint32_t pbsw, uint32_t pefw) {
        float xn00 = 0.f, xn01 = 0.f, xn10 = 0.f, xn11 = 0.f;
        if (act && s + 1 < SS) {
            const float* xb = g_xproj + ((size_t)(s + 1) * BB + (b0 + nb)) * HH;
            xn00 = __ldcs(xb + colg);
            xn01 = __ldcs(xb + (size_t)HH + colg);
            xn10 = __ldcs(xb + colg + 8);
            xn11 = __ldcs(xb + (size_t)HH + colg + 8);
        }
        float sums[4];
        ring_mma(eFr, fpr, bsr, false, sums);
        if (act) {
            push_state(bsw, pbsw, pefw,
                       tanhfast(sums[0] + xc00), tanhfast(sums[1] + xc01),
                       tanhfast(sums[2] + xc10), tanhfast(sums[3] + xc11));
        }
        __syncthreads();
        xc00 = xn00; xc01 = xn01; xc10 = xn10; xc11 = xn11;
    };

    #pragma unroll 1
    for (int sb = 0; sb < SS; sb += 4) {
        enc_step(sb + 0, eF[3], fp3, RING(3), RING(0), pRG[0], peF[0]);
        enc_step(sb + 1, eF[0], fp0, RING(0), RING(1), pRG[1], peF[1]);
        enc_step(sb + 2, eF[1], fp1, RING(1), RING(2), pRG[2], peF[2]);
        enc_step(sb + 3, eF[2], fp2, RING(2), RING(3), pRG[3], peF[3]);
    }

    mbar_wait_par(eF[3], fp3); fp3 ^= 1;
    {
        uint32_t w0h = *(const uint32_t*)(dsm + RING(3) + t * 16);
        uint32_t w1h = *(const uint32_t*)(dsm + RING(3) + t * 16 + 4);
        uint32_t w0l = *(const uint32_t*)(dsm + RING(3) + 4096 + t * 16);
        uint32_t w1l = *(const uint32_t*)(dsm + RING(3) + 4096 + t * 16 + 4);
        a4s[t] = make_float4(bfu(w0h) + bfu(w0l), bfu(w0h >> 16) + bfu(w0l >> 16),
                             bfu(w1h) + bfu(w1l), bfu(w1h >> 16) + bfu(w1l >> 16));
    }
    __syncthreads();

    // ======================= glue: y0, base =======================
    {
        float2 byv = *(const float2*)&by[col];
        float2 b2xv = *(const float2*)&b2x[col];
        float2 b2av = *(const float2*)&b2a[col];
        float bb0 = b2xv.x + b2av.x, bb1 = b2xv.y + b2av.y;

        float acc[16];
        gemv16_g(Wy + (size_t)(kq * 32) * 256 + c0 + cq * 4, &a4s[kq * 32], acc);
        #pragma unroll
        for (int r = 0; r < 4; r++)
            *(float4*)&red[r * RSTRIDE + kq * 128 + cq * 4] =
                make_float4(acc[r * 4], acc[r * 4 + 1], acc[r * 4 + 2], acc[r * 4 + 3]);
        __syncthreads();
        float v0 = 0.f, v1 = 0.f;
        #pragma unroll
        for (int gg = 0; gg < 8; gg++) {
            float2 rv = *(const float2*)&red[row_o * RSTRIDE + gg * 128 + coll];
            v0 += rv.x; v1 += rv.y;
        }
        ((float*)&y4s[col])[row_o]     = sigf(v0 + byv.x);
        ((float*)&y4s[col + 1])[row_o] = sigf(v1 + byv.y);
        __syncthreads();
        if (kq == 0) {
            #pragma unroll
            for (int j = 0; j < 4; j++) {
                int idx = c0 + cq + 32 * j;
                st_cluster_f4(py4 + (uint32_t)idx * 16u, y4s[idx]);
            }
        }
        cluster_sync_all();

        gemv16_g(W2x + (size_t)(kq * 32) * 256 + c0 + cq * 4, y4s + kq * 32, acc);
        #pragma unroll
        for (int r = 0; r < 4; r++)
            *(float4*)&red[r * RSTRIDE + kq * 128 + cq * 4] =
                make_float4(acc[r * 4], acc[r * 4 + 1], acc[r * 4 + 2], acc[r * 4 + 3]);
        __syncthreads();
        v0 = 0.f; v1 = 0.f;
        #pragma unroll
        for (int gg = 0; gg < 8; gg++) {
            float2 rv = *(const float2*)&red[row_o * RSTRIDE + gg * 128 + coll];
            v0 += rv.x; v1 += rv.y;
        }
        basef[row_o * 256 + coll]     = v0 + bb0;
        basef[row_o * 256 + coll + 1] = v1 + bb1;
        __syncthreads();
    }

    // restage A = W2a^T hi/lo, reload register fragments
    {
        const int m = t & 127, hb = t >> 7;
        #pragma unroll 4
        for (int kk = 0; kk < 128; kk++) {
            int k = hb * 128 + kk;
            float v = W2a[(size_t)k * 256 + c0 + m];
            __nv_bfloat16 h = __float2bfloat16(v);
            __nv_bfloat16 l = __float2bfloat16(v - __bfloat162float(h));
            *(unsigned short*)(dsm + m * A_STRIDE + k * 2) = __bfloat16_as_ushort(h);
            *(unsigned short*)(dsm + ALO + m * A_STRIDE + k * 2) = __bfloat16_as_ushort(l);
        }
    }
    __syncthreads();
    load_a_regs();

    const int mbg = mb + g;
    float bbA = 0.f, bbB = 0.f;
    if (act) {
        bbA = b2x[colg] + b2a[colg];
        bbB = b2x[colg + 8] + b2a[colg + 8];
    }

    // ======================= decoder (ring continues) =======================
    auto dec_step = [&](int i, uint32_t eFr, int& fpr, uint32_t bsr, uint32_t bsw,
                        uint32_t pbsw, uint32_t pefw, bool skipwait) {
        float sums[4];
        ring_mma(eFr, fpr, bsr, skipwait, sums);
        if (act) {
            float a00, a01, a10, a11;
            if (i == 0) {
                a00 = basef[nb * 256 + mbg];
                a01 = basef[(nb + 1) * 256 + mbg];
                a10 = basef[nb * 256 + mbg + 8];
                a11 = basef[(nb + 1) * 256 + mbg + 8];
            } else {
                a00 = bbA; a01 = bbA; a10 = bbB; a11 = bbB;
            }
            float t00 = tanhfast(sums[0] + a00);
            float t01 = tanhfast(sums[1] + a01);
            float t10 = tanhfast(sums[2] + a10);
            float t11 = tanhfast(sums[3] + a11);
            g_ahist[((size_t)(b0 + nb) * LL + i) * 256 + colg]          = t00;
            g_ahist[((size_t)(b0 + nb + 1) * LL + i) * 256 + colg]      = t01;
            g_ahist[((size_t)(b0 + nb) * LL + i) * 256 + colg + 8]      = t10;
            g_ahist[((size_t)(b0 + nb + 1) * LL + i) * 256 + colg + 8]  = t11;
            push_state(bsw, pbsw, pefw, t00, t01, t10, t11);
        }
        __syncthreads();
    };

    #pragma unroll 1
    for (int ib = 0; ib < 16; ib++) {
        const int i0 = ib * 4;
        dec_step(i0 + 0, eF[3], fp3, RING(3), RING(0), pRG[0], peF[0], ib == 0);
        dec_step(i0 + 1, eF[0], fp0, RING(0), RING(1), pRG[1], peF[1], false);
        dec_step(i0 + 2, eF[1], fp1, RING(1), RING(2), pRG[2], peF[2], false);
        dec_step(i0 + 3, eF[2], fp2, RING(2), RING(3), pRG[3], peF[3], false);
    }

    cluster_sync_all();
}

// ---------------------------------------------------------------------------
extern "C" void kernel_launch(void* const* d_in, const int* in_sizes, int n_in,
                              void* d_out, int out_size)
{
    const float* x   = (const float*)d_in[0];
    const float* W1x = (const float*)d_in[1];
    const float* b1x = (const float*)d_in[2];
    const float* W1a = (const float*)d_in[3];
    const float* b1a = (const float*)d_in[4];
    const float* W2x = (const float*)d_in[5];
    const float* b2x = (const float*)d_in[6];
    const float* W2a = (const float*)d_in[7];
    const float* b2a = (const float*)d_in[8];
    const float* Wy  = (const float*)d_in[9];
    const float* by  = (const float*)d_in[10];
    float* out = (float*)d_out;

    (void)in_sizes; (void)n_in; (void)out_size;

    cudaFuncSetAttribute(xproj_mma_kernel,
                         cudaFuncAttributeMaxDynamicSharedMemorySize, XP_SMEM);
    cudaFuncSetAttribute(y_mma_kernel,
                         cudaFuncAttributeMaxDynamicSharedMemorySize, XP_SMEM);
    cudaFuncSetAttribute(rnn_kernel,
                         cudaFuncAttributeMaxDynamicSharedMemorySize, RNN_SMEM);

    wconv_kernel<<<256, 256>>>(W1x);
    wconv_wy_kernel<<<256, 256>>>(Wy);
    dim3 xgrid((BB * SS) / 128, HH / 128);
    xproj_mma_kernel<<<xgrid, 256, XP_SMEM>>>(x, b1x, b1a);
    rnn_kernel<<<BB / 2, 256, RNN_SMEM>>>(W1a, W2x, b2x, W2a, b2a, Wy, by);
    dim3 ygrid((BB * LL) / 128, OO / 128);
    y_mma_kernel<<<ygrid, 256, XP_SMEM>>>(by, out);
}